// round 3
// baseline (speedup 1.0000x reference)
#include <cuda_runtime.h>
#include <math.h>

#define BB 4
#define SS 1024
#define DD 1024
#define HH 16
#define DK 64
#define MM (BB * SS)   // 4096

// ---------------- scratch (device globals; no allocation allowed) -------------
__device__ float g_wqf[DD * DD];
__device__ float g_wkf[DD * DD];
__device__ float g_wvf[DD * DD];
__device__ float g_bqf[DD];
__device__ float g_bkf[DD];
__device__ float g_bvf[DD];
__device__ float g_wck[DD * HH];
__device__ float g_wcb[DD * HH];
__device__ float g_bck[HH];
__device__ float g_bcb[HH];
__device__ float g_qv[DK];
__device__ float g_bmean;
__device__ float g_qs[MM * DD];
__device__ float g_k2[MM * DD];
__device__ float g_v2[MM * DD];
__device__ float g_x[MM * DD];
__device__ float g_m[BB * HH * SS];
__device__ float g_ck[MM * HH];
__device__ float g_cb[MM * HH];

// ---------------- 1. fold per-head 64x64 projections into the big weights ----
// out[d, h*64+e'] = sum_e W[d, h*64+e] * P[e, e']
__global__ void fold_w_kernel(const float* __restrict__ wq,
                              const float* __restrict__ wk,
                              const float* __restrict__ wv,
                              const float* __restrict__ sw,
                              const float* __restrict__ kp,
                              const float* __restrict__ vl) {
    int f = blockIdx.y;
    int idx = blockIdx.x * 256 + threadIdx.x;           // [0, 1M)
    const float* W = (f == 0) ? wq : (f == 1) ? wk : wv;
    const float* P = (f == 0) ? sw : (f == 1) ? kp : vl;
    float* O = (f == 0) ? g_wqf : (f == 1) ? g_wkf : g_wvf;
    int d = idx >> 10;
    int c = idx & 1023;
    int h = c >> 6;
    int ep = c & 63;
    const float* wrow = W + d * DD + (h << 6);
    float sum = 0.f;
#pragma unroll 8
    for (int e = 0; e < DK; e++) sum += wrow[e] * P[e * DK + ep];
    O[idx] = sum;
}

// ---------------- 2. small precompute: fused biases, chan-folded wk, qv ------
__global__ void small_prep_kernel(const float* __restrict__ bq,
                                  const float* __restrict__ bk,
                                  const float* __restrict__ bv,
                                  const float* __restrict__ sw,
                                  const float* __restrict__ kp,
                                  const float* __restrict__ vl,
                                  const float* __restrict__ sb,
                                  const float* __restrict__ kpb,
                                  const float* __restrict__ vlb,
                                  const float* __restrict__ wk,
                                  const float* __restrict__ chan_w,
                                  const float* __restrict__ chan_b,
                                  const float* __restrict__ qproj_w,
                                  const float* __restrict__ qproj_b) {
    int T = blockIdx.x * 256 + threadIdx.x;
    if (T < 3072) {
        int f = T >> 10;
        int c = T & 1023;
        int h = c >> 6;
        int ep = c & 63;
        const float* b = (f == 0) ? bq : (f == 1) ? bk : bv;
        const float* P = (f == 0) ? sw : (f == 1) ? kp : vl;
        const float* pb = (f == 0) ? sb : (f == 1) ? kpb : vlb;
        float* O = (f == 0) ? g_bqf : (f == 1) ? g_bkf : g_bvf;
        float sum = pb[ep];
        for (int e = 0; e < DK; e++) sum += b[(h << 6) + e] * P[e * DK + ep];
        O[c] = sum;
        return;
    }
    T -= 3072;
    if (T < 16384) {                                      // wck
        int d = T >> 4, h = T & 15;
        float sum = 0.f;
        for (int e = 0; e < DK; e++) sum += wk[d * DD + (h << 6) + e] * chan_w[e];
        g_wck[d * HH + h] = sum;
        return;
    }
    T -= 16384;
    if (T < 16384) {                                      // wcb
        int d = T >> 4, h = T & 15;
        float sum = 0.f;
        for (int e = 0; e < DK; e++) sum += wk[d * DD + (h << 6) + e] * chan_b[e];
        g_wcb[d * HH + h] = sum;
        return;
    }
    T -= 16384;
    if (T < 16) {                                         // bck
        float sum = 0.f;
        for (int e = 0; e < DK; e++) sum += bk[(T << 6) + e] * chan_w[e];
        g_bck[T] = sum;
        return;
    }
    T -= 16;
    if (T < 16) {                                         // bcb
        float sum = 0.f;
        for (int e = 0; e < DK; e++) sum += bk[(T << 6) + e] * chan_b[e];
        g_bcb[T] = sum;
        return;
    }
    T -= 16;
    if (T < 64) {                                         // qv[e] = rowmean of qproj_w
        float sum = 0.f;
        for (int ep = 0; ep < DK; ep++) sum += qproj_w[T * DK + ep];
        g_qv[T] = sum * (1.f / 64.f);
        return;
    }
    T -= 64;
    if (T == 0) {                                         // bmean
        float sum = 0.f;
        for (int ep = 0; ep < DK; ep++) sum += qproj_b[ep];
        g_bmean = sum * (1.f / 64.f);
    }
}

// ---------------- 3. big GEMM: C = act(A @ W + bias) --------------------------
// A [M,K] rm, W [K,N] rm. 128x128 tile, BK=8, 256 thr, 8x8 microtile.
template <int ACT>   // 0 = none, 1 = elu
__global__ void gemm_bias_act(const float* __restrict__ A,
                              const float* __restrict__ Bm,
                              const float* __restrict__ bias,
                              float* __restrict__ C,
                              int Mm, int Nn, int Kk) {
    __shared__ float As[8][128];
    __shared__ float Bs[8][128];
    int tid = threadIdx.x;
    int brow = blockIdx.y * 128;
    int bcol = blockIdx.x * 128;
    int ty = tid >> 4, tx = tid & 15;
    int ar = tid >> 1, ak = (tid & 1) << 2;     // A tile 128x8 loader
    int bk = tid >> 5, bn = (tid & 31) << 2;    // B tile 8x128 loader
    const float* Aptr = A + (size_t)(brow + ar) * Kk + ak;
    const float* Bptr = Bm + (size_t)bk * Nn + bcol + bn;
    float acc[8][8];
#pragma unroll
    for (int i = 0; i < 8; i++)
#pragma unroll
        for (int j = 0; j < 8; j++) acc[i][j] = 0.f;

    for (int k0 = 0; k0 < Kk; k0 += 8) {
        float4 a4 = *(const float4*)(Aptr + k0);
        float4 b4 = *(const float4*)(Bptr + (size_t)k0 * Nn);
        As[ak + 0][ar] = a4.x;
        As[ak + 1][ar] = a4.y;
        As[ak + 2][ar] = a4.z;
        As[ak + 3][ar] = a4.w;
        *(float4*)&Bs[bk][bn] = b4;
        __syncthreads();
#pragma unroll
        for (int kk = 0; kk < 8; kk++) {
            float a[8], b[8];
            *(float4*)(a) = *(float4*)&As[kk][ty * 8];
            *(float4*)(a + 4) = *(float4*)&As[kk][ty * 8 + 4];
            *(float4*)(b) = *(float4*)&Bs[kk][tx * 8];
            *(float4*)(b + 4) = *(float4*)&Bs[kk][tx * 8 + 4];
#pragma unroll
            for (int i = 0; i < 8; i++)
#pragma unroll
                for (int j = 0; j < 8; j++) acc[i][j] = fmaf(a[i], b[j], acc[i][j]);
        }
        __syncthreads();
    }
    // epilogue
#pragma unroll
    for (int i = 0; i < 8; i++) {
        int row = brow + ty * 8 + i;
        float* crow = C + (size_t)row * Nn + bcol + tx * 8;
#pragma unroll
        for (int j4 = 0; j4 < 8; j4 += 4) {
            float4 o;
            float v0 = acc[i][j4 + 0] + bias[bcol + tx * 8 + j4 + 0];
            float v1 = acc[i][j4 + 1] + bias[bcol + tx * 8 + j4 + 1];
            float v2 = acc[i][j4 + 2] + bias[bcol + tx * 8 + j4 + 2];
            float v3 = acc[i][j4 + 3] + bias[bcol + tx * 8 + j4 + 3];
            if (ACT == 1) {
                v0 = v0 > 0.f ? v0 : expm1f(v0);
                v1 = v1 > 0.f ? v1 : expm1f(v1);
                v2 = v2 > 0.f ? v2 : expm1f(v2);
                v3 = v3 > 0.f ? v3 : expm1f(v3);
            }
            o.x = v0; o.y = v1; o.z = v2; o.w = v3;
            *(float4*)(crow + j4) = o;
        }
    }
}

// ---------------- 4. ck/cb skinny GEMV: key @ wck / wcb -----------------------
__global__ void ckcb_kernel(const float* __restrict__ key) {
    __shared__ float rows[8][1024];
    int tid = threadIdx.x;
    int row0 = blockIdx.x * 8;
#pragma unroll
    for (int l = 0; l < 8; l++) {
        int lin = tid + l * 256;          // 2048 float4s
        int r = lin >> 8;
        int c4 = (lin & 255) << 2;
        *(float4*)&rows[r][c4] = *(const float4*)&key[(size_t)(row0 + r) * DD + c4];
    }
    __syncthreads();
    int r = tid >> 5;
    int o = tid & 31;
    int h = o & 15;
    int isB = o >> 4;
    const float* wp = isB ? g_wcb : g_wck;
    float sum = isB ? g_bcb[h] : g_bck[h];
#pragma unroll 8
    for (int d = 0; d < DD; d++) sum += rows[r][d] * wp[d * HH + h];
    (isB ? g_cb : g_ck)[(size_t)(row0 + r) * HH + h] = sum;
}

// ---------------- 5. per-query scalar m = qs . qv + bmean ---------------------
__global__ void m_kernel() {
    int i = blockIdx.x * 256 + threadIdx.x;     // [0, B*H*S)
    int b = i >> 14;
    int h = (i >> 10) & 15;
    int s = i & 1023;
    const float* q = g_qs + ((size_t)((b << 10) + s) << 10) + (h << 6);
    float sum = g_bmean;
#pragma unroll 8
    for (int e = 0; e < DK; e++) sum += q[e] * g_qv[e];
    g_m[i] = sum;
}

// ---------------- 6. fused flash attention with xlinear gate ------------------
// scores = (qs.k2)/8 * sigmoid(m_q*ck + cb); mask; online softmax; out = P @ v2
#define ATT_STRIDE 68
__global__ void attn_kernel(const int* __restrict__ mask) {
    extern __shared__ float sm[];
    float* Qs = sm;                        // [e][r] transposed, 64x68
    float* KPs = Qs + 64 * ATT_STRIDE;     // K as [e][c]; later reused as P [k][r]
    float* Vs = KPs + 64 * ATT_STRIDE;     // [k][e]
    float* mrow = Vs + 64 * ATT_STRIDE;    // 64
    float* ckv = mrow + 64;
    float* cbv = ckv + 64;
    float* rmax = cbv + 64;
    float* rsum = rmax + 64;
    float* csc = rsum + 64;

    int tid = threadIdx.x;
    int q0 = blockIdx.x * 64;
    int h = blockIdx.y;
    int b = blockIdx.z;
    int ty = tid >> 4, tx = tid & 15;

    if (tid < 64) {
        rmax[tid] = -INFINITY;
        rsum[tid] = 0.f;
        mrow[tid] = g_m[(size_t)((b * HH + h) << 10) + q0 + tid];
    }
    // load Q tile transposed: Qs[e][r]
#pragma unroll
    for (int l = 0; l < 4; l++) {
        int lin = tid + l * 256;
        int r = lin >> 4;
        int e4 = (lin & 15) << 2;
        float4 v = *(const float4*)&g_qs[(size_t)((b << 10) + q0 + r) * DD + (h << 6) + e4];
        Qs[(e4 + 0) * ATT_STRIDE + r] = v.x;
        Qs[(e4 + 1) * ATT_STRIDE + r] = v.y;
        Qs[(e4 + 2) * ATT_STRIDE + r] = v.z;
        Qs[(e4 + 3) * ATT_STRIDE + r] = v.w;
    }
    float acc[4][4];
#pragma unroll
    for (int i = 0; i < 4; i++)
#pragma unroll
        for (int j = 0; j < 4; j++) acc[i][j] = 0.f;
    __syncthreads();

    for (int kt = 0; kt < 16; kt++) {
        int k0 = kt * 64;
        // K transposed [e][c], V natural [k][e]
#pragma unroll
        for (int l = 0; l < 4; l++) {
            int lin = tid + l * 256;
            int r = lin >> 4;
            int e4 = (lin & 15) << 2;
            float4 kv = *(const float4*)&g_k2[(size_t)((b << 10) + k0 + r) * DD + (h << 6) + e4];
            KPs[(e4 + 0) * ATT_STRIDE + r] = kv.x;
            KPs[(e4 + 1) * ATT_STRIDE + r] = kv.y;
            KPs[(e4 + 2) * ATT_STRIDE + r] = kv.z;
            KPs[(e4 + 3) * ATT_STRIDE + r] = kv.w;
            float4 vv = *(const float4*)&g_v2[(size_t)((b << 10) + k0 + r) * DD + (h << 6) + e4];
            *(float4*)&Vs[r * ATT_STRIDE + e4] = vv;
        }
        if (tid < 64) {
            ckv[tid] = g_ck[(size_t)((b << 10) + k0 + tid) * HH + h];
            cbv[tid] = g_cb[(size_t)((b << 10) + k0 + tid) * HH + h];
        }
        __syncthreads();

        float s[4][4];
#pragma unroll
        for (int i = 0; i < 4; i++)
#pragma unroll
            for (int j = 0; j < 4; j++) s[i][j] = 0.f;
#pragma unroll
        for (int e = 0; e < 64; e++) {
            float4 qa = *(float4*)&Qs[e * ATT_STRIDE + ty * 4];
            float4 kb = *(float4*)&KPs[e * ATT_STRIDE + tx * 4];
            float qr[4] = {qa.x, qa.y, qa.z, qa.w};
            float kc[4] = {kb.x, kb.y, kb.z, kb.w};
#pragma unroll
            for (int i = 0; i < 4; i++)
#pragma unroll
                for (int j = 0; j < 4; j++) s[i][j] = fmaf(qr[i], kc[j], s[i][j]);
        }
        // gate + mask
#pragma unroll
        for (int i = 0; i < 4; i++) {
            int qr = ty * 4 + i;
            float mq = mrow[qr];
            const int* mptr = mask + (size_t)(b * SS + q0 + qr) * SS + k0;
#pragma unroll
            for (int j = 0; j < 4; j++) {
                int kc = tx * 4 + j;
                float val = s[i][j] * 0.125f;
                float logit = fmaf(mq, ckv[kc], cbv[kc]);
                float gate = 1.f / (1.f + expf(-logit));
                val *= gate;
                if (mptr[kc] == 0) val = -1e9f;
                s[i][j] = val;
            }
        }
        __syncthreads();   // everyone done reading KPs as K
        // store scores to KPs as P[k][r]
#pragma unroll
        for (int i = 0; i < 4; i++)
#pragma unroll
            for (int j = 0; j < 4; j++)
                KPs[(tx * 4 + j) * ATT_STRIDE + ty * 4 + i] = s[i][j];
        __syncthreads();
        // row softmax (online): one thread per q row
        if (tid < 64) {
            int r = tid;
            float om = rmax[r];
            float tm = om;
#pragma unroll 8
            for (int c = 0; c < 64; c++) tm = fmaxf(tm, KPs[c * ATT_STRIDE + r]);
            float c0 = expf(om - tm);
            float sum = 0.f;
#pragma unroll 8
            for (int c = 0; c < 64; c++) {
                float p = expf(KPs[c * ATT_STRIDE + r] - tm);
                KPs[c * ATT_STRIDE + r] = p;
                sum += p;
            }
            rsum[r] = rsum[r] * c0 + sum;
            rmax[r] = tm;
            csc[r] = c0;
        }
        __syncthreads();
        // rescale + accumulate P @ V
#pragma unroll
        for (int i = 0; i < 4; i++) {
            float cs = csc[ty * 4 + i];
#pragma unroll
            for (int j = 0; j < 4; j++) acc[i][j] *= cs;
        }
#pragma unroll
        for (int k = 0; k < 64; k++) {
            float4 pa = *(float4*)&KPs[k * ATT_STRIDE + ty * 4];
            float4 va = *(float4*)&Vs[k * ATT_STRIDE + tx * 4];
            float pr[4] = {pa.x, pa.y, pa.z, pa.w};
            float vc[4] = {va.x, va.y, va.z, va.w};
#pragma unroll
            for (int i = 0; i < 4; i++)
#pragma unroll
                for (int j = 0; j < 4; j++) acc[i][j] = fmaf(pr[i], vc[j], acc[i][j]);
        }
        __syncthreads();   // before next tile overwrites KPs/Vs
    }
    // normalize + write
#pragma unroll
    for (int i = 0; i < 4; i++) {
        int qr = ty * 4 + i;
        float inv = 1.f / rsum[qr];
        float4 o;
        o.x = acc[i][0] * inv;
        o.y = acc[i][1] * inv;
        o.z = acc[i][2] * inv;
        o.w = acc[i][3] * inv;
        *(float4*)&g_x[(size_t)((b << 10) + q0 + qr) * DD + (h << 6) + tx * 4] = o;
    }
}

// ---------------- launch ------------------------------------------------------
extern "C" void kernel_launch(void* const* d_in, const int* in_sizes, int n_in,
                              void* d_out, int out_size) {
    const float* query = (const float*)d_in[0];
    const float* key   = (const float*)d_in[1];
    const float* value = (const float*)d_in[2];
    const int*   mask  = (const int*)d_in[3];
    const float* wq = (const float*)d_in[4];
    const float* bq = (const float*)d_in[5];
    const float* wk = (const float*)d_in[6];
    const float* bk = (const float*)d_in[7];
    const float* wv = (const float*)d_in[8];
    const float* bv = (const float*)d_in[9];
    const float* wo = (const float*)d_in[10];
    const float* bo = (const float*)d_in[11];
    const float* spatial_w = (const float*)d_in[12];
    const float* spatial_b = (const float*)d_in[13];
    const float* qproj_w = (const float*)d_in[14];
    const float* qproj_b = (const float*)d_in[15];
    const float* kproj_w = (const float*)d_in[16];
    const float* kproj_b = (const float*)d_in[17];
    const float* vlin_w = (const float*)d_in[18];
    const float* vlin_b = (const float*)d_in[19];
    const float* chan_w = (const float*)d_in[20];
    const float* chan_b = (const float*)d_in[21];
    float* out = (float*)d_out;

    // resolve device-global addresses
    float *p_wqf, *p_wkf, *p_wvf, *p_bqf, *p_bkf, *p_bvf;
    float *p_qs, *p_k2, *p_v2, *p_x;
    cudaGetSymbolAddress((void**)&p_wqf, g_wqf);
    cudaGetSymbolAddress((void**)&p_wkf, g_wkf);
    cudaGetSymbolAddress((void**)&p_wvf, g_wvf);
    cudaGetSymbolAddress((void**)&p_bqf, g_bqf);
    cudaGetSymbolAddress((void**)&p_bkf, g_bkf);
    cudaGetSymbolAddress((void**)&p_bvf, g_bvf);
    cudaGetSymbolAddress((void**)&p_qs, g_qs);
    cudaGetSymbolAddress((void**)&p_k2, g_k2);
    cudaGetSymbolAddress((void**)&p_v2, g_v2);
    cudaGetSymbolAddress((void**)&p_x, g_x);

    // 1. fold small projections into big weights
    fold_w_kernel<<<dim3(DD * DD / 256, 3), 256>>>(wq, wk, wv, spatial_w, kproj_w, vlin_w);
    // 2. biases / chan fold / qv
    small_prep_kernel<<<141, 256>>>(bq, bk, bv, spatial_w, kproj_w, vlin_w,
                                    spatial_b, kproj_b, vlin_b,
                                    wk, chan_w, chan_b, qproj_w, qproj_b);
    // 3. big GEMMs with fused ELU
    dim3 ggrid(DD / 128, MM / 128);
    gemm_bias_act<1><<<ggrid, 256>>>(query, p_wqf, p_bqf, p_qs, MM, DD, DD);
    gemm_bias_act<1><<<ggrid, 256>>>(key,   p_wkf, p_bkf, p_k2, MM, DD, DD);
    gemm_bias_act<1><<<ggrid, 256>>>(value, p_wvf, p_bvf, p_v2, MM, DD, DD);
    // 4. ck/cb gate scalars
    ckcb_kernel<<<MM / 8, 256>>>(key);
    // 5. m scalar per (b,h,q)
    m_kernel<<<(BB * HH * SS) / 256, 256>>>();
    // 6. fused attention
    int smem = (3 * 64 * ATT_STRIDE + 6 * 64) * (int)sizeof(float);
    cudaFuncSetAttribute(attn_kernel, cudaFuncAttributeMaxDynamicSharedMemorySize, smem);
    attn_kernel<<<dim3(SS / 64, HH, BB), 256, smem>>>(mask);
    // 7. output projection
    gemm_bias_act<0><<<ggrid, 256>>>(p_x, wo, bo, out, MM, DD, DD);
}

// round 4
// speedup vs baseline: 1.7978x; 1.7978x over previous
#include <cuda_runtime.h>
#include <math.h>
#include <stdint.h>

#define BB 4
#define SS 1024
#define DD 1024
#define HH 16
#define DK 64
#define MM (BB * SS)   // 4096

// ---------------- scratch (device globals; no allocation allowed) -------------
__device__ float g_wqf[DD * DD];
__device__ float g_wkf[DD * DD];
__device__ float g_wvf[DD * DD];
__device__ float g_wof[DD * DD];
__device__ float g_bqf[DD];
__device__ float g_bkf[DD];
__device__ float g_bvf[DD];
__device__ float g_wck[DD * HH];
__device__ float g_wcb[DD * HH];
__device__ float g_bck[HH];
__device__ float g_bcb[HH];
__device__ float g_qv[DK];
__device__ float g_bmean;
__device__ float g_qs[MM * DD];
__device__ float g_k2[MM * DD];
__device__ float g_v2[MM * DD];
__device__ float g_x[MM * DD];
__device__ float g_acvt[MM * DD];   // tf32-rounded activation staging
__device__ float g_m[BB * HH * SS];
__device__ float g_ck[MM * HH];
__device__ float g_cb[MM * HH];

__device__ __forceinline__ float tf32r(float x) {
    float y;
    asm("cvt.rna.tf32.f32 %0, %1;" : "=f"(y) : "f"(x));
    return y;
}

// ---------------- 0. elementwise tf32 rounding pass ---------------------------
__global__ void tf32_cvt_kernel(const float* __restrict__ in, float* __restrict__ out) {
    int i = (blockIdx.x * 256 + threadIdx.x);
    float4 v = *(const float4*)(in + (size_t)i * 4);
    v.x = tf32r(v.x); v.y = tf32r(v.y); v.z = tf32r(v.z); v.w = tf32r(v.w);
    *(float4*)(out + (size_t)i * 4) = v;
}

// ---------------- 1. fold per-head 64x64 projections into the big weights ----
// out[d, h*64+e'] = sum_e W[d, h*64+e] * P[e, e']   (output tf32-rounded)
__global__ void fold_w_kernel(const float* __restrict__ wq,
                              const float* __restrict__ wk,
                              const float* __restrict__ wv,
                              const float* __restrict__ sw,
                              const float* __restrict__ kp,
                              const float* __restrict__ vl) {
    int f = blockIdx.y;
    int idx = blockIdx.x * 256 + threadIdx.x;
    const float* W = (f == 0) ? wq : (f == 1) ? wk : wv;
    const float* P = (f == 0) ? sw : (f == 1) ? kp : vl;
    float* O = (f == 0) ? g_wqf : (f == 1) ? g_wkf : g_wvf;
    int d = idx >> 10;
    int c = idx & 1023;
    int h = c >> 6;
    int ep = c & 63;
    const float* wrow = W + d * DD + (h << 6);
    float sum = 0.f;
#pragma unroll 8
    for (int e = 0; e < DK; e++) sum += wrow[e] * P[e * DK + ep];
    O[idx] = tf32r(sum);
}

// ---------------- 2. small precompute -----------------------------------------
__global__ void small_prep_kernel(const float* __restrict__ bq,
                                  const float* __restrict__ bk,
                                  const float* __restrict__ bv,
                                  const float* __restrict__ sw,
                                  const float* __restrict__ kp,
                                  const float* __restrict__ vl,
                                  const float* __restrict__ sb,
                                  const float* __restrict__ kpb,
                                  const float* __restrict__ vlb,
                                  const float* __restrict__ wk,
                                  const float* __restrict__ chan_w,
                                  const float* __restrict__ chan_b,
                                  const float* __restrict__ qproj_w,
                                  const float* __restrict__ qproj_b) {
    int T = blockIdx.x * 256 + threadIdx.x;
    if (T < 3072) {
        int f = T >> 10;
        int c = T & 1023;
        int h = c >> 6;
        int ep = c & 63;
        const float* b = (f == 0) ? bq : (f == 1) ? bk : bv;
        const float* P = (f == 0) ? sw : (f == 1) ? kp : vl;
        const float* pb = (f == 0) ? sb : (f == 1) ? kpb : vlb;
        float* O = (f == 0) ? g_bqf : (f == 1) ? g_bkf : g_bvf;
        float sum = pb[ep];
        for (int e = 0; e < DK; e++) sum += b[(h << 6) + e] * P[e * DK + ep];
        O[c] = sum;
        return;
    }
    T -= 3072;
    if (T < 16384) {
        int d = T >> 4, h = T & 15;
        float sum = 0.f;
        for (int e = 0; e < DK; e++) sum += wk[d * DD + (h << 6) + e] * chan_w[e];
        g_wck[d * HH + h] = sum;
        return;
    }
    T -= 16384;
    if (T < 16384) {
        int d = T >> 4, h = T & 15;
        float sum = 0.f;
        for (int e = 0; e < DK; e++) sum += wk[d * DD + (h << 6) + e] * chan_b[e];
        g_wcb[d * HH + h] = sum;
        return;
    }
    T -= 16384;
    if (T < 16) {
        float sum = 0.f;
        for (int e = 0; e < DK; e++) sum += bk[(T << 6) + e] * chan_w[e];
        g_bck[T] = sum;
        return;
    }
    T -= 16;
    if (T < 16) {
        float sum = 0.f;
        for (int e = 0; e < DK; e++) sum += bk[(T << 6) + e] * chan_b[e];
        g_bcb[T] = sum;
        return;
    }
    T -= 16;
    if (T < 64) {
        float sum = 0.f;
        for (int ep = 0; ep < DK; ep++) sum += qproj_w[T * DK + ep];
        g_qv[T] = sum * (1.f / 64.f);
        return;
    }
    T -= 64;
    if (T == 0) {
        float sum = 0.f;
        for (int ep = 0; ep < DK; ep++) sum += qproj_b[ep];
        g_bmean = sum * (1.f / 64.f);
    }
}

// ---------------- 3. tf32 tensor-core GEMM: C = act(A @ W + bias) -------------
// A [M,K] rm (pre-rounded tf32), W [K,N] rm (pre-rounded tf32).
// 128x128 block tile, BK=16, 4-stage cp.async, 8 warps (2x4), 64x32 warp tile.
#define GSTAGES 4
#define GBK 16
#define AST 20     // padded A smem stride (bank-conflict-free for fragment loads)
#define BST 136    // padded B smem stride (bank-conflict-free)
#define ASZ (128 * AST)
#define BSZ (GBK * BST)

__device__ __forceinline__ void cpa16(float* dst, const float* src) {
    unsigned d = (unsigned)__cvta_generic_to_shared(dst);
    asm volatile("cp.async.cg.shared.global [%0], [%1], 16;\n" :: "r"(d), "l"(src));
}

__device__ __forceinline__ void gemm_load_stage(float* As, float* Bs,
                                                const float* A, const float* Bm,
                                                int brow, int bcol, int kt, int tid,
                                                int Kk, int Nn) {
#pragma unroll
    for (int l = 0; l < 2; l++) {
        int lin = tid + l * 256;
        int row = lin >> 2, c4 = (lin & 3) << 2;
        cpa16(&As[row * AST + c4], &A[(size_t)(brow + row) * Kk + kt * GBK + c4]);
    }
#pragma unroll
    for (int l = 0; l < 2; l++) {
        int lin = tid + l * 256;
        int kr = lin >> 5, c4 = (lin & 31) << 2;
        cpa16(&Bs[kr * BST + c4], &Bm[(size_t)(kt * GBK + kr) * Nn + bcol + c4]);
    }
}

#define MMA_TF32(d, a, b) \
    asm volatile("mma.sync.aligned.m16n8k8.row.col.f32.tf32.tf32.f32 " \
                 "{%0,%1,%2,%3},{%4,%5,%6,%7},{%8,%9},{%0,%1,%2,%3};" \
                 : "+f"(d[0]), "+f"(d[1]), "+f"(d[2]), "+f"(d[3]) \
                 : "r"(a[0]), "r"(a[1]), "r"(a[2]), "r"(a[3]), "r"(b[0]), "r"(b[1]));

template <int ACT>   // 0 = none, 1 = elu
__global__ void __launch_bounds__(256, 2)
gemm_tf32(const float* __restrict__ A,
          const float* __restrict__ Bm,
          const float* __restrict__ bias,
          float* __restrict__ C,
          int Mm, int Nn, int Kk) {
    extern __shared__ float smem[];
    float* Asm = smem;
    float* Bsm = smem + GSTAGES * ASZ;

    int tid = threadIdx.x;
    int brow = blockIdx.y * 128;
    int bcol = blockIdx.x * 128;
    int warp = tid >> 5;
    int lane = tid & 31;
    int gr = lane >> 2;      // group id (0..7)
    int gc = lane & 3;       // thread in group (0..3)
    int wrow = (warp >> 2) * 64;   // warp row origin within block tile
    int wcol = (warp & 3) * 32;    // warp col origin

    float acc[4][4][4];
#pragma unroll
    for (int mt = 0; mt < 4; mt++)
#pragma unroll
        for (int nt = 0; nt < 4; nt++)
#pragma unroll
            for (int r = 0; r < 4; r++) acc[mt][nt][r] = 0.f;

    const int KT = Kk / GBK;
    // prologue
#pragma unroll
    for (int s = 0; s < GSTAGES - 1; s++) {
        gemm_load_stage(Asm + s * ASZ, Bsm + s * BSZ, A, Bm, brow, bcol, s, tid, Kk, Nn);
        asm volatile("cp.async.commit_group;\n");
    }

    for (int kt = 0; kt < KT; kt++) {
        asm volatile("cp.async.wait_group %0;\n" :: "n"(GSTAGES - 2));
        __syncthreads();
        int s = kt & (GSTAGES - 1);
        float* As = Asm + s * ASZ;
        float* Bs = Bsm + s * BSZ;
#pragma unroll
        for (int kb = 0; kb < GBK; kb += 8) {
            uint32_t af[4][4], bf[4][2];
#pragma unroll
            for (int mt = 0; mt < 4; mt++) {
                int row0 = wrow + mt * 16 + gr;
                af[mt][0] = __float_as_uint(As[row0 * AST + kb + gc]);
                af[mt][1] = __float_as_uint(As[(row0 + 8) * AST + kb + gc]);
                af[mt][2] = __float_as_uint(As[row0 * AST + kb + gc + 4]);
                af[mt][3] = __float_as_uint(As[(row0 + 8) * AST + kb + gc + 4]);
            }
#pragma unroll
            for (int nt = 0; nt < 4; nt++) {
                int col0 = wcol + nt * 8 + gr;
                bf[nt][0] = __float_as_uint(Bs[(kb + gc) * BST + col0]);
                bf[nt][1] = __float_as_uint(Bs[(kb + gc + 4) * BST + col0]);
            }
#pragma unroll
            for (int mt = 0; mt < 4; mt++)
#pragma unroll
                for (int nt = 0; nt < 4; nt++)
                    MMA_TF32(acc[mt][nt], af[mt], bf[nt]);
        }
        int nk = kt + GSTAGES - 1;
        if (nk < KT)
            gemm_load_stage(Asm + (nk & (GSTAGES - 1)) * ASZ,
                            Bsm + (nk & (GSTAGES - 1)) * BSZ,
                            A, Bm, brow, bcol, nk, tid, Kk, Nn);
        asm volatile("cp.async.commit_group;\n");
    }

    // epilogue: bias + optional ELU
#pragma unroll
    for (int mt = 0; mt < 4; mt++) {
        int r0 = brow + wrow + mt * 16 + gr;
#pragma unroll
        for (int nt = 0; nt < 4; nt++) {
            int c0 = bcol + wcol + nt * 8 + (gc << 1);
            float b0 = bias[c0], b1 = bias[c0 + 1];
            float v0 = acc[mt][nt][0] + b0;
            float v1 = acc[mt][nt][1] + b1;
            float v2 = acc[mt][nt][2] + b0;
            float v3 = acc[mt][nt][3] + b1;
            if (ACT == 1) {
                v0 = v0 > 0.f ? v0 : expm1f(v0);
                v1 = v1 > 0.f ? v1 : expm1f(v1);
                v2 = v2 > 0.f ? v2 : expm1f(v2);
                v3 = v3 > 0.f ? v3 : expm1f(v3);
            }
            float2 o01 = make_float2(v0, v1);
            float2 o23 = make_float2(v2, v3);
            *(float2*)&C[(size_t)r0 * Nn + c0] = o01;
            *(float2*)&C[(size_t)(r0 + 8) * Nn + c0] = o23;
        }
    }
}

// ---------------- 4. ck/cb skinny GEMV: key @ wck / wcb -----------------------
__global__ void ckcb_kernel(const float* __restrict__ key) {
    __shared__ float rows[8][1024];
    int tid = threadIdx.x;
    int row0 = blockIdx.x * 8;
#pragma unroll
    for (int l = 0; l < 8; l++) {
        int lin = tid + l * 256;
        int r = lin >> 8;
        int c4 = (lin & 255) << 2;
        *(float4*)&rows[r][c4] = *(const float4*)&key[(size_t)(row0 + r) * DD + c4];
    }
    __syncthreads();
    int r = tid >> 5;
    int o = tid & 31;
    int h = o & 15;
    int isB = o >> 4;
    const float* wp = isB ? g_wcb : g_wck;
    float sum = isB ? g_bcb[h] : g_bck[h];
#pragma unroll 8
    for (int d = 0; d < DD; d++) sum += rows[r][d] * wp[d * HH + h];
    (isB ? g_cb : g_ck)[(size_t)(row0 + r) * HH + h] = sum;
}

// ---------------- 5. per-query scalar m = qs . qv + bmean ---------------------
__global__ void m_kernel() {
    int i = blockIdx.x * 256 + threadIdx.x;
    int b = i >> 14;
    int h = (i >> 10) & 15;
    int s = i & 1023;
    const float* q = g_qs + ((size_t)((b << 10) + s) << 10) + (h << 6);
    float sum = g_bmean;
#pragma unroll 8
    for (int e = 0; e < DK; e++) sum += q[e] * g_qv[e];
    g_m[i] = sum;
}

// ---------------- 6. fused flash attention with xlinear gate ------------------
// scores = (qs.k2)/8 * sigmoid(m_q*ck + cb); mask; online softmax; out = P @ v2
#define ATT_STRIDE 68
__global__ void attn_kernel(const int* __restrict__ mask) {
    extern __shared__ float sm[];
    float* Qs = sm;                        // Q^T [e][r]
    float* Ks = Qs + 64 * ATT_STRIDE;      // K^T [e][c]
    float* Vs = Ks + 64 * ATT_STRIDE;      // V   [k][e]
    float* Ps = Vs + 64 * ATT_STRIDE;      // P   [k][r]
    float* ckv = Ps + 64 * ATT_STRIDE;
    float* cbv = ckv + 64;

    int tid = threadIdx.x;
    int q0 = blockIdx.x * 64;
    int h = blockIdx.y;
    int b = blockIdx.z;
    int ty = tid >> 4, tx = tid & 15;

    // per-row state in registers (replicated across the 16 lanes of a row group)
    float rm[4], rs[4], mq[4];
#pragma unroll
    for (int i = 0; i < 4; i++) {
        rm[i] = -INFINITY;
        rs[i] = 0.f;
        mq[i] = g_m[(size_t)((b * HH + h) << 10) + q0 + ty * 4 + i];
    }

    // load Q tile transposed
#pragma unroll
    for (int l = 0; l < 4; l++) {
        int lin = tid + l * 256;
        int r = lin >> 4;
        int e4 = (lin & 15) << 2;
        float4 v = *(const float4*)&g_qs[(size_t)((b << 10) + q0 + r) * DD + (h << 6) + e4];
        Qs[(e4 + 0) * ATT_STRIDE + r] = v.x;
        Qs[(e4 + 1) * ATT_STRIDE + r] = v.y;
        Qs[(e4 + 2) * ATT_STRIDE + r] = v.z;
        Qs[(e4 + 3) * ATT_STRIDE + r] = v.w;
    }
    float acc[4][4];
#pragma unroll
    for (int i = 0; i < 4; i++)
#pragma unroll
        for (int j = 0; j < 4; j++) acc[i][j] = 0.f;
    __syncthreads();

    for (int kt = 0; kt < 16; kt++) {
        int k0 = kt * 64;
#pragma unroll
        for (int l = 0; l < 4; l++) {
            int lin = tid + l * 256;
            int r = lin >> 4;
            int e4 = (lin & 15) << 2;
            float4 kv = *(const float4*)&g_k2[(size_t)((b << 10) + k0 + r) * DD + (h << 6) + e4];
            Ks[(e4 + 0) * ATT_STRIDE + r] = kv.x;
            Ks[(e4 + 1) * ATT_STRIDE + r] = kv.y;
            Ks[(e4 + 2) * ATT_STRIDE + r] = kv.z;
            Ks[(e4 + 3) * ATT_STRIDE + r] = kv.w;
            float4 vv = *(const float4*)&g_v2[(size_t)((b << 10) + k0 + r) * DD + (h << 6) + e4];
            *(float4*)&Vs[r * ATT_STRIDE + e4] = vv;
        }
        if (tid < 64) {
            ckv[tid] = g_ck[(size_t)((b << 10) + k0 + tid) * HH + h];
            cbv[tid] = g_cb[(size_t)((b << 10) + k0 + tid) * HH + h];
        }
        __syncthreads();

        // scores: 4x4 micro-GEMM over e
        float s[4][4];
#pragma unroll
        for (int i = 0; i < 4; i++)
#pragma unroll
            for (int j = 0; j < 4; j++) s[i][j] = 0.f;
#pragma unroll
        for (int e = 0; e < 64; e++) {
            float4 qa = *(float4*)&Qs[e * ATT_STRIDE + ty * 4];
            float4 kb = *(float4*)&Ks[e * ATT_STRIDE + tx * 4];
            float qr[4] = {qa.x, qa.y, qa.z, qa.w};
            float kc[4] = {kb.x, kb.y, kb.z, kb.w};
#pragma unroll
            for (int i = 0; i < 4; i++)
#pragma unroll
                for (int j = 0; j < 4; j++) s[i][j] = fmaf(qr[i], kc[j], s[i][j]);
        }
        // gate + mask
#pragma unroll
        for (int i = 0; i < 4; i++) {
            int qr = q0 + ty * 4 + i;
            const int* mptr = mask + (size_t)(b * SS + qr) * SS + k0;
#pragma unroll
            for (int j = 0; j < 4; j++) {
                int kc = tx * 4 + j;
                float val = s[i][j] * 0.125f;
                float logit = fmaf(mq[i], ckv[kc], cbv[kc]);
                float gate = __fdividef(1.f, 1.f + __expf(-logit));
                val *= gate;
                if (mptr[kc] == 0) val = -1e9f;
                s[i][j] = val;
            }
        }
        // parallel online softmax: reduce across the 16 lanes of each row group
#pragma unroll
        for (int i = 0; i < 4; i++) {
            float pm = fmaxf(fmaxf(s[i][0], s[i][1]), fmaxf(s[i][2], s[i][3]));
#pragma unroll
            for (int m = 1; m < 16; m <<= 1)
                pm = fmaxf(pm, __shfl_xor_sync(0xffffffffu, pm, m));
            float tm = fmaxf(rm[i], pm);
            float scale = __expf(rm[i] - tm);
            rm[i] = tm;
            float psum = 0.f;
#pragma unroll
            for (int j = 0; j < 4; j++) {
                s[i][j] = __expf(s[i][j] - tm);
                psum += s[i][j];
            }
#pragma unroll
            for (int m = 1; m < 16; m <<= 1)
                psum += __shfl_xor_sync(0xffffffffu, psum, m);
            rs[i] = rs[i] * scale + psum;
#pragma unroll
            for (int j = 0; j < 4; j++) acc[i][j] *= scale;
        }
        // stage P (transposed) into its own buffer — Ks stays intact
#pragma unroll
        for (int i = 0; i < 4; i++)
#pragma unroll
            for (int j = 0; j < 4; j++)
                Ps[(tx * 4 + j) * ATT_STRIDE + ty * 4 + i] = s[i][j];
        __syncthreads();
        // accumulate P @ V
#pragma unroll
        for (int k = 0; k < 64; k++) {
            float4 pa = *(float4*)&Ps[k * ATT_STRIDE + ty * 4];
            float4 va = *(float4*)&Vs[k * ATT_STRIDE + tx * 4];
            float pr[4] = {pa.x, pa.y, pa.z, pa.w};
            float vc[4] = {va.x, va.y, va.z, va.w};
#pragma unroll
            for (int i = 0; i < 4; i++)
#pragma unroll
                for (int j = 0; j < 4; j++) acc[i][j] = fmaf(pr[i], vc[j], acc[i][j]);
        }
        __syncthreads();   // before next tile overwrites Ks/Vs/Ps
    }
    // normalize + write (tf32-rounded: feeds the tf32 out-projection GEMM)
#pragma unroll
    for (int i = 0; i < 4; i++) {
        int qr = ty * 4 + i;
        float inv = 1.f / rs[i];
        float4 o;
        o.x = tf32r(acc[i][0] * inv);
        o.y = tf32r(acc[i][1] * inv);
        o.z = tf32r(acc[i][2] * inv);
        o.w = tf32r(acc[i][3] * inv);
        *(float4*)&g_x[(size_t)((b << 10) + q0 + qr) * DD + (h << 6) + tx * 4] = o;
    }
}

// ---------------- launch ------------------------------------------------------
extern "C" void kernel_launch(void* const* d_in, const int* in_sizes, int n_in,
                              void* d_out, int out_size) {
    const float* query = (const float*)d_in[0];
    const float* key   = (const float*)d_in[1];
    const float* value = (const float*)d_in[2];
    const int*   mask  = (const int*)d_in[3];
    const float* wq = (const float*)d_in[4];
    const float* bq = (const float*)d_in[5];
    const float* wk = (const float*)d_in[6];
    const float* bk = (const float*)d_in[7];
    const float* wv = (const float*)d_in[8];
    const float* bv = (const float*)d_in[9];
    const float* wo = (const float*)d_in[10];
    const float* bo = (const float*)d_in[11];
    const float* spatial_w = (const float*)d_in[12];
    const float* spatial_b = (const float*)d_in[13];
    const float* qproj_w = (const float*)d_in[14];
    const float* qproj_b = (const float*)d_in[15];
    const float* kproj_w = (const float*)d_in[16];
    const float* kproj_b = (const float*)d_in[17];
    const float* vlin_w = (const float*)d_in[18];
    const float* vlin_b = (const float*)d_in[19];
    const float* chan_w = (const float*)d_in[20];
    const float* chan_b = (const float*)d_in[21];
    float* out = (float*)d_out;

    float *p_wqf, *p_wkf, *p_wvf, *p_wof, *p_bqf, *p_bkf, *p_bvf;
    float *p_qs, *p_k2, *p_v2, *p_x, *p_acvt;
    cudaGetSymbolAddress((void**)&p_wqf, g_wqf);
    cudaGetSymbolAddress((void**)&p_wkf, g_wkf);
    cudaGetSymbolAddress((void**)&p_wvf, g_wvf);
    cudaGetSymbolAddress((void**)&p_wof, g_wof);
    cudaGetSymbolAddress((void**)&p_bqf, g_bqf);
    cudaGetSymbolAddress((void**)&p_bkf, g_bkf);
    cudaGetSymbolAddress((void**)&p_bvf, g_bvf);
    cudaGetSymbolAddress((void**)&p_qs, g_qs);
    cudaGetSymbolAddress((void**)&p_k2, g_k2);
    cudaGetSymbolAddress((void**)&p_v2, g_v2);
    cudaGetSymbolAddress((void**)&p_x, g_x);
    cudaGetSymbolAddress((void**)&p_acvt, g_acvt);

    int gsmem = GSTAGES * (ASZ + BSZ) * (int)sizeof(float);   // ~75.8 KB
    cudaFuncSetAttribute(gemm_tf32<1>, cudaFuncAttributeMaxDynamicSharedMemorySize, gsmem);
    cudaFuncSetAttribute(gemm_tf32<0>, cudaFuncAttributeMaxDynamicSharedMemorySize, gsmem);
    int asmem = (4 * 64 * ATT_STRIDE + 2 * 64) * (int)sizeof(float);  // ~70.1 KB
    cudaFuncSetAttribute(attn_kernel, cudaFuncAttributeMaxDynamicSharedMemorySize, asmem);

    // 1. fold small projections into big weights (tf32-rounded)
    fold_w_kernel<<<dim3(DD * DD / 256, 3), 256>>>(wq, wk, wv, spatial_w, kproj_w, vlin_w);
    // 2. biases / chan fold / qv
    small_prep_kernel<<<141, 256>>>(bq, bk, bv, spatial_w, kproj_w, vlin_w,
                                    spatial_b, kproj_b, vlin_b,
                                    wk, chan_w, chan_b, qproj_w, qproj_b);
    // 3. round wo
    tf32_cvt_kernel<<<DD * DD / 1024, 256>>>(wo, p_wof);

    dim3 ggrid(DD / 128, MM / 128);
    // 4-6. activations: round then tensor-core GEMM with fused ELU
    tf32_cvt_kernel<<<MM * DD / 1024, 256>>>(query, p_acvt);
    gemm_tf32<1><<<ggrid, 256, gsmem>>>(p_acvt, p_wqf, p_bqf, p_qs, MM, DD, DD);
    tf32_cvt_kernel<<<MM * DD / 1024, 256>>>(key, p_acvt);
    gemm_tf32<1><<<ggrid, 256, gsmem>>>(p_acvt, p_wkf, p_bkf, p_k2, MM, DD, DD);
    tf32_cvt_kernel<<<MM * DD / 1024, 256>>>(value, p_acvt);
    gemm_tf32<1><<<ggrid, 256, gsmem>>>(p_acvt, p_wvf, p_bvf, p_v2, MM, DD, DD);
    // 7. ck/cb gate scalars (reads raw key)
    ckcb_kernel<<<MM / 8, 256>>>(key);
    // 8. m scalar per (b,h,q)
    m_kernel<<<(BB * HH * SS) / 256, 256>>>();
    // 9. fused attention (writes tf32-rounded g_x)
    attn_kernel<<<dim3(SS / 64, HH, BB), 256, asmem>>>(mask);
    // 10. output projection
    gemm_tf32<0><<<ggrid, 256, gsmem>>>(p_x, p_wof, bo, out, MM, DD, DD);
}

// round 5
// speedup vs baseline: 2.5081x; 1.3951x over previous
#include <cuda_runtime.h>
#include <math.h>
#include <stdint.h>

#define BB 4
#define SS 1024
#define DD 1024
#define HH 16
#define DK 64
#define MM (BB * SS)   // 4096

// ---------------- scratch (device globals; no allocation allowed) -------------
__device__ float g_wqf[DD * DD];
__device__ float g_wkf[DD * DD];
__device__ float g_wvf[DD * DD];
__device__ float g_wof[DD * DD];
__device__ float g_bqf[DD];
__device__ float g_bkf[DD];
__device__ float g_bvf[DD];
__device__ float g_wck[DD * HH];
__device__ float g_wcb[DD * HH];
__device__ float g_bck[HH];
__device__ float g_bcb[HH];
__device__ float g_qv[DK];
__device__ float g_bmean;
__device__ float g_qs[MM * DD];
__device__ float g_k2[MM * DD];
__device__ float g_v2[MM * DD];
__device__ float g_x[MM * DD];
__device__ float g_acvt[MM * DD];   // tf32-rounded activation staging
__device__ float g_m[BB * HH * SS];
__device__ float g_ck[MM * HH];
__device__ float g_cb[MM * HH];
__device__ unsigned g_pm[BB * SS * SS / 32];   // packed mask bits

__device__ __forceinline__ float tf32r(float x) {
    float y;
    asm("cvt.rna.tf32.f32 %0, %1;" : "=f"(y) : "f"(x));
    return y;
}

#define MMA_TF32(d, a, b) \
    asm volatile("mma.sync.aligned.m16n8k8.row.col.f32.tf32.tf32.f32 " \
                 "{%0,%1,%2,%3},{%4,%5,%6,%7},{%8,%9},{%0,%1,%2,%3};" \
                 : "+f"(d[0]), "+f"(d[1]), "+f"(d[2]), "+f"(d[3]) \
                 : "r"(a[0]), "r"(a[1]), "r"(a[2]), "r"(a[3]), "r"(b[0]), "r"(b[1]));

// ---------------- 0. elementwise tf32 rounding pass ---------------------------
__global__ void tf32_cvt_kernel(const float* __restrict__ in, float* __restrict__ out) {
    int i = (blockIdx.x * 256 + threadIdx.x);
    float4 v = *(const float4*)(in + (size_t)i * 4);
    v.x = tf32r(v.x); v.y = tf32r(v.y); v.z = tf32r(v.z); v.w = tf32r(v.w);
    *(float4*)(out + (size_t)i * 4) = v;
}

// ---------------- 0b. pack mask into bits -------------------------------------
__global__ void mask_pack_kernel(const int* __restrict__ mask) {
    int t = blockIdx.x * 256 + threadIdx.x;       // [0, B*S*S)
    int v = mask[t];
    unsigned bal = __ballot_sync(0xffffffffu, v != 0);
    if ((threadIdx.x & 31) == 0) g_pm[t >> 5] = bal;
}

// ---------------- 1. fold per-head 64x64 projections into the big weights ----
__global__ void fold_w_kernel(const float* __restrict__ wq,
                              const float* __restrict__ wk,
                              const float* __restrict__ wv,
                              const float* __restrict__ sw,
                              const float* __restrict__ kp,
                              const float* __restrict__ vl) {
    int f = blockIdx.y;
    int idx = blockIdx.x * 256 + threadIdx.x;
    const float* W = (f == 0) ? wq : (f == 1) ? wk : wv;
    const float* P = (f == 0) ? sw : (f == 1) ? kp : vl;
    float* O = (f == 0) ? g_wqf : (f == 1) ? g_wkf : g_wvf;
    int d = idx >> 10;
    int c = idx & 1023;
    int h = c >> 6;
    int ep = c & 63;
    const float* wrow = W + d * DD + (h << 6);
    float sum = 0.f;
#pragma unroll 8
    for (int e = 0; e < DK; e++) sum += wrow[e] * P[e * DK + ep];
    O[idx] = tf32r(sum);
}

// ---------------- 2. small precompute -----------------------------------------
__global__ void small_prep_kernel(const float* __restrict__ bq,
                                  const float* __restrict__ bk,
                                  const float* __restrict__ bv,
                                  const float* __restrict__ sw,
                                  const float* __restrict__ kp,
                                  const float* __restrict__ vl,
                                  const float* __restrict__ sb,
                                  const float* __restrict__ kpb,
                                  const float* __restrict__ vlb,
                                  const float* __restrict__ wk,
                                  const float* __restrict__ chan_w,
                                  const float* __restrict__ chan_b,
                                  const float* __restrict__ qproj_w,
                                  const float* __restrict__ qproj_b) {
    int T = blockIdx.x * 256 + threadIdx.x;
    if (T < 3072) {
        int f = T >> 10;
        int c = T & 1023;
        int h = c >> 6;
        int ep = c & 63;
        const float* b = (f == 0) ? bq : (f == 1) ? bk : bv;
        const float* P = (f == 0) ? sw : (f == 1) ? kp : vl;
        const float* pb = (f == 0) ? sb : (f == 1) ? kpb : vlb;
        float* O = (f == 0) ? g_bqf : (f == 1) ? g_bkf : g_bvf;
        float sum = pb[ep];
        for (int e = 0; e < DK; e++) sum += b[(h << 6) + e] * P[e * DK + ep];
        O[c] = sum;
        return;
    }
    T -= 3072;
    if (T < 16384) {
        int d = T >> 4, h = T & 15;
        float sum = 0.f;
        for (int e = 0; e < DK; e++) sum += wk[d * DD + (h << 6) + e] * chan_w[e];
        g_wck[d * HH + h] = sum;
        return;
    }
    T -= 16384;
    if (T < 16384) {
        int d = T >> 4, h = T & 15;
        float sum = 0.f;
        for (int e = 0; e < DK; e++) sum += wk[d * DD + (h << 6) + e] * chan_b[e];
        g_wcb[d * HH + h] = sum;
        return;
    }
    T -= 16384;
    if (T < 16) {
        float sum = 0.f;
        for (int e = 0; e < DK; e++) sum += bk[(T << 6) + e] * chan_w[e];
        g_bck[T] = sum;
        return;
    }
    T -= 16;
    if (T < 16) {
        float sum = 0.f;
        for (int e = 0; e < DK; e++) sum += bk[(T << 6) + e] * chan_b[e];
        g_bcb[T] = sum;
        return;
    }
    T -= 16;
    if (T < 64) {
        float sum = 0.f;
        for (int ep = 0; ep < DK; ep++) sum += qproj_w[T * DK + ep];
        g_qv[T] = sum * (1.f / 64.f);
        return;
    }
    T -= 64;
    if (T == 0) {
        float sum = 0.f;
        for (int ep = 0; ep < DK; ep++) sum += qproj_b[ep];
        g_bmean = sum * (1.f / 64.f);
    }
}

// ---------------- 3. tf32 tensor-core GEMM: C = act(A @ W + bias) -------------
#define GSTAGES 4
#define GBK 16
#define AST 20
#define BST 136
#define ASZ (128 * AST)
#define BSZ (GBK * BST)

__device__ __forceinline__ void cpa16(float* dst, const float* src) {
    unsigned d = (unsigned)__cvta_generic_to_shared(dst);
    asm volatile("cp.async.cg.shared.global [%0], [%1], 16;\n" :: "r"(d), "l"(src));
}

__device__ __forceinline__ void gemm_load_stage(float* As, float* Bs,
                                                const float* A, const float* Bm,
                                                int brow, int bcol, int kt, int tid,
                                                int Kk, int Nn) {
#pragma unroll
    for (int l = 0; l < 2; l++) {
        int lin = tid + l * 256;
        int row = lin >> 2, c4 = (lin & 3) << 2;
        cpa16(&As[row * AST + c4], &A[(size_t)(brow + row) * Kk + kt * GBK + c4]);
    }
#pragma unroll
    for (int l = 0; l < 2; l++) {
        int lin = tid + l * 256;
        int kr = lin >> 5, c4 = (lin & 31) << 2;
        cpa16(&Bs[kr * BST + c4], &Bm[(size_t)(kt * GBK + kr) * Nn + bcol + c4]);
    }
}

template <int ACT>   // 0 = none, 1 = elu
__global__ void __launch_bounds__(256, 2)
gemm_tf32(const float* __restrict__ A,
          const float* __restrict__ Bm,
          const float* __restrict__ bias,
          float* __restrict__ C,
          int Mm, int Nn, int Kk) {
    extern __shared__ float smem[];
    float* Asm = smem;
    float* Bsm = smem + GSTAGES * ASZ;

    int tid = threadIdx.x;
    int brow = blockIdx.y * 128;
    int bcol = blockIdx.x * 128;
    int warp = tid >> 5;
    int lane = tid & 31;
    int gr = lane >> 2;
    int gc = lane & 3;
    int wrow = (warp >> 2) * 64;
    int wcol = (warp & 3) * 32;

    float acc[4][4][4];
#pragma unroll
    for (int mt = 0; mt < 4; mt++)
#pragma unroll
        for (int nt = 0; nt < 4; nt++)
#pragma unroll
            for (int r = 0; r < 4; r++) acc[mt][nt][r] = 0.f;

    const int KT = Kk / GBK;
#pragma unroll
    for (int s = 0; s < GSTAGES - 1; s++) {
        gemm_load_stage(Asm + s * ASZ, Bsm + s * BSZ, A, Bm, brow, bcol, s, tid, Kk, Nn);
        asm volatile("cp.async.commit_group;\n");
    }

    for (int kt = 0; kt < KT; kt++) {
        asm volatile("cp.async.wait_group %0;\n" :: "n"(GSTAGES - 2));
        __syncthreads();
        int s = kt & (GSTAGES - 1);
        float* As = Asm + s * ASZ;
        float* Bs = Bsm + s * BSZ;
#pragma unroll
        for (int kb = 0; kb < GBK; kb += 8) {
            uint32_t af[4][4], bf[4][2];
#pragma unroll
            for (int mt = 0; mt < 4; mt++) {
                int row0 = wrow + mt * 16 + gr;
                af[mt][0] = __float_as_uint(As[row0 * AST + kb + gc]);
                af[mt][1] = __float_as_uint(As[(row0 + 8) * AST + kb + gc]);
                af[mt][2] = __float_as_uint(As[row0 * AST + kb + gc + 4]);
                af[mt][3] = __float_as_uint(As[(row0 + 8) * AST + kb + gc + 4]);
            }
#pragma unroll
            for (int nt = 0; nt < 4; nt++) {
                int col0 = wcol + nt * 8 + gr;
                bf[nt][0] = __float_as_uint(Bs[(kb + gc) * BST + col0]);
                bf[nt][1] = __float_as_uint(Bs[(kb + gc + 4) * BST + col0]);
            }
#pragma unroll
            for (int mt = 0; mt < 4; mt++)
#pragma unroll
                for (int nt = 0; nt < 4; nt++)
                    MMA_TF32(acc[mt][nt], af[mt], bf[nt]);
        }
        int nk = kt + GSTAGES - 1;
        if (nk < KT)
            gemm_load_stage(Asm + (nk & (GSTAGES - 1)) * ASZ,
                            Bsm + (nk & (GSTAGES - 1)) * BSZ,
                            A, Bm, brow, bcol, nk, tid, Kk, Nn);
        asm volatile("cp.async.commit_group;\n");
    }

#pragma unroll
    for (int mt = 0; mt < 4; mt++) {
        int r0 = brow + wrow + mt * 16 + gr;
#pragma unroll
        for (int nt = 0; nt < 4; nt++) {
            int c0 = bcol + wcol + nt * 8 + (gc << 1);
            float b0 = bias[c0], b1 = bias[c0 + 1];
            float v0 = acc[mt][nt][0] + b0;
            float v1 = acc[mt][nt][1] + b1;
            float v2 = acc[mt][nt][2] + b0;
            float v3 = acc[mt][nt][3] + b1;
            if (ACT == 1) {
                v0 = v0 > 0.f ? v0 : expm1f(v0);
                v1 = v1 > 0.f ? v1 : expm1f(v1);
                v2 = v2 > 0.f ? v2 : expm1f(v2);
                v3 = v3 > 0.f ? v3 : expm1f(v3);
            }
            *(float2*)&C[(size_t)r0 * Nn + c0] = make_float2(v0, v1);
            *(float2*)&C[(size_t)(r0 + 8) * Nn + c0] = make_float2(v2, v3);
        }
    }
}

// ---------------- 4. ck/cb skinny GEMV ----------------------------------------
__global__ void ckcb_kernel(const float* __restrict__ key) {
    __shared__ float rows[8][1024];
    int tid = threadIdx.x;
    int row0 = blockIdx.x * 8;
#pragma unroll
    for (int l = 0; l < 8; l++) {
        int lin = tid + l * 256;
        int r = lin >> 8;
        int c4 = (lin & 255) << 2;
        *(float4*)&rows[r][c4] = *(const float4*)&key[(size_t)(row0 + r) * DD + c4];
    }
    __syncthreads();
    int r = tid >> 5;
    int o = tid & 31;
    int h = o & 15;
    int isB = o >> 4;
    const float* wp = isB ? g_wcb : g_wck;
    float sum = isB ? g_bcb[h] : g_bck[h];
#pragma unroll 8
    for (int d = 0; d < DD; d++) sum += rows[r][d] * wp[d * HH + h];
    (isB ? g_cb : g_ck)[(size_t)(row0 + r) * HH + h] = sum;
}

// ---------------- 5. per-query scalar m ---------------------------------------
__global__ void m_kernel() {
    int i = blockIdx.x * 256 + threadIdx.x;
    int b = i >> 14;
    int h = (i >> 10) & 15;
    int s = i & 1023;
    const float* q = g_qs + ((size_t)((b << 10) + s) << 10) + (h << 6);
    float sum = g_bmean;
#pragma unroll 8
    for (int e = 0; e < DK; e++) sum += q[e] * g_qv[e];
    g_m[i] = sum;
}

// ---------------- 6. tensor-core flash attention with xlinear gate ------------
// CTA: 128 q-rows x (b,h). 8 warps x 16 q-rows. K-tiles of 64.
// scores = (Q.K2)/8 * sigmoid(m_q*ck + cb); mask; online softmax; O = P @ V2.
#define AS 68   // smem stride: B-fragment LDS bank = 4*gr+gc = lane (conflict-free)
__global__ void __launch_bounds__(256, 1) attn_tc_kernel() {
    extern __shared__ float sm[];
    float* Ks = sm;                     // K2 tile [key][e]    64 x AS
    float* Vt = Ks + 64 * AS;           // V2 tile [e][key]    64 x AS (transposed)
    float* Ps = Vt + 64 * AS;           // P [q][key] 128 x AS; also Q staging [q][e]
    float* ckv = Ps + 128 * AS;
    float* cbv = ckv + 64;

    int tid = threadIdx.x;
    int q0 = blockIdx.x * 128;
    int h = blockIdx.y;
    int b = blockIdx.z;
    int warp = tid >> 5;
    int lane = tid & 31;
    int gr = lane >> 2;
    int gc = lane & 3;
    int wrow = warp * 16;

    // stage Q tile (tf32-rounded) into Ps
#pragma unroll
    for (int l = 0; l < 8; l++) {
        int lin = tid + l * 256;
        int r = lin >> 4;
        int e4 = (lin & 15) << 2;
        float4 v = *(const float4*)&g_qs[(size_t)((b << 10) + q0 + r) * DD + (h << 6) + e4];
        v.x = tf32r(v.x); v.y = tf32r(v.y); v.z = tf32r(v.z); v.w = tf32r(v.w);
        *(float4*)&Ps[r * AS + e4] = v;
    }
    __syncthreads();
    // preload Q A-fragments (8 k-chunks x 4 regs)
    uint32_t qf[8][4];
#pragma unroll
    for (int c = 0; c < 8; c++) {
        qf[c][0] = __float_as_uint(Ps[(wrow + gr) * AS + c * 8 + gc]);
        qf[c][1] = __float_as_uint(Ps[(wrow + gr + 8) * AS + c * 8 + gc]);
        qf[c][2] = __float_as_uint(Ps[(wrow + gr) * AS + c * 8 + gc + 4]);
        qf[c][3] = __float_as_uint(Ps[(wrow + gr + 8) * AS + c * 8 + gc + 4]);
    }

    int qrow0 = q0 + wrow + gr;        // global q row for regs 0,1
    int qrow1 = qrow0 + 8;             // regs 2,3
    float mq0 = g_m[(size_t)((b * HH + h) << 10) + qrow0];
    float mq1 = g_m[(size_t)((b * HH + h) << 10) + qrow1];
    float rm0 = -INFINITY, rm1 = -INFINITY, rs0 = 0.f, rs1 = 0.f;
    float ofr[8][4];
#pragma unroll
    for (int nf = 0; nf < 8; nf++)
#pragma unroll
        for (int r = 0; r < 4; r++) ofr[nf][r] = 0.f;

    unsigned pmbase0 = ((unsigned)((b << 10) + qrow0)) << 5;
    unsigned pmbase1 = ((unsigned)((b << 10) + qrow1)) << 5;

    for (int kt = 0; kt < 16; kt++) {
        int k0 = kt * 64;
        __syncthreads();   // previous tile's reads of Ks/Vt done
        // load K tile [key][e], coalesced
#pragma unroll
        for (int l = 0; l < 4; l++) {
            int lin = tid + l * 256;
            int r = lin >> 4;
            int e4 = (lin & 15) << 2;
            float4 v = *(const float4*)&g_k2[(size_t)((b << 10) + k0 + r) * DD + (h << 6) + e4];
            v.x = tf32r(v.x); v.y = tf32r(v.y); v.z = tf32r(v.z); v.w = tf32r(v.w);
            *(float4*)&Ks[r * AS + e4] = v;
        }
        // load V tile transposed [e][key]; per-lane k => conflict-free STS
#pragma unroll
        for (int l = 0; l < 4; l++) {
            int lin = tid + l * 256;
            int k = lin & 63;
            int e4 = (lin >> 6) << 2;
            float4 v = *(const float4*)&g_v2[(size_t)((b << 10) + k0 + k) * DD + (h << 6) + e4];
            Vt[(e4 + 0) * AS + k] = tf32r(v.x);
            Vt[(e4 + 1) * AS + k] = tf32r(v.y);
            Vt[(e4 + 2) * AS + k] = tf32r(v.z);
            Vt[(e4 + 3) * AS + k] = tf32r(v.w);
        }
        if (tid < 64) {
            ckv[tid] = g_ck[(size_t)((b << 10) + k0 + tid) * HH + h];
            cbv[tid] = g_cb[(size_t)((b << 10) + k0 + tid) * HH + h];
        }
        __syncthreads();

        // ---- scores S = Q @ K^T (16x64 per warp) ----
        float sfr[8][4];
#pragma unroll
        for (int nf = 0; nf < 8; nf++)
#pragma unroll
            for (int r = 0; r < 4; r++) sfr[nf][r] = 0.f;
#pragma unroll
        for (int c = 0; c < 8; c++) {
#pragma unroll
            for (int nf = 0; nf < 8; nf++) {
                uint32_t bf[2];
                bf[0] = __float_as_uint(Ks[(nf * 8 + gr) * AS + c * 8 + gc]);
                bf[1] = __float_as_uint(Ks[(nf * 8 + gr) * AS + c * 8 + gc + 4]);
                MMA_TF32(sfr[nf], qf[c], bf);
            }
        }

        // ---- gate + mask ----
        unsigned w00 = g_pm[pmbase0 + (k0 >> 5)];
        unsigned w01 = g_pm[pmbase0 + (k0 >> 5) + 1];
        unsigned w10 = g_pm[pmbase1 + (k0 >> 5)];
        unsigned w11 = g_pm[pmbase1 + (k0 >> 5) + 1];
#pragma unroll
        for (int nf = 0; nf < 8; nf++) {
            int c0 = nf * 8 + (gc << 1);
            int c1 = c0 + 1;
            float lk0 = ckv[c0], lk1 = ckv[c1];
            float lb0 = cbv[c0], lb1 = cbv[c1];
            float g00 = __fdividef(1.f, 1.f + __expf(-fmaf(mq0, lk0, lb0)));
            float g01 = __fdividef(1.f, 1.f + __expf(-fmaf(mq0, lk1, lb1)));
            float g10 = __fdividef(1.f, 1.f + __expf(-fmaf(mq1, lk0, lb0)));
            float g11 = __fdividef(1.f, 1.f + __expf(-fmaf(mq1, lk1, lb1)));
            float v0 = sfr[nf][0] * 0.125f * g00;
            float v1 = sfr[nf][1] * 0.125f * g01;
            float v2 = sfr[nf][2] * 0.125f * g10;
            float v3 = sfr[nf][3] * 0.125f * g11;
            unsigned wa0 = (c0 < 32) ? w00 : w01;
            unsigned wa1 = (c1 < 32) ? w00 : w01;
            unsigned wb0 = (c0 < 32) ? w10 : w11;
            unsigned wb1 = (c1 < 32) ? w10 : w11;
            if (!((wa0 >> (c0 & 31)) & 1u)) v0 = -1e9f;
            if (!((wa1 >> (c1 & 31)) & 1u)) v1 = -1e9f;
            if (!((wb0 >> (c0 & 31)) & 1u)) v2 = -1e9f;
            if (!((wb1 >> (c1 & 31)) & 1u)) v3 = -1e9f;
            sfr[nf][0] = v0; sfr[nf][1] = v1; sfr[nf][2] = v2; sfr[nf][3] = v3;
        }

        // ---- online softmax (rows gr and gr+8, 4 lanes per row) ----
        float m0 = -INFINITY, m1 = -INFINITY;
#pragma unroll
        for (int nf = 0; nf < 8; nf++) {
            m0 = fmaxf(m0, fmaxf(sfr[nf][0], sfr[nf][1]));
            m1 = fmaxf(m1, fmaxf(sfr[nf][2], sfr[nf][3]));
        }
#pragma unroll
        for (int d = 1; d < 4; d <<= 1) {
            m0 = fmaxf(m0, __shfl_xor_sync(0xffffffffu, m0, d));
            m1 = fmaxf(m1, __shfl_xor_sync(0xffffffffu, m1, d));
        }
        float tm0 = fmaxf(rm0, m0);
        float tm1 = fmaxf(rm1, m1);
        float sc0 = __expf(rm0 - tm0);
        float sc1 = __expf(rm1 - tm1);
        rm0 = tm0; rm1 = tm1;
        float sum0 = 0.f, sum1 = 0.f;
#pragma unroll
        for (int nf = 0; nf < 8; nf++) {
            float p0 = __expf(sfr[nf][0] - tm0);
            float p1 = __expf(sfr[nf][1] - tm0);
            float p2 = __expf(sfr[nf][2] - tm1);
            float p3 = __expf(sfr[nf][3] - tm1);
            sum0 += p0 + p1;
            sum1 += p2 + p3;
            sfr[nf][0] = p0; sfr[nf][1] = p1; sfr[nf][2] = p2; sfr[nf][3] = p3;
        }
#pragma unroll
        for (int d = 1; d < 4; d <<= 1) {
            sum0 += __shfl_xor_sync(0xffffffffu, sum0, d);
            sum1 += __shfl_xor_sync(0xffffffffu, sum1, d);
        }
        rs0 = rs0 * sc0 + sum0;
        rs1 = rs1 * sc1 + sum1;
#pragma unroll
        for (int nf = 0; nf < 8; nf++) {
            ofr[nf][0] *= sc0; ofr[nf][1] *= sc0;
            ofr[nf][2] *= sc1; ofr[nf][3] *= sc1;
        }

        // ---- store P (warp-private rows) ----
#pragma unroll
        for (int nf = 0; nf < 8; nf++) {
            int c0 = nf * 8 + (gc << 1);
            *(float2*)&Ps[(wrow + gr) * AS + c0] =
                make_float2(tf32r(sfr[nf][0]), tf32r(sfr[nf][1]));
            *(float2*)&Ps[(wrow + gr + 8) * AS + c0] =
                make_float2(tf32r(sfr[nf][2]), tf32r(sfr[nf][3]));
        }
        __syncwarp();

        // ---- O += P @ V ----
#pragma unroll
        for (int c = 0; c < 8; c++) {
            uint32_t af[4];
            af[0] = __float_as_uint(Ps[(wrow + gr) * AS + c * 8 + gc]);
            af[1] = __float_as_uint(Ps[(wrow + gr + 8) * AS + c * 8 + gc]);
            af[2] = __float_as_uint(Ps[(wrow + gr) * AS + c * 8 + gc + 4]);
            af[3] = __float_as_uint(Ps[(wrow + gr + 8) * AS + c * 8 + gc + 4]);
#pragma unroll
            for (int nf = 0; nf < 8; nf++) {
                uint32_t bf[2];
                bf[0] = __float_as_uint(Vt[(nf * 8 + gr) * AS + c * 8 + gc]);
                bf[1] = __float_as_uint(Vt[(nf * 8 + gr) * AS + c * 8 + gc + 4]);
                MMA_TF32(ofr[nf], af, bf);
            }
        }
    }

    // ---- normalize + write (tf32-rounded for the out-proj GEMM) ----
    float inv0 = 1.f / rs0;
    float inv1 = 1.f / rs1;
#pragma unroll
    for (int nf = 0; nf < 8; nf++) {
        int c0 = (h << 6) + nf * 8 + (gc << 1);
        *(float2*)&g_x[(size_t)((b << 10) + qrow0) * DD + c0] =
            make_float2(tf32r(ofr[nf][0] * inv0), tf32r(ofr[nf][1] * inv0));
        *(float2*)&g_x[(size_t)((b << 10) + qrow1) * DD + c0] =
            make_float2(tf32r(ofr[nf][2] * inv1), tf32r(ofr[nf][3] * inv1));
    }
}

// ---------------- launch ------------------------------------------------------
extern "C" void kernel_launch(void* const* d_in, const int* in_sizes, int n_in,
                              void* d_out, int out_size) {
    const float* query = (const float*)d_in[0];
    const float* key   = (const float*)d_in[1];
    const float* value = (const float*)d_in[2];
    const int*   mask  = (const int*)d_in[3];
    const float* wq = (const float*)d_in[4];
    const float* bq = (const float*)d_in[5];
    const float* wk = (const float*)d_in[6];
    const float* bk = (const float*)d_in[7];
    const float* wv = (const float*)d_in[8];
    const float* bv = (const float*)d_in[9];
    const float* wo = (const float*)d_in[10];
    const float* bo = (const float*)d_in[11];
    const float* spatial_w = (const float*)d_in[12];
    const float* spatial_b = (const float*)d_in[13];
    const float* qproj_w = (const float*)d_in[14];
    const float* qproj_b = (const float*)d_in[15];
    const float* kproj_w = (const float*)d_in[16];
    const float* kproj_b = (const float*)d_in[17];
    const float* vlin_w = (const float*)d_in[18];
    const float* vlin_b = (const float*)d_in[19];
    const float* chan_w = (const float*)d_in[20];
    const float* chan_b = (const float*)d_in[21];
    float* out = (float*)d_out;

    float *p_wqf, *p_wkf, *p_wvf, *p_wof, *p_bqf, *p_bkf, *p_bvf;
    float *p_qs, *p_k2, *p_v2, *p_x, *p_acvt;
    cudaGetSymbolAddress((void**)&p_wqf, g_wqf);
    cudaGetSymbolAddress((void**)&p_wkf, g_wkf);
    cudaGetSymbolAddress((void**)&p_wvf, g_wvf);
    cudaGetSymbolAddress((void**)&p_wof, g_wof);
    cudaGetSymbolAddress((void**)&p_bqf, g_bqf);
    cudaGetSymbolAddress((void**)&p_bkf, g_bkf);
    cudaGetSymbolAddress((void**)&p_bvf, g_bvf);
    cudaGetSymbolAddress((void**)&p_qs, g_qs);
    cudaGetSymbolAddress((void**)&p_k2, g_k2);
    cudaGetSymbolAddress((void**)&p_v2, g_v2);
    cudaGetSymbolAddress((void**)&p_x, g_x);
    cudaGetSymbolAddress((void**)&p_acvt, g_acvt);

    int gsmem = GSTAGES * (ASZ + BSZ) * (int)sizeof(float);
    cudaFuncSetAttribute(gemm_tf32<1>, cudaFuncAttributeMaxDynamicSharedMemorySize, gsmem);
    cudaFuncSetAttribute(gemm_tf32<0>, cudaFuncAttributeMaxDynamicSharedMemorySize, gsmem);
    int asmem = (256 * AS + 128) * (int)sizeof(float);   // ~70.1 KB
    cudaFuncSetAttribute(attn_tc_kernel, cudaFuncAttributeMaxDynamicSharedMemorySize, asmem);

    // 1. fold small projections into big weights (tf32-rounded)
    fold_w_kernel<<<dim3(DD * DD / 256, 3), 256>>>(wq, wk, wv, spatial_w, kproj_w, vlin_w);
    // 2. biases / chan fold / qv
    small_prep_kernel<<<141, 256>>>(bq, bk, bv, spatial_w, kproj_w, vlin_w,
                                    spatial_b, kproj_b, vlin_b,
                                    wk, chan_w, chan_b, qproj_w, qproj_b);
    // 3. round wo; pack mask
    tf32_cvt_kernel<<<DD * DD / 1024, 256>>>(wo, p_wof);
    mask_pack_kernel<<<BB * SS * SS / 256, 256>>>(mask);

    dim3 ggrid(DD / 128, MM / 128);
    // 4-6. activations: round then tensor-core GEMM with fused ELU
    tf32_cvt_kernel<<<MM * DD / 1024, 256>>>(query, p_acvt);
    gemm_tf32<1><<<ggrid, 256, gsmem>>>(p_acvt, p_wqf, p_bqf, p_qs, MM, DD, DD);
    tf32_cvt_kernel<<<MM * DD / 1024, 256>>>(key, p_acvt);
    gemm_tf32<1><<<ggrid, 256, gsmem>>>(p_acvt, p_wkf, p_bkf, p_k2, MM, DD, DD);
    tf32_cvt_kernel<<<MM * DD / 1024, 256>>>(value, p_acvt);
    gemm_tf32<1><<<ggrid, 256, gsmem>>>(p_acvt, p_wvf, p_bvf, p_v2, MM, DD, DD);
    // 7. ck/cb gate scalars (reads raw key)
    ckcb_kernel<<<MM / 8, 256>>>(key);
    // 8. m scalar per (b,h,q)
    m_kernel<<<(BB * HH * SS) / 256, 256>>>();
    // 9. tensor-core attention (writes tf32-rounded g_x)
    attn_tc_kernel<<<dim3(SS / 128, HH, BB), 256, asmem>>>();
    // 10. output projection
    gemm_tf32<0><<<ggrid, 256, gsmem>>>(p_x, p_wof, bo, out, MM, DD, DD);
}

// round 6
// speedup vs baseline: 2.6445x; 1.0544x over previous
#include <cuda_runtime.h>
#include <math.h>
#include <stdint.h>

#define BB 4
#define SS 1024
#define DD 1024
#define HH 16
#define DK 64
#define MM (BB * SS)   // 4096

// ---------------- scratch (device globals; no allocation allowed) -------------
__device__ float g_wqf[DD * DD];
__device__ float g_wkf[DD * DD];
__device__ float g_wvf[DD * DD];
__device__ float g_wof[DD * DD];
__device__ float g_bqf[DD];
__device__ float g_bkf[DD];
__device__ float g_bvf[DD];
__device__ float g_wck[DD * HH];
__device__ float g_wcb[DD * HH];
__device__ float g_bck[HH];
__device__ float g_bcb[HH];
__device__ float g_qv[DK];
__device__ float g_bmean;
__device__ float g_qs[MM * DD];
__device__ float g_k2[MM * DD];
__device__ float g_v2[MM * DD];
__device__ float g_x[MM * DD];
__device__ float g_acvt[MM * DD];   // tf32-rounded activation staging
__device__ float g_ck[MM * HH];
__device__ float g_cb[MM * HH];
__device__ unsigned g_pm[BB * SS * SS / 32];   // packed mask bits

__device__ __forceinline__ float tf32r(float x) {
    float y;
    asm("cvt.rna.tf32.f32 %0, %1;" : "=f"(y) : "f"(x));
    return y;
}

#define MMA_TF32(d, a, b) \
    asm volatile("mma.sync.aligned.m16n8k8.row.col.f32.tf32.tf32.f32 " \
                 "{%0,%1,%2,%3},{%4,%5,%6,%7},{%8,%9},{%0,%1,%2,%3};" \
                 : "+f"(d[0]), "+f"(d[1]), "+f"(d[2]), "+f"(d[3]) \
                 : "r"(a[0]), "r"(a[1]), "r"(a[2]), "r"(a[3]), "r"(b[0]), "r"(b[1]));

// ---------------- 0. elementwise tf32 rounding pass ---------------------------
__global__ void tf32_cvt_kernel(const float* __restrict__ in, float* __restrict__ out) {
    int i = (blockIdx.x * 256 + threadIdx.x);
    float4 v = *(const float4*)(in + (size_t)i * 4);
    v.x = tf32r(v.x); v.y = tf32r(v.y); v.z = tf32r(v.z); v.w = tf32r(v.w);
    *(float4*)(out + (size_t)i * 4) = v;
}

// ---------------- 0b. pack mask into bits (8 ints -> 1 byte per thread) -------
__global__ void mask_pack_kernel(const int* __restrict__ mask) {
    int t = blockIdx.x * 256 + threadIdx.x;     // byte index
    const int4* p = (const int4*)mask + (size_t)t * 2;
    int4 a = p[0], b = p[1];
    unsigned byte = (unsigned)(a.x != 0) | ((unsigned)(a.y != 0) << 1)
                  | ((unsigned)(a.z != 0) << 2) | ((unsigned)(a.w != 0) << 3)
                  | ((unsigned)(b.x != 0) << 4) | ((unsigned)(b.y != 0) << 5)
                  | ((unsigned)(b.z != 0) << 6) | ((unsigned)(b.w != 0) << 7);
    ((unsigned char*)g_pm)[t] = (unsigned char)byte;
}

// ---------------- 1. fold per-head 64x64 projections into the big weights ----
__global__ void fold_w_kernel(const float* __restrict__ wq,
                              const float* __restrict__ wk,
                              const float* __restrict__ wv,
                              const float* __restrict__ sw,
                              const float* __restrict__ kp,
                              const float* __restrict__ vl) {
    int f = blockIdx.y;
    int idx = blockIdx.x * 256 + threadIdx.x;
    const float* W = (f == 0) ? wq : (f == 1) ? wk : wv;
    const float* P = (f == 0) ? sw : (f == 1) ? kp : vl;
    float* O = (f == 0) ? g_wqf : (f == 1) ? g_wkf : g_wvf;
    int d = idx >> 10;
    int c = idx & 1023;
    int h = c >> 6;
    int ep = c & 63;
    const float* wrow = W + d * DD + (h << 6);
    float sum = 0.f;
#pragma unroll 8
    for (int e = 0; e < DK; e++) sum += wrow[e] * P[e * DK + ep];
    O[idx] = tf32r(sum);
}

// ---------------- 2. small precompute -----------------------------------------
__global__ void small_prep_kernel(const float* __restrict__ bq,
                                  const float* __restrict__ bk,
                                  const float* __restrict__ bv,
                                  const float* __restrict__ sw,
                                  const float* __restrict__ kp,
                                  const float* __restrict__ vl,
                                  const float* __restrict__ sb,
                                  const float* __restrict__ kpb,
                                  const float* __restrict__ vlb,
                                  const float* __restrict__ wk,
                                  const float* __restrict__ chan_w,
                                  const float* __restrict__ chan_b,
                                  const float* __restrict__ qproj_w,
                                  const float* __restrict__ qproj_b) {
    int T = blockIdx.x * 256 + threadIdx.x;
    if (T < 3072) {
        int f = T >> 10;
        int c = T & 1023;
        int h = c >> 6;
        int ep = c & 63;
        const float* b = (f == 0) ? bq : (f == 1) ? bk : bv;
        const float* P = (f == 0) ? sw : (f == 1) ? kp : vl;
        const float* pb = (f == 0) ? sb : (f == 1) ? kpb : vlb;
        float* O = (f == 0) ? g_bqf : (f == 1) ? g_bkf : g_bvf;
        float sum = pb[ep];
        for (int e = 0; e < DK; e++) sum += b[(h << 6) + e] * P[e * DK + ep];
        O[c] = sum;
        return;
    }
    T -= 3072;
    if (T < 16384) {
        int d = T >> 4, h = T & 15;
        float sum = 0.f;
        for (int e = 0; e < DK; e++) sum += wk[d * DD + (h << 6) + e] * chan_w[e];
        g_wck[d * HH + h] = sum;
        return;
    }
    T -= 16384;
    if (T < 16384) {
        int d = T >> 4, h = T & 15;
        float sum = 0.f;
        for (int e = 0; e < DK; e++) sum += wk[d * DD + (h << 6) + e] * chan_b[e];
        g_wcb[d * HH + h] = sum;
        return;
    }
    T -= 16384;
    if (T < 16) {
        float sum = 0.f;
        for (int e = 0; e < DK; e++) sum += bk[(T << 6) + e] * chan_w[e];
        g_bck[T] = sum;
        return;
    }
    T -= 16;
    if (T < 16) {
        float sum = 0.f;
        for (int e = 0; e < DK; e++) sum += bk[(T << 6) + e] * chan_b[e];
        g_bcb[T] = sum;
        return;
    }
    T -= 16;
    if (T < 64) {
        float sum = 0.f;
        for (int ep = 0; ep < DK; ep++) sum += qproj_w[T * DK + ep];
        g_qv[T] = sum * (1.f / 64.f);
        return;
    }
    T -= 64;
    if (T == 0) {
        float sum = 0.f;
        for (int ep = 0; ep < DK; ep++) sum += qproj_b[ep];
        g_bmean = sum * (1.f / 64.f);
    }
}

// ---------------- 3. tf32 tensor-core GEMM: C = act(A @ W + bias) -------------
#define GSTAGES 4
#define GBK 16
#define AST 20
#define BST 136
#define ASZ (128 * AST)
#define BSZ (GBK * BST)

__device__ __forceinline__ void cpa16(float* dst, const float* src) {
    unsigned d = (unsigned)__cvta_generic_to_shared(dst);
    asm volatile("cp.async.cg.shared.global [%0], [%1], 16;\n" :: "r"(d), "l"(src));
}

__device__ __forceinline__ void gemm_load_stage(float* As, float* Bs,
                                                const float* A, const float* Bm,
                                                int brow, int bcol, int kt, int tid,
                                                int Kk, int Nn) {
#pragma unroll
    for (int l = 0; l < 2; l++) {
        int lin = tid + l * 256;
        int row = lin >> 2, c4 = (lin & 3) << 2;
        cpa16(&As[row * AST + c4], &A[(size_t)(brow + row) * Kk + kt * GBK + c4]);
    }
#pragma unroll
    for (int l = 0; l < 2; l++) {
        int lin = tid + l * 256;
        int kr = lin >> 5, c4 = (lin & 31) << 2;
        cpa16(&Bs[kr * BST + c4], &Bm[(size_t)(kt * GBK + kr) * Nn + bcol + c4]);
    }
}

template <int ACT>   // 0 = none, 1 = elu
__global__ void __launch_bounds__(256, 2)
gemm_tf32(const float* __restrict__ A,
          const float* __restrict__ Bm,
          const float* __restrict__ bias,
          float* __restrict__ C,
          int Mm, int Nn, int Kk) {
    extern __shared__ float smem[];
    float* Asm = smem;
    float* Bsm = smem + GSTAGES * ASZ;

    int tid = threadIdx.x;
    int brow = blockIdx.y * 128;
    int bcol = blockIdx.x * 128;
    int warp = tid >> 5;
    int lane = tid & 31;
    int gr = lane >> 2;
    int gc = lane & 3;
    int wrow = (warp >> 2) * 64;
    int wcol = (warp & 3) * 32;

    float acc[4][4][4];
#pragma unroll
    for (int mt = 0; mt < 4; mt++)
#pragma unroll
        for (int nt = 0; nt < 4; nt++)
#pragma unroll
            for (int r = 0; r < 4; r++) acc[mt][nt][r] = 0.f;

    const int KT = Kk / GBK;
#pragma unroll
    for (int s = 0; s < GSTAGES - 1; s++) {
        gemm_load_stage(Asm + s * ASZ, Bsm + s * BSZ, A, Bm, brow, bcol, s, tid, Kk, Nn);
        asm volatile("cp.async.commit_group;\n");
    }

    for (int kt = 0; kt < KT; kt++) {
        asm volatile("cp.async.wait_group %0;\n" :: "n"(GSTAGES - 2));
        __syncthreads();
        int s = kt & (GSTAGES - 1);
        float* As = Asm + s * ASZ;
        float* Bs = Bsm + s * BSZ;
#pragma unroll
        for (int kb = 0; kb < GBK; kb += 8) {
            uint32_t af[4][4], bf[4][2];
#pragma unroll
            for (int mt = 0; mt < 4; mt++) {
                int row0 = wrow + mt * 16 + gr;
                af[mt][0] = __float_as_uint(As[row0 * AST + kb + gc]);
                af[mt][1] = __float_as_uint(As[(row0 + 8) * AST + kb + gc]);
                af[mt][2] = __float_as_uint(As[row0 * AST + kb + gc + 4]);
                af[mt][3] = __float_as_uint(As[(row0 + 8) * AST + kb + gc + 4]);
            }
#pragma unroll
            for (int nt = 0; nt < 4; nt++) {
                int col0 = wcol + nt * 8 + gr;
                bf[nt][0] = __float_as_uint(Bs[(kb + gc) * BST + col0]);
                bf[nt][1] = __float_as_uint(Bs[(kb + gc + 4) * BST + col0]);
            }
#pragma unroll
            for (int mt = 0; mt < 4; mt++)
#pragma unroll
                for (int nt = 0; nt < 4; nt++)
                    MMA_TF32(acc[mt][nt], af[mt], bf[nt]);
        }
        int nk = kt + GSTAGES - 1;
        if (nk < KT)
            gemm_load_stage(Asm + (nk & (GSTAGES - 1)) * ASZ,
                            Bsm + (nk & (GSTAGES - 1)) * BSZ,
                            A, Bm, brow, bcol, nk, tid, Kk, Nn);
        asm volatile("cp.async.commit_group;\n");
    }

#pragma unroll
    for (int mt = 0; mt < 4; mt++) {
        int r0 = brow + wrow + mt * 16 + gr;
#pragma unroll
        for (int nt = 0; nt < 4; nt++) {
            int c0 = bcol + wcol + nt * 8 + (gc << 1);
            float b0 = bias[c0], b1 = bias[c0 + 1];
            float v0 = acc[mt][nt][0] + b0;
            float v1 = acc[mt][nt][1] + b1;
            float v2 = acc[mt][nt][2] + b0;
            float v3 = acc[mt][nt][3] + b1;
            if (ACT == 1) {
                v0 = v0 > 0.f ? v0 : (__expf(v0) - 1.f);
                v1 = v1 > 0.f ? v1 : (__expf(v1) - 1.f);
                v2 = v2 > 0.f ? v2 : (__expf(v2) - 1.f);
                v3 = v3 > 0.f ? v3 : (__expf(v3) - 1.f);
            }
            *(float2*)&C[(size_t)r0 * Nn + c0] = make_float2(v0, v1);
            *(float2*)&C[(size_t)(r0 + 8) * Nn + c0] = make_float2(v2, v3);
        }
    }
}

// ---------------- 4. ck/cb skinny GEMV ----------------------------------------
__global__ void ckcb_kernel(const float* __restrict__ key) {
    __shared__ float rows[8][1024];
    int tid = threadIdx.x;
    int row0 = blockIdx.x * 8;
#pragma unroll
    for (int l = 0; l < 8; l++) {
        int lin = tid + l * 256;
        int r = lin >> 8;
        int c4 = (lin & 255) << 2;
        *(float4*)&rows[r][c4] = *(const float4*)&key[(size_t)(row0 + r) * DD + c4];
    }
    __syncthreads();
    int r = tid >> 5;
    int o = tid & 31;
    int h = o & 15;
    int isB = o >> 4;
    const float* wp = isB ? g_wcb : g_wck;
    float sum = isB ? g_bcb[h] : g_bck[h];
#pragma unroll 8
    for (int d = 0; d < DD; d++) sum += rows[r][d] * wp[d * HH + h];
    (isB ? g_cb : g_ck)[(size_t)(row0 + r) * HH + h] = sum;
}

// ---------------- 5. tensor-core flash attention, double-buffered -------------
// CTA: 128 q-rows x (b,h). 8 warps x 16 q-rows. K-tiles of 64, 2-deep pipeline.
#define AS 68
#define KVSZ (64 * AS)
__global__ void __launch_bounds__(256, 1) attn_tc_kernel() {
    extern __shared__ float sm[];
    float* KsB = sm;                    // 2 x [key][e]
    float* VtB = sm + 2 * KVSZ;         // 2 x [e][key]
    float* Ps  = sm + 4 * KVSZ;         // Q staging, then P [q][key]
    float* ckB = Ps + 128 * AS;         // 2 x 64
    float* cbB = ckB + 128;             // 2 x 64

    int tid = threadIdx.x;
    int q0 = blockIdx.x * 128;
    int h = blockIdx.y;
    int b = blockIdx.z;
    int warp = tid >> 5;
    int lane = tid & 31;
    int gr = lane >> 2;
    int gc = lane & 3;
    int wrow = warp * 16;

    // thread's loader coords
    int kr = tid >> 4;                  // K tile: rows kr, kr+... (lin>>4)
    int ke4 = (tid & 15) << 2;
    int vk = tid & 63;                  // V tile: per-lane key
    int ve4 = (tid >> 6) << 2;

    // stage Q tile (tf32-rounded) into Ps
#pragma unroll
    for (int l = 0; l < 8; l++) {
        int lin = tid + l * 256;
        int r = lin >> 4;
        int e4 = (lin & 15) << 2;
        float4 v = *(const float4*)&g_qs[(size_t)((b << 10) + q0 + r) * DD + (h << 6) + e4];
        v.x = tf32r(v.x); v.y = tf32r(v.y); v.z = tf32r(v.z); v.w = tf32r(v.w);
        *(float4*)&Ps[r * AS + e4] = v;
    }
    // prefetch tile 0 into registers (overlaps with Q-stage sync)
    float4 kreg[4], vreg[4];
    float creg0 = 0.f, creg1 = 0.f;
#pragma unroll
    for (int l = 0; l < 4; l++) {
        int r = kr + l * 16;
        kreg[l] = *(const float4*)&g_k2[(size_t)((b << 10) + r) * DD + (h << 6) + ke4];
        int e4 = ve4 + l * 16;
        vreg[l] = *(const float4*)&g_v2[(size_t)((b << 10) + vk) * DD + (h << 6) + e4];
    }
    if (tid < 64) {
        creg0 = g_ck[(size_t)((b << 10) + tid) * HH + h];
        creg1 = g_cb[(size_t)((b << 10) + tid) * HH + h];
    }
    __syncthreads();   // Q visible

    // preload Q A-fragments
    uint32_t qf[8][4];
#pragma unroll
    for (int c = 0; c < 8; c++) {
        qf[c][0] = __float_as_uint(Ps[(wrow + gr) * AS + c * 8 + gc]);
        qf[c][1] = __float_as_uint(Ps[(wrow + gr + 8) * AS + c * 8 + gc]);
        qf[c][2] = __float_as_uint(Ps[(wrow + gr) * AS + c * 8 + gc + 4]);
        qf[c][3] = __float_as_uint(Ps[(wrow + gr + 8) * AS + c * 8 + gc + 4]);
    }
    // compute per-row gate scalar m inline: m = Q_row . qv + bmean
    float a0 = 0.f, a1 = 0.f;
#pragma unroll
    for (int e16 = 0; e16 < 16; e16++) {
        int e = gc * 16 + e16;
        float qv = __ldg(&g_qv[e]);
        a0 = fmaf(Ps[(wrow + gr) * AS + e], qv, a0);
        a1 = fmaf(Ps[(wrow + gr + 8) * AS + e], qv, a1);
    }
#pragma unroll
    for (int d = 1; d < 4; d <<= 1) {
        a0 += __shfl_xor_sync(0xffffffffu, a0, d);
        a1 += __shfl_xor_sync(0xffffffffu, a1, d);
    }
    float bmean = g_bmean;
    float mq0 = a0 + bmean;
    float mq1 = a1 + bmean;

    // store tile 0 into buffer 0 (tf32-rounded)
    {
        float* Ks = KsB;
        float* Vt = VtB;
#pragma unroll
        for (int l = 0; l < 4; l++) {
            int r = kr + l * 16;
            float4 v = kreg[l];
            v.x = tf32r(v.x); v.y = tf32r(v.y); v.z = tf32r(v.z); v.w = tf32r(v.w);
            *(float4*)&Ks[r * AS + ke4] = v;
            int e4 = ve4 + l * 16;
            float4 w = vreg[l];
            Vt[(e4 + 0) * AS + vk] = tf32r(w.x);
            Vt[(e4 + 1) * AS + vk] = tf32r(w.y);
            Vt[(e4 + 2) * AS + vk] = tf32r(w.z);
            Vt[(e4 + 3) * AS + vk] = tf32r(w.w);
        }
        if (tid < 64) { ckB[tid] = creg0; cbB[tid] = creg1; }
    }

    int qrow0 = q0 + wrow + gr;
    int qrow1 = qrow0 + 8;
    float rm0 = -INFINITY, rm1 = -INFINITY, rs0 = 0.f, rs1 = 0.f;
    float ofr[8][4];
#pragma unroll
    for (int nf = 0; nf < 8; nf++)
#pragma unroll
        for (int r = 0; r < 4; r++) ofr[nf][r] = 0.f;

    unsigned pmbase0 = ((unsigned)((b << 10) + qrow0)) << 5;
    unsigned pmbase1 = ((unsigned)((b << 10) + qrow1)) << 5;

    for (int kt = 0; kt < 16; kt++) {
        __syncthreads();   // buf[cur] writes visible; buf[nxt] readers done
        int cur = kt & 1;
        float* Ks = KsB + cur * KVSZ;
        float* Vt = VtB + cur * KVSZ;
        float* ckv = ckB + cur * 64;
        float* cbv = cbB + cur * 64;
        int k0 = kt * 64;

        // prefetch next tile into registers (latency hidden under MMAs)
        if (kt < 15) {
            int kn = k0 + 64;
#pragma unroll
            for (int l = 0; l < 4; l++) {
                int r = kn + kr + l * 16;
                kreg[l] = *(const float4*)&g_k2[(size_t)((b << 10) + r) * DD + (h << 6) + ke4];
                int e4 = ve4 + l * 16;
                vreg[l] = *(const float4*)&g_v2[(size_t)((b << 10) + kn + vk) * DD + (h << 6) + e4];
            }
            if (tid < 64) {
                creg0 = g_ck[(size_t)((b << 10) + kn + tid) * HH + h];
                creg1 = g_cb[(size_t)((b << 10) + kn + tid) * HH + h];
            }
        }

        // ---- scores S = Q @ K^T ----
        float sfr[8][4];
#pragma unroll
        for (int nf = 0; nf < 8; nf++)
#pragma unroll
            for (int r = 0; r < 4; r++) sfr[nf][r] = 0.f;
#pragma unroll
        for (int c = 0; c < 8; c++) {
#pragma unroll
            for (int nf = 0; nf < 8; nf++) {
                uint32_t bf[2];
                bf[0] = __float_as_uint(Ks[(nf * 8 + gr) * AS + c * 8 + gc]);
                bf[1] = __float_as_uint(Ks[(nf * 8 + gr) * AS + c * 8 + gc + 4]);
                MMA_TF32(sfr[nf], qf[c], bf);
            }
        }

        // ---- gate + mask ----
        unsigned w00 = g_pm[pmbase0 + (k0 >> 5)];
        unsigned w01 = g_pm[pmbase0 + (k0 >> 5) + 1];
        unsigned w10 = g_pm[pmbase1 + (k0 >> 5)];
        unsigned w11 = g_pm[pmbase1 + (k0 >> 5) + 1];
#pragma unroll
        for (int nf = 0; nf < 8; nf++) {
            int c0 = nf * 8 + (gc << 1);
            int c1 = c0 + 1;
            float lk0 = ckv[c0], lk1 = ckv[c1];
            float lb0 = cbv[c0], lb1 = cbv[c1];
            float g00 = __fdividef(1.f, 1.f + __expf(-fmaf(mq0, lk0, lb0)));
            float g01 = __fdividef(1.f, 1.f + __expf(-fmaf(mq0, lk1, lb1)));
            float g10 = __fdividef(1.f, 1.f + __expf(-fmaf(mq1, lk0, lb0)));
            float g11 = __fdividef(1.f, 1.f + __expf(-fmaf(mq1, lk1, lb1)));
            float v0 = sfr[nf][0] * 0.125f * g00;
            float v1 = sfr[nf][1] * 0.125f * g01;
            float v2 = sfr[nf][2] * 0.125f * g10;
            float v3 = sfr[nf][3] * 0.125f * g11;
            unsigned wa0 = (c0 < 32) ? w00 : w01;
            unsigned wa1 = (c1 < 32) ? w00 : w01;
            unsigned wb0 = (c0 < 32) ? w10 : w11;
            unsigned wb1 = (c1 < 32) ? w10 : w11;
            if (!((wa0 >> (c0 & 31)) & 1u)) v0 = -1e9f;
            if (!((wa1 >> (c1 & 31)) & 1u)) v1 = -1e9f;
            if (!((wb0 >> (c0 & 31)) & 1u)) v2 = -1e9f;
            if (!((wb1 >> (c1 & 31)) & 1u)) v3 = -1e9f;
            sfr[nf][0] = v0; sfr[nf][1] = v1; sfr[nf][2] = v2; sfr[nf][3] = v3;
        }

        // ---- online softmax ----
        float m0 = -INFINITY, m1 = -INFINITY;
#pragma unroll
        for (int nf = 0; nf < 8; nf++) {
            m0 = fmaxf(m0, fmaxf(sfr[nf][0], sfr[nf][1]));
            m1 = fmaxf(m1, fmaxf(sfr[nf][2], sfr[nf][3]));
        }
#pragma unroll
        for (int d = 1; d < 4; d <<= 1) {
            m0 = fmaxf(m0, __shfl_xor_sync(0xffffffffu, m0, d));
            m1 = fmaxf(m1, __shfl_xor_sync(0xffffffffu, m1, d));
        }
        float tm0 = fmaxf(rm0, m0);
        float tm1 = fmaxf(rm1, m1);
        float sc0 = __expf(rm0 - tm0);
        float sc1 = __expf(rm1 - tm1);
        rm0 = tm0; rm1 = tm1;
        float sum0 = 0.f, sum1 = 0.f;
#pragma unroll
        for (int nf = 0; nf < 8; nf++) {
            float p0 = __expf(sfr[nf][0] - tm0);
            float p1 = __expf(sfr[nf][1] - tm0);
            float p2 = __expf(sfr[nf][2] - tm1);
            float p3 = __expf(sfr[nf][3] - tm1);
            sum0 += p0 + p1;
            sum1 += p2 + p3;
            sfr[nf][0] = p0; sfr[nf][1] = p1; sfr[nf][2] = p2; sfr[nf][3] = p3;
        }
#pragma unroll
        for (int d = 1; d < 4; d <<= 1) {
            sum0 += __shfl_xor_sync(0xffffffffu, sum0, d);
            sum1 += __shfl_xor_sync(0xffffffffu, sum1, d);
        }
        rs0 = rs0 * sc0 + sum0;
        rs1 = rs1 * sc1 + sum1;
#pragma unroll
        for (int nf = 0; nf < 8; nf++) {
            ofr[nf][0] *= sc0; ofr[nf][1] *= sc0;
            ofr[nf][2] *= sc1; ofr[nf][3] *= sc1;
        }

        // ---- store P (warp-private rows) ----
#pragma unroll
        for (int nf = 0; nf < 8; nf++) {
            int c0 = nf * 8 + (gc << 1);
            *(float2*)&Ps[(wrow + gr) * AS + c0] =
                make_float2(tf32r(sfr[nf][0]), tf32r(sfr[nf][1]));
            *(float2*)&Ps[(wrow + gr + 8) * AS + c0] =
                make_float2(tf32r(sfr[nf][2]), tf32r(sfr[nf][3]));
        }
        __syncwarp();

        // ---- O += P @ V ----
#pragma unroll
        for (int c = 0; c < 8; c++) {
            uint32_t af[4];
            af[0] = __float_as_uint(Ps[(wrow + gr) * AS + c * 8 + gc]);
            af[1] = __float_as_uint(Ps[(wrow + gr + 8) * AS + c * 8 + gc]);
            af[2] = __float_as_uint(Ps[(wrow + gr) * AS + c * 8 + gc + 4]);
            af[3] = __float_as_uint(Ps[(wrow + gr + 8) * AS + c * 8 + gc + 4]);
#pragma unroll
            for (int nf = 0; nf < 8; nf++) {
                uint32_t bf[2];
                bf[0] = __float_as_uint(Vt[(nf * 8 + gr) * AS + c * 8 + gc]);
                bf[1] = __float_as_uint(Vt[(nf * 8 + gr) * AS + c * 8 + gc + 4]);
                MMA_TF32(ofr[nf], af, bf);
            }
        }

        // ---- drain prefetch regs into the other buffer ----
        if (kt < 15) {
            int nxt = 1 - cur;
            float* Ksn = KsB + nxt * KVSZ;
            float* Vtn = VtB + nxt * KVSZ;
#pragma unroll
            for (int l = 0; l < 4; l++) {
                int r = kr + l * 16;
                float4 v = kreg[l];
                v.x = tf32r(v.x); v.y = tf32r(v.y); v.z = tf32r(v.z); v.w = tf32r(v.w);
                *(float4*)&Ksn[r * AS + ke4] = v;
                int e4 = ve4 + l * 16;
                float4 w = vreg[l];
                Vtn[(e4 + 0) * AS + vk] = tf32r(w.x);
                Vtn[(e4 + 1) * AS + vk] = tf32r(w.y);
                Vtn[(e4 + 2) * AS + vk] = tf32r(w.z);
                Vtn[(e4 + 3) * AS + vk] = tf32r(w.w);
            }
            if (tid < 64) { ckB[nxt * 64 + tid] = creg0; cbB[nxt * 64 + tid] = creg1; }
        }
    }

    // ---- normalize + write (tf32-rounded for the out-proj GEMM) ----
    float inv0 = 1.f / rs0;
    float inv1 = 1.f / rs1;
#pragma unroll
    for (int nf = 0; nf < 8; nf++) {
        int c0 = (h << 6) + nf * 8 + (gc << 1);
        *(float2*)&g_x[(size_t)((b << 10) + qrow0) * DD + c0] =
            make_float2(tf32r(ofr[nf][0] * inv0), tf32r(ofr[nf][1] * inv0));
        *(float2*)&g_x[(size_t)((b << 10) + qrow1) * DD + c0] =
            make_float2(tf32r(ofr[nf][2] * inv1), tf32r(ofr[nf][3] * inv1));
    }
}

// ---------------- launch ------------------------------------------------------
extern "C" void kernel_launch(void* const* d_in, const int* in_sizes, int n_in,
                              void* d_out, int out_size) {
    const float* query = (const float*)d_in[0];
    const float* key   = (const float*)d_in[1];
    const float* value = (const float*)d_in[2];
    const int*   mask  = (const int*)d_in[3];
    const float* wq = (const float*)d_in[4];
    const float* bq = (const float*)d_in[5];
    const float* wk = (const float*)d_in[6];
    const float* bk = (const float*)d_in[7];
    const float* wv = (const float*)d_in[8];
    const float* bv = (const float*)d_in[9];
    const float* wo = (const float*)d_in[10];
    const float* bo = (const float*)d_in[11];
    const float* spatial_w = (const float*)d_in[12];
    const float* spatial_b = (const float*)d_in[13];
    const float* qproj_w = (const float*)d_in[14];
    const float* qproj_b = (const float*)d_in[15];
    const float* kproj_w = (const float*)d_in[16];
    const float* kproj_b = (const float*)d_in[17];
    const float* vlin_w = (const float*)d_in[18];
    const float* vlin_b = (const float*)d_in[19];
    const float* chan_w = (const float*)d_in[20];
    const float* chan_b = (const float*)d_in[21];
    float* out = (float*)d_out;

    float *p_wqf, *p_wkf, *p_wvf, *p_wof, *p_bqf, *p_bkf, *p_bvf;
    float *p_qs, *p_k2, *p_v2, *p_x, *p_acvt;
    cudaGetSymbolAddress((void**)&p_wqf, g_wqf);
    cudaGetSymbolAddress((void**)&p_wkf, g_wkf);
    cudaGetSymbolAddress((void**)&p_wvf, g_wvf);
    cudaGetSymbolAddress((void**)&p_wof, g_wof);
    cudaGetSymbolAddress((void**)&p_bqf, g_bqf);
    cudaGetSymbolAddress((void**)&p_bkf, g_bkf);
    cudaGetSymbolAddress((void**)&p_bvf, g_bvf);
    cudaGetSymbolAddress((void**)&p_qs, g_qs);
    cudaGetSymbolAddress((void**)&p_k2, g_k2);
    cudaGetSymbolAddress((void**)&p_v2, g_v2);
    cudaGetSymbolAddress((void**)&p_x, g_x);
    cudaGetSymbolAddress((void**)&p_acvt, g_acvt);

    int gsmem = GSTAGES * (ASZ + BSZ) * (int)sizeof(float);
    cudaFuncSetAttribute(gemm_tf32<1>, cudaFuncAttributeMaxDynamicSharedMemorySize, gsmem);
    cudaFuncSetAttribute(gemm_tf32<0>, cudaFuncAttributeMaxDynamicSharedMemorySize, gsmem);
    int asmem = (4 * KVSZ + 128 * AS + 256) * (int)sizeof(float);   // ~103 KB
    cudaFuncSetAttribute(attn_tc_kernel, cudaFuncAttributeMaxDynamicSharedMemorySize, asmem);

    // 1. fold small projections into big weights (tf32-rounded)
    fold_w_kernel<<<dim3(DD * DD / 256, 3), 256>>>(wq, wk, wv, spatial_w, kproj_w, vlin_w);
    // 2. biases / chan fold / qv / bmean
    small_prep_kernel<<<141, 256>>>(bq, bk, bv, spatial_w, kproj_w, vlin_w,
                                    spatial_b, kproj_b, vlin_b,
                                    wk, chan_w, chan_b, qproj_w, qproj_b);
    // 3. round wo; pack mask; ck/cb gate scalars (raw key)
    tf32_cvt_kernel<<<DD * DD / 1024, 256>>>(wo, p_wof);
    mask_pack_kernel<<<BB * SS * SS / 8 / 256, 256>>>(mask);
    ckcb_kernel<<<MM / 8, 256>>>(key);

    dim3 ggrid(DD / 128, MM / 128);
    // 4-6. activations: round then tensor-core GEMM with fused ELU
    tf32_cvt_kernel<<<MM * DD / 1024, 256>>>(query, p_acvt);
    gemm_tf32<1><<<ggrid, 256, gsmem>>>(p_acvt, p_wqf, p_bqf, p_qs, MM, DD, DD);
    tf32_cvt_kernel<<<MM * DD / 1024, 256>>>(key, p_acvt);
    gemm_tf32<1><<<ggrid, 256, gsmem>>>(p_acvt, p_wkf, p_bkf, p_k2, MM, DD, DD);
    tf32_cvt_kernel<<<MM * DD / 1024, 256>>>(value, p_acvt);
    gemm_tf32<1><<<ggrid, 256, gsmem>>>(p_acvt, p_wvf, p_bvf, p_v2, MM, DD, DD);
    // 7. tensor-core attention (m computed inline; writes tf32-rounded g_x)
    attn_tc_kernel<<<dim3(SS / 128, HH, BB), 256, asmem>>>();
    // 8. output projection
    gemm_tf32<0><<<ggrid, 256, gsmem>>>(p_x, p_wof, bo, out, MM, DD, DD);
}

// round 8
// speedup vs baseline: 2.7415x; 1.0367x over previous
#include <cuda_runtime.h>
#include <math.h>
#include <stdint.h>

#define BB 4
#define SS 1024
#define DD 1024
#define HH 16
#define DK 64
#define MM (BB * SS)   // 4096

// ---------------- scratch (device globals; no allocation allowed) -------------
__device__ float g_wqf[DD * DD];
__device__ float g_wkf[DD * DD];
__device__ float g_wvf[DD * DD];
__device__ float g_wof[DD * DD];
__device__ float g_bqf[DD];
__device__ float g_bkf[DD];
__device__ float g_bvf[DD];
__device__ float g_wck[DD * HH];
__device__ float g_wcb[DD * HH];
__device__ float g_bck[HH];
__device__ float g_bcb[HH];
__device__ float g_qv[DK];
__device__ float g_bmean;
__device__ float g_qs[MM * DD];
__device__ float g_k2[MM * DD];
__device__ float g_v2[MM * DD];
__device__ float g_x[MM * DD];
__device__ float g_aq[MM * DD];     // tf32-rounded activations (3 buffers for merged launch)
__device__ float g_ak[MM * DD];
__device__ float g_av[MM * DD];
__device__ float g_ck[MM * HH];
__device__ float g_cb[MM * HH];
__device__ unsigned g_pm[BB * SS * SS / 32];   // packed mask bits

__device__ __forceinline__ float tf32r(float x) {
    float y;
    asm("cvt.rna.tf32.f32 %0, %1;" : "=f"(y) : "f"(x));
    return y;
}

#define MMA_TF32(d, a, b) \
    asm volatile("mma.sync.aligned.m16n8k8.row.col.f32.tf32.tf32.f32 " \
                 "{%0,%1,%2,%3},{%4,%5,%6,%7},{%8,%9},{%0,%1,%2,%3};" \
                 : "+f"(d[0]), "+f"(d[1]), "+f"(d[2]), "+f"(d[3]) \
                 : "r"(a[0]), "r"(a[1]), "r"(a[2]), "r"(a[3]), "r"(b[0]), "r"(b[1]));

// ---------------- 0. elementwise tf32 rounding pass ---------------------------
__global__ void tf32_cvt_kernel(const float* __restrict__ in, float* __restrict__ out) {
    int i = (blockIdx.x * 256 + threadIdx.x);
    float4 v = *(const float4*)(in + (size_t)i * 4);
    v.x = tf32r(v.x); v.y = tf32r(v.y); v.z = tf32r(v.z); v.w = tf32r(v.w);
    *(float4*)(out + (size_t)i * 4) = v;
}

// ---------------- 0b. pack mask into bits (8 ints -> 1 byte per thread) -------
__global__ void mask_pack_kernel(const int* __restrict__ mask) {
    int t = blockIdx.x * 256 + threadIdx.x;     // byte index
    const int4* p = (const int4*)mask + (size_t)t * 2;
    int4 a = p[0], b = p[1];
    unsigned byte = (unsigned)(a.x != 0) | ((unsigned)(a.y != 0) << 1)
                  | ((unsigned)(a.z != 0) << 2) | ((unsigned)(a.w != 0) << 3)
                  | ((unsigned)(b.x != 0) << 4) | ((unsigned)(b.y != 0) << 5)
                  | ((unsigned)(b.z != 0) << 6) | ((unsigned)(b.w != 0) << 7);
    ((unsigned char*)g_pm)[t] = (unsigned char)byte;
}

// ---------------- 1. fold per-head 64x64 projections into the big weights ----
__global__ void fold_w_kernel(const float* __restrict__ wq,
                              const float* __restrict__ wk,
                              const float* __restrict__ wv,
                              const float* __restrict__ sw,
                              const float* __restrict__ kp,
                              const float* __restrict__ vl) {
    int f = blockIdx.y;
    int idx = blockIdx.x * 256 + threadIdx.x;
    const float* W = (f == 0) ? wq : (f == 1) ? wk : wv;
    const float* P = (f == 0) ? sw : (f == 1) ? kp : vl;
    float* O = (f == 0) ? g_wqf : (f == 1) ? g_wkf : g_wvf;
    int d = idx >> 10;
    int c = idx & 1023;
    int h = c >> 6;
    int ep = c & 63;
    const float* wrow = W + d * DD + (h << 6);
    float sum = 0.f;
#pragma unroll 8
    for (int e = 0; e < DK; e++) sum += wrow[e] * P[e * DK + ep];
    O[idx] = tf32r(sum);
}

// ---------------- 2. small precompute -----------------------------------------
__global__ void small_prep_kernel(const float* __restrict__ bq,
                                  const float* __restrict__ bk,
                                  const float* __restrict__ bv,
                                  const float* __restrict__ sw,
                                  const float* __restrict__ kp,
                                  const float* __restrict__ vl,
                                  const float* __restrict__ sb,
                                  const float* __restrict__ kpb,
                                  const float* __restrict__ vlb,
                                  const float* __restrict__ wk,
                                  const float* __restrict__ chan_w,
                                  const float* __restrict__ chan_b,
                                  const float* __restrict__ qproj_w,
                                  const float* __restrict__ qproj_b) {
    int T = blockIdx.x * 256 + threadIdx.x;
    if (T < 3072) {
        int f = T >> 10;
        int c = T & 1023;
        int h = c >> 6;
        int ep = c & 63;
        const float* b = (f == 0) ? bq : (f == 1) ? bk : bv;
        const float* P = (f == 0) ? sw : (f == 1) ? kp : vl;
        const float* pb = (f == 0) ? sb : (f == 1) ? kpb : vlb;
        float* O = (f == 0) ? g_bqf : (f == 1) ? g_bkf : g_bvf;
        float sum = pb[ep];
        for (int e = 0; e < DK; e++) sum += b[(h << 6) + e] * P[e * DK + ep];
        O[c] = sum;
        return;
    }
    T -= 3072;
    if (T < 16384) {
        int d = T >> 4, h = T & 15;
        float sum = 0.f;
        for (int e = 0; e < DK; e++) sum += wk[d * DD + (h << 6) + e] * chan_w[e];
        g_wck[d * HH + h] = sum;
        return;
    }
    T -= 16384;
    if (T < 16384) {
        int d = T >> 4, h = T & 15;
        float sum = 0.f;
        for (int e = 0; e < DK; e++) sum += wk[d * DD + (h << 6) + e] * chan_b[e];
        g_wcb[d * HH + h] = sum;
        return;
    }
    T -= 16384;
    if (T < 16) {
        float sum = 0.f;
        for (int e = 0; e < DK; e++) sum += bk[(T << 6) + e] * chan_w[e];
        g_bck[T] = sum;
        return;
    }
    T -= 16;
    if (T < 16) {
        float sum = 0.f;
        for (int e = 0; e < DK; e++) sum += bk[(T << 6) + e] * chan_b[e];
        g_bcb[T] = sum;
        return;
    }
    T -= 16;
    if (T < 64) {
        float sum = 0.f;
        for (int ep = 0; ep < DK; ep++) sum += qproj_w[T * DK + ep];
        g_qv[T] = sum * (1.f / 64.f);
        return;
    }
    T -= 64;
    if (T == 0) {
        float sum = 0.f;
        for (int ep = 0; ep < DK; ep++) sum += qproj_b[ep];
        g_bmean = sum * (1.f / 64.f);
    }
}

// ---------------- 3. tf32 tensor-core GEMM: C = act(A @ W + bias) -------------
// A [M,K] rm (pre-rounded tf32), W [K,N] rm (pre-rounded tf32).
// 128x128 block tile, BK=32, 3-stage cp.async, 8 warps (2x4), 64x32 warp tile.
// blockIdx.z selects among up to 3 (A, W, bias, C) problem sets.
#define GSTAGES 3
#define GBK 32
#define AST 36     // padded A smem stride
#define BST 136    // padded B smem stride
#define ASZ (128 * AST)
#define BSZ (GBK * BST)
#define GSM_BYTES (GSTAGES * (ASZ + BSZ) * 4)   // 107520

struct GemmArgs {
    const float* A[3];
    const float* B[3];
    const float* bias[3];
    float* C[3];
};

__device__ __forceinline__ void cpa16(float* dst, const float* src) {
    unsigned d = (unsigned)__cvta_generic_to_shared(dst);
    asm volatile("cp.async.cg.shared.global [%0], [%1], 16;\n" :: "r"(d), "l"(src));
}

__device__ __forceinline__ void gemm_load_stage(float* As, float* Bs,
                                                const float* A, const float* Bm,
                                                int brow, int bcol, int kt, int tid) {
#pragma unroll
    for (int l = 0; l < 4; l++) {
        int lin = tid + l * 256;
        int row = lin >> 3, c4 = (lin & 7) << 2;         // 128 x 32 A tile
        cpa16(&As[row * AST + c4], &A[(size_t)(brow + row) * DD + kt * GBK + c4]);
    }
#pragma unroll
    for (int l = 0; l < 4; l++) {
        int lin = tid + l * 256;
        int kr = lin >> 5, c4 = (lin & 31) << 2;         // 32 x 128 B tile
        cpa16(&Bs[kr * BST + c4], &Bm[(size_t)(kt * GBK + kr) * DD + bcol + c4]);
    }
}

template <int ACT>   // 0 = none, 1 = elu
__global__ void __launch_bounds__(256, 2)
gemm_tf32(GemmArgs ga) {
    extern __shared__ float smem[];
    float* Asm = smem;
    float* Bsm = smem + GSTAGES * ASZ;

    int z = blockIdx.z;
    const float* A = ga.A[z];
    const float* Bm = ga.B[z];
    const float* bias = ga.bias[z];
    float* C = ga.C[z];

    int tid = threadIdx.x;
    int brow = blockIdx.y * 128;
    int bcol = blockIdx.x * 128;
    int warp = tid >> 5;
    int lane = tid & 31;
    int gr = lane >> 2;
    int gc = lane & 3;
    int wrow = (warp >> 2) * 64;
    int wcol = (warp & 3) * 32;

    float acc[4][4][4];
#pragma unroll
    for (int mt = 0; mt < 4; mt++)
#pragma unroll
        for (int nt = 0; nt < 4; nt++)
#pragma unroll
            for (int r = 0; r < 4; r++) acc[mt][nt][r] = 0.f;

    const int KT = DD / GBK;    // 32
    gemm_load_stage(Asm, Bsm, A, Bm, brow, bcol, 0, tid);
    asm volatile("cp.async.commit_group;\n");
    gemm_load_stage(Asm + ASZ, Bsm + BSZ, A, Bm, brow, bcol, 1, tid);
    asm volatile("cp.async.commit_group;\n");

    int s0 = 0, s1 = 1, s2 = 2;
    for (int kt = 0; kt < KT; kt++) {
        asm volatile("cp.async.wait_group 1;\n" ::: "memory");
        __syncthreads();
        float* As = Asm + s0 * ASZ;
        float* Bs = Bsm + s0 * BSZ;
#pragma unroll
        for (int kb = 0; kb < GBK; kb += 8) {
            uint32_t af[4][4], bf[4][2];
#pragma unroll
            for (int mt = 0; mt < 4; mt++) {
                int row0 = wrow + mt * 16 + gr;
                af[mt][0] = __float_as_uint(As[row0 * AST + kb + gc]);
                af[mt][1] = __float_as_uint(As[(row0 + 8) * AST + kb + gc]);
                af[mt][2] = __float_as_uint(As[row0 * AST + kb + gc + 4]);
                af[mt][3] = __float_as_uint(As[(row0 + 8) * AST + kb + gc + 4]);
            }
#pragma unroll
            for (int nt = 0; nt < 4; nt++) {
                int col0 = wcol + nt * 8 + gr;
                bf[nt][0] = __float_as_uint(Bs[(kb + gc) * BST + col0]);
                bf[nt][1] = __float_as_uint(Bs[(kb + gc + 4) * BST + col0]);
            }
#pragma unroll
            for (int mt = 0; mt < 4; mt++)
#pragma unroll
                for (int nt = 0; nt < 4; nt++)
                    MMA_TF32(acc[mt][nt], af[mt], bf[nt]);
        }
        int nk = kt + 2;
        if (nk < KT)
            gemm_load_stage(Asm + s2 * ASZ, Bsm + s2 * BSZ, A, Bm, brow, bcol, nk, tid);
        asm volatile("cp.async.commit_group;\n");
        int t = s0; s0 = s1; s1 = s2; s2 = t;
    }

    // epilogue: bias + optional ELU
#pragma unroll
    for (int mt = 0; mt < 4; mt++) {
        int r0 = brow + wrow + mt * 16 + gr;
#pragma unroll
        for (int nt = 0; nt < 4; nt++) {
            int c0 = bcol + wcol + nt * 8 + (gc << 1);
            float b0 = bias[c0], b1 = bias[c0 + 1];
            float v0 = acc[mt][nt][0] + b0;
            float v1 = acc[mt][nt][1] + b1;
            float v2 = acc[mt][nt][2] + b0;
            float v3 = acc[mt][nt][3] + b1;
            if (ACT == 1) {
                v0 = v0 > 0.f ? v0 : (__expf(v0) - 1.f);
                v1 = v1 > 0.f ? v1 : (__expf(v1) - 1.f);
                v2 = v2 > 0.f ? v2 : (__expf(v2) - 1.f);
                v3 = v3 > 0.f ? v3 : (__expf(v3) - 1.f);
            }
            *(float2*)&C[(size_t)r0 * DD + c0] = make_float2(v0, v1);
            *(float2*)&C[(size_t)(r0 + 8) * DD + c0] = make_float2(v2, v3);
        }
    }
}

// ---------------- 4. ck/cb skinny GEMV ----------------------------------------
__global__ void ckcb_kernel(const float* __restrict__ key) {
    __shared__ float rows[8][1024];
    int tid = threadIdx.x;
    int row0 = blockIdx.x * 8;
#pragma unroll
    for (int l = 0; l < 8; l++) {
        int lin = tid + l * 256;
        int r = lin >> 8;
        int c4 = (lin & 255) << 2;
        *(float4*)&rows[r][c4] = *(const float4*)&key[(size_t)(row0 + r) * DD + c4];
    }
    __syncthreads();
    int r = tid >> 5;
    int o = tid & 31;
    int h = o & 15;
    int isB = o >> 4;
    const float* wp = isB ? g_wcb : g_wck;
    float sum = isB ? g_bcb[h] : g_bck[h];
#pragma unroll 8
    for (int d = 0; d < DD; d++) sum += rows[r][d] * wp[d * HH + h];
    (isB ? g_cb : g_ck)[(size_t)(row0 + r) * HH + h] = sum;
}

// ---------------- 5. tensor-core flash attention, double-buffered -------------
// CTA: 128 q-rows x (b,h). 8 warps x 16 q-rows. K-tiles of 64, 2-deep pipeline.
#define AS 68
#define KVSZ (64 * AS)
__global__ void __launch_bounds__(256, 1) attn_tc_kernel() {
    extern __shared__ float sm[];
    float* KsB = sm;                    // 2 x [key][e]
    float* VtB = sm + 2 * KVSZ;         // 2 x [e][key]
    float* Ps  = sm + 4 * KVSZ;         // Q staging, then P [q][key]
    float* ckB = Ps + 128 * AS;         // 2 x 64
    float* cbB = ckB + 128;             // 2 x 64

    int tid = threadIdx.x;
    int q0 = blockIdx.x * 128;
    int h = blockIdx.y;
    int b = blockIdx.z;
    int warp = tid >> 5;
    int lane = tid & 31;
    int gr = lane >> 2;
    int gc = lane & 3;
    int wrow = warp * 16;

    int kr = tid >> 4;
    int ke4 = (tid & 15) << 2;
    int vk = tid & 63;
    int ve4 = (tid >> 6) << 2;

    // stage Q tile (tf32-rounded) into Ps
#pragma unroll
    for (int l = 0; l < 8; l++) {
        int lin = tid + l * 256;
        int r = lin >> 4;
        int e4 = (lin & 15) << 2;
        float4 v = *(const float4*)&g_qs[(size_t)((b << 10) + q0 + r) * DD + (h << 6) + e4];
        v.x = tf32r(v.x); v.y = tf32r(v.y); v.z = tf32r(v.z); v.w = tf32r(v.w);
        *(float4*)&Ps[r * AS + e4] = v;
    }
    // prefetch tile 0 into registers
    float4 kreg[4], vreg[4];
    float creg0 = 0.f, creg1 = 0.f;
#pragma unroll
    for (int l = 0; l < 4; l++) {
        int r = kr + l * 16;
        kreg[l] = *(const float4*)&g_k2[(size_t)((b << 10) + r) * DD + (h << 6) + ke4];
        int e4 = ve4 + l * 16;
        vreg[l] = *(const float4*)&g_v2[(size_t)((b << 10) + vk) * DD + (h << 6) + e4];
    }
    if (tid < 64) {
        creg0 = g_ck[(size_t)((b << 10) + tid) * HH + h];
        creg1 = g_cb[(size_t)((b << 10) + tid) * HH + h];
    }
    __syncthreads();   // Q visible

    uint32_t qf[8][4];
#pragma unroll
    for (int c = 0; c < 8; c++) {
        qf[c][0] = __float_as_uint(Ps[(wrow + gr) * AS + c * 8 + gc]);
        qf[c][1] = __float_as_uint(Ps[(wrow + gr + 8) * AS + c * 8 + gc]);
        qf[c][2] = __float_as_uint(Ps[(wrow + gr) * AS + c * 8 + gc + 4]);
        qf[c][3] = __float_as_uint(Ps[(wrow + gr + 8) * AS + c * 8 + gc + 4]);
    }
    // inline per-row gate scalar m = Q_row . qv + bmean
    float a0 = 0.f, a1 = 0.f;
#pragma unroll
    for (int e16 = 0; e16 < 16; e16++) {
        int e = gc * 16 + e16;
        float qv = __ldg(&g_qv[e]);
        a0 = fmaf(Ps[(wrow + gr) * AS + e], qv, a0);
        a1 = fmaf(Ps[(wrow + gr + 8) * AS + e], qv, a1);
    }
#pragma unroll
    for (int d = 1; d < 4; d <<= 1) {
        a0 += __shfl_xor_sync(0xffffffffu, a0, d);
        a1 += __shfl_xor_sync(0xffffffffu, a1, d);
    }
    float bmean = g_bmean;
    float mq0 = a0 + bmean;
    float mq1 = a1 + bmean;

    {   // store tile 0 into buffer 0
        float* Ks = KsB;
        float* Vt = VtB;
#pragma unroll
        for (int l = 0; l < 4; l++) {
            int r = kr + l * 16;
            float4 v = kreg[l];
            v.x = tf32r(v.x); v.y = tf32r(v.y); v.z = tf32r(v.z); v.w = tf32r(v.w);
            *(float4*)&Ks[r * AS + ke4] = v;
            int e4 = ve4 + l * 16;
            float4 w = vreg[l];
            Vt[(e4 + 0) * AS + vk] = tf32r(w.x);
            Vt[(e4 + 1) * AS + vk] = tf32r(w.y);
            Vt[(e4 + 2) * AS + vk] = tf32r(w.z);
            Vt[(e4 + 3) * AS + vk] = tf32r(w.w);
        }
        if (tid < 64) { ckB[tid] = creg0; cbB[tid] = creg1; }
    }

    int qrow0 = q0 + wrow + gr;
    int qrow1 = qrow0 + 8;
    float rm0 = -INFINITY, rm1 = -INFINITY, rs0 = 0.f, rs1 = 0.f;
    float ofr[8][4];
#pragma unroll
    for (int nf = 0; nf < 8; nf++)
#pragma unroll
        for (int r = 0; r < 4; r++) ofr[nf][r] = 0.f;

    unsigned pmbase0 = ((unsigned)((b << 10) + qrow0)) << 5;
    unsigned pmbase1 = ((unsigned)((b << 10) + qrow1)) << 5;

    for (int kt = 0; kt < 16; kt++) {
        __syncthreads();
        int cur = kt & 1;
        float* Ks = KsB + cur * KVSZ;
        float* Vt = VtB + cur * KVSZ;
        float* ckv = ckB + cur * 64;
        float* cbv = cbB + cur * 64;
        int k0 = kt * 64;

        if (kt < 15) {
            int kn = k0 + 64;
#pragma unroll
            for (int l = 0; l < 4; l++) {
                int r = kn + kr + l * 16;
                kreg[l] = *(const float4*)&g_k2[(size_t)((b << 10) + r) * DD + (h << 6) + ke4];
                int e4 = ve4 + l * 16;
                vreg[l] = *(const float4*)&g_v2[(size_t)((b << 10) + kn + vk) * DD + (h << 6) + e4];
            }
            if (tid < 64) {
                creg0 = g_ck[(size_t)((b << 10) + kn + tid) * HH + h];
                creg1 = g_cb[(size_t)((b << 10) + kn + tid) * HH + h];
            }
        }

        float sfr[8][4];
#pragma unroll
        for (int nf = 0; nf < 8; nf++)
#pragma unroll
            for (int r = 0; r < 4; r++) sfr[nf][r] = 0.f;
#pragma unroll
        for (int c = 0; c < 8; c++) {
#pragma unroll
            for (int nf = 0; nf < 8; nf++) {
                uint32_t bf[2];
                bf[0] = __float_as_uint(Ks[(nf * 8 + gr) * AS + c * 8 + gc]);
                bf[1] = __float_as_uint(Ks[(nf * 8 + gr) * AS + c * 8 + gc + 4]);
                MMA_TF32(sfr[nf], qf[c], bf);
            }
        }

        unsigned w00 = g_pm[pmbase0 + (k0 >> 5)];
        unsigned w01 = g_pm[pmbase0 + (k0 >> 5) + 1];
        unsigned w10 = g_pm[pmbase1 + (k0 >> 5)];
        unsigned w11 = g_pm[pmbase1 + (k0 >> 5) + 1];
#pragma unroll
        for (int nf = 0; nf < 8; nf++) {
            int c0 = nf * 8 + (gc << 1);
            int c1 = c0 + 1;
            float lk0 = ckv[c0], lk1 = ckv[c1];
            float lb0 = cbv[c0], lb1 = cbv[c1];
            float g00 = __fdividef(1.f, 1.f + __expf(-fmaf(mq0, lk0, lb0)));
            float g01 = __fdividef(1.f, 1.f + __expf(-fmaf(mq0, lk1, lb1)));
            float g10 = __fdividef(1.f, 1.f + __expf(-fmaf(mq1, lk0, lb0)));
            float g11 = __fdividef(1.f, 1.f + __expf(-fmaf(mq1, lk1, lb1)));
            float v0 = sfr[nf][0] * 0.125f * g00;
            float v1 = sfr[nf][1] * 0.125f * g01;
            float v2 = sfr[nf][2] * 0.125f * g10;
            float v3 = sfr[nf][3] * 0.125f * g11;
            unsigned wa0 = (c0 < 32) ? w00 : w01;
            unsigned wa1 = (c1 < 32) ? w00 : w01;
            unsigned wb0 = (c0 < 32) ? w10 : w11;
            unsigned wb1 = (c1 < 32) ? w10 : w11;
            if (!((wa0 >> (c0 & 31)) & 1u)) v0 = -1e9f;
            if (!((wa1 >> (c1 & 31)) & 1u)) v1 = -1e9f;
            if (!((wb0 >> (c0 & 31)) & 1u)) v2 = -1e9f;
            if (!((wb1 >> (c1 & 31)) & 1u)) v3 = -1e9f;
            sfr[nf][0] = v0; sfr[nf][1] = v1; sfr[nf][2] = v2; sfr[nf][3] = v3;
        }

        float m0 = -INFINITY, m1 = -INFINITY;
#pragma unroll
        for (int nf = 0; nf < 8; nf++) {
            m0 = fmaxf(m0, fmaxf(sfr[nf][0], sfr[nf][1]));
            m1 = fmaxf(m1, fmaxf(sfr[nf][2], sfr[nf][3]));
        }
#pragma unroll
        for (int d = 1; d < 4; d <<= 1) {
            m0 = fmaxf(m0, __shfl_xor_sync(0xffffffffu, m0, d));
            m1 = fmaxf(m1, __shfl_xor_sync(0xffffffffu, m1, d));
        }
        float tm0 = fmaxf(rm0, m0);
        float tm1 = fmaxf(rm1, m1);
        float sc0 = __expf(rm0 - tm0);
        float sc1 = __expf(rm1 - tm1);
        rm0 = tm0; rm1 = tm1;
        float sum0 = 0.f, sum1 = 0.f;
#pragma unroll
        for (int nf = 0; nf < 8; nf++) {
            float p0 = __expf(sfr[nf][0] - tm0);
            float p1 = __expf(sfr[nf][1] - tm0);
            float p2 = __expf(sfr[nf][2] - tm1);
            float p3 = __expf(sfr[nf][3] - tm1);
            sum0 += p0 + p1;
            sum1 += p2 + p3;
            sfr[nf][0] = p0; sfr[nf][1] = p1; sfr[nf][2] = p2; sfr[nf][3] = p3;
        }
#pragma unroll
        for (int d = 1; d < 4; d <<= 1) {
            sum0 += __shfl_xor_sync(0xffffffffu, sum0, d);
            sum1 += __shfl_xor_sync(0xffffffffu, sum1, d);
        }
        rs0 = rs0 * sc0 + sum0;
        rs1 = rs1 * sc1 + sum1;
#pragma unroll
        for (int nf = 0; nf < 8; nf++) {
            ofr[nf][0] *= sc0; ofr[nf][1] *= sc0;
            ofr[nf][2] *= sc1; ofr[nf][3] *= sc1;
        }

#pragma unroll
        for (int nf = 0; nf < 8; nf++) {
            int c0 = nf * 8 + (gc << 1);
            *(float2*)&Ps[(wrow + gr) * AS + c0] =
                make_float2(tf32r(sfr[nf][0]), tf32r(sfr[nf][1]));
            *(float2*)&Ps[(wrow + gr + 8) * AS + c0] =
                make_float2(tf32r(sfr[nf][2]), tf32r(sfr[nf][3]));
        }
        __syncwarp();

#pragma unroll
        for (int c = 0; c < 8; c++) {
            uint32_t af[4];
            af[0] = __float_as_uint(Ps[(wrow + gr) * AS + c * 8 + gc]);
            af[1] = __float_as_uint(Ps[(wrow + gr + 8) * AS + c * 8 + gc]);
            af[2] = __float_as_uint(Ps[(wrow + gr) * AS + c * 8 + gc + 4]);
            af[3] = __float_as_uint(Ps[(wrow + gr + 8) * AS + c * 8 + gc + 4]);
#pragma unroll
            for (int nf = 0; nf < 8; nf++) {
                uint32_t bf[2];
                bf[0] = __float_as_uint(Vt[(nf * 8 + gr) * AS + c * 8 + gc]);
                bf[1] = __float_as_uint(Vt[(nf * 8 + gr) * AS + c * 8 + gc + 4]);
                MMA_TF32(ofr[nf], af, bf);
            }
        }

        if (kt < 15) {
            int nxt = 1 - cur;
            float* Ksn = KsB + nxt * KVSZ;
            float* Vtn = VtB + nxt * KVSZ;
#pragma unroll
            for (int l = 0; l < 4; l++) {
                int r = kr + l * 16;
                float4 v = kreg[l];
                v.x = tf32r(v.x); v.y = tf32r(v.y); v.z = tf32r(v.z); v.w = tf32r(v.w);
                *(float4*)&Ksn[r * AS + ke4] = v;
                int e4 = ve4 + l * 16;
                float4 w = vreg[l];
                Vtn[(e4 + 0) * AS + vk] = tf32r(w.x);
                Vtn[(e4 + 1) * AS + vk] = tf32r(w.y);
                Vtn[(e4 + 2) * AS + vk] = tf32r(w.z);
                Vtn[(e4 + 3) * AS + vk] = tf32r(w.w);
            }
            if (tid < 64) { ckB[nxt * 64 + tid] = creg0; cbB[nxt * 64 + tid] = creg1; }
        }
    }

    // normalize + write (tf32-rounded for the out-proj GEMM)
    float inv0 = 1.f / rs0;
    float inv1 = 1.f / rs1;
#pragma unroll
    for (int nf = 0; nf < 8; nf++) {
        int c0 = (h << 6) + nf * 8 + (gc << 1);
        *(float2*)&g_x[(size_t)((b << 10) + qrow0) * DD + c0] =
            make_float2(tf32r(ofr[nf][0] * inv0), tf32r(ofr[nf][1] * inv0));
        *(float2*)&g_x[(size_t)((b << 10) + qrow1) * DD + c0] =
            make_float2(tf32r(ofr[nf][2] * inv1), tf32r(ofr[nf][3] * inv1));
    }
}

// ---------------- launch ------------------------------------------------------
extern "C" void kernel_launch(void* const* d_in, const int* in_sizes, int n_in,
                              void* d_out, int out_size) {
    const float* query = (const float*)d_in[0];
    const float* key   = (const float*)d_in[1];
    const float* value = (const float*)d_in[2];
    const int*   mask  = (const int*)d_in[3];
    const float* wq = (const float*)d_in[4];
    const float* bq = (const float*)d_in[5];
    const float* wk = (const float*)d_in[6];
    const float* bk = (const float*)d_in[7];
    const float* wv = (const float*)d_in[8];
    const float* bv = (const float*)d_in[9];
    const float* wo = (const float*)d_in[10];
    const float* bo = (const float*)d_in[11];
    const float* spatial_w = (const float*)d_in[12];
    const float* spatial_b = (const float*)d_in[13];
    const float* qproj_w = (const float*)d_in[14];
    const float* qproj_b = (const float*)d_in[15];
    const float* kproj_w = (const float*)d_in[16];
    const float* kproj_b = (const float*)d_in[17];
    const float* vlin_w = (const float*)d_in[18];
    const float* vlin_b = (const float*)d_in[19];
    const float* chan_w = (const float*)d_in[20];
    const float* chan_b = (const float*)d_in[21];
    float* out = (float*)d_out;

    float *p_wqf, *p_wkf, *p_wvf, *p_wof, *p_bqf, *p_bkf, *p_bvf;
    float *p_qs, *p_k2, *p_v2, *p_x, *p_aq, *p_ak, *p_av;
    cudaGetSymbolAddress((void**)&p_wqf, g_wqf);
    cudaGetSymbolAddress((void**)&p_wkf, g_wkf);
    cudaGetSymbolAddress((void**)&p_wvf, g_wvf);
    cudaGetSymbolAddress((void**)&p_wof, g_wof);
    cudaGetSymbolAddress((void**)&p_bqf, g_bqf);
    cudaGetSymbolAddress((void**)&p_bkf, g_bkf);
    cudaGetSymbolAddress((void**)&p_bvf, g_bvf);
    cudaGetSymbolAddress((void**)&p_qs, g_qs);
    cudaGetSymbolAddress((void**)&p_k2, g_k2);
    cudaGetSymbolAddress((void**)&p_v2, g_v2);
    cudaGetSymbolAddress((void**)&p_x, g_x);
    cudaGetSymbolAddress((void**)&p_aq, g_aq);
    cudaGetSymbolAddress((void**)&p_ak, g_ak);
    cudaGetSymbolAddress((void**)&p_av, g_av);

    cudaFuncSetAttribute(gemm_tf32<1>, cudaFuncAttributeMaxDynamicSharedMemorySize, GSM_BYTES);
    cudaFuncSetAttribute(gemm_tf32<0>, cudaFuncAttributeMaxDynamicSharedMemorySize, GSM_BYTES);
    int asmem = (4 * KVSZ + 128 * AS + 256) * (int)sizeof(float);   // ~103 KB
    cudaFuncSetAttribute(attn_tc_kernel, cudaFuncAttributeMaxDynamicSharedMemorySize, asmem);

    // 1. fold small projections into big weights (tf32-rounded)
    fold_w_kernel<<<dim3(DD * DD / 256, 3), 256>>>(wq, wk, wv, spatial_w, kproj_w, vlin_w);
    // 2. biases / chan fold / qv / bmean
    small_prep_kernel<<<141, 256>>>(bq, bk, bv, spatial_w, kproj_w, vlin_w,
                                    spatial_b, kproj_b, vlin_b,
                                    wk, chan_w, chan_b, qproj_w, qproj_b);
    // 3. round wo; pack mask; ck/cb gate scalars (raw key)
    tf32_cvt_kernel<<<DD * DD / 1024, 256>>>(wo, p_wof);
    mask_pack_kernel<<<BB * SS * SS / 8 / 256, 256>>>(mask);
    ckcb_kernel<<<MM / 8, 256>>>(key);

    // 4. round all three activations
    tf32_cvt_kernel<<<MM * DD / 1024, 256>>>(query, p_aq);
    tf32_cvt_kernel<<<MM * DD / 1024, 256>>>(key, p_ak);
    tf32_cvt_kernel<<<MM * DD / 1024, 256>>>(value, p_av);

    // 5. merged QKV GEMM (z = 0,1,2) with fused ELU
    GemmArgs gqkv;
    gqkv.A[0] = p_aq;  gqkv.A[1] = p_ak;  gqkv.A[2] = p_av;
    gqkv.B[0] = p_wqf; gqkv.B[1] = p_wkf; gqkv.B[2] = p_wvf;
    gqkv.bias[0] = p_bqf; gqkv.bias[1] = p_bkf; gqkv.bias[2] = p_bvf;
    gqkv.C[0] = p_qs;  gqkv.C[1] = p_k2;  gqkv.C[2] = p_v2;
    gemm_tf32<1><<<dim3(DD / 128, MM / 128, 3), 256, GSM_BYTES>>>(gqkv);

    // 6. tensor-core attention (m computed inline; writes tf32-rounded g_x)
    attn_tc_kernel<<<dim3(SS / 128, HH, BB), 256, asmem>>>();

    // 7. output projection
    GemmArgs go;
    go.A[0] = go.A[1] = go.A[2] = p_x;
    go.B[0] = go.B[1] = go.B[2] = p_wof;
    go.bias[0] = go.bias[1] = go.bias[2] = bo;
    go.C[0] = go.C[1] = go.C[2] = out;
    gemm_tf32<0><<<dim3(DD / 128, MM / 128, 1), 256, GSM_BYTES>>>(go);
}

// round 9
// speedup vs baseline: 3.1090x; 1.1340x over previous
#include <cuda_runtime.h>
#include <math.h>
#include <stdint.h>

#define BB 4
#define SS 1024
#define DD 1024
#define HH 16
#define DK 64
#define MM (BB * SS)   // 4096

// ---------------- scratch (device globals; no allocation allowed) -------------
__device__ float g_wqf[DD * DD];
__device__ float g_wkf[DD * DD];
__device__ float g_wvf[DD * DD];
__device__ float g_wof[DD * DD];
__device__ float g_bqf[DD];
__device__ float g_bkf[DD];
__device__ float g_bvf[DD];
__device__ float g_wck[DD * HH];
__device__ float g_wcb[DD * HH];
__device__ float g_bck[HH];
__device__ float g_bcb[HH];
__device__ float g_qv[DK];
__device__ float g_bmean;
__device__ float g_qs[MM * DD];
__device__ float g_k2[MM * DD];
__device__ float g_v2[MM * DD];
__device__ float g_x[MM * DD];
__device__ float g_aq[MM * DD];     // tf32-rounded activations
__device__ float g_ak[MM * DD];
__device__ float g_av[MM * DD];
__device__ float g_ck[MM * HH];
__device__ float g_cb[MM * HH];
__device__ unsigned g_pm[BB * SS * SS / 32];   // packed mask bits

__device__ __forceinline__ float tf32r(float x) {
    float y;
    asm("cvt.rna.tf32.f32 %0, %1;" : "=f"(y) : "f"(x));
    return y;
}

#define MMA_TF32(d, a, b) \
    asm volatile("mma.sync.aligned.m16n8k8.row.col.f32.tf32.tf32.f32 " \
                 "{%0,%1,%2,%3},{%4,%5,%6,%7},{%8,%9},{%0,%1,%2,%3};" \
                 : "+f"(d[0]), "+f"(d[1]), "+f"(d[2]), "+f"(d[3]) \
                 : "r"(a[0]), "r"(a[1]), "r"(a[2]), "r"(a[3]), "r"(b[0]), "r"(b[1]));

__device__ __forceinline__ void cpa16(float* dst, const float* src) {
    unsigned d = (unsigned)__cvta_generic_to_shared(dst);
    asm volatile("cp.async.cg.shared.global [%0], [%1], 16;\n" :: "r"(d), "l"(src));
}
__device__ __forceinline__ void cpa4(float* dst, const float* src) {
    unsigned d = (unsigned)__cvta_generic_to_shared(dst);
    asm volatile("cp.async.ca.shared.global [%0], [%1], 4;\n" :: "r"(d), "l"(src));
}

// ---------------- 0. elementwise tf32 rounding pass ---------------------------
__global__ void tf32_cvt_kernel(const float* __restrict__ in, float* __restrict__ out) {
    int i = (blockIdx.x * 256 + threadIdx.x);
    float4 v = *(const float4*)(in + (size_t)i * 4);
    v.x = tf32r(v.x); v.y = tf32r(v.y); v.z = tf32r(v.z); v.w = tf32r(v.w);
    *(float4*)(out + (size_t)i * 4) = v;
}

// ---------------- 0b. pack mask into bits (8 ints -> 1 byte per thread) -------
__global__ void mask_pack_kernel(const int* __restrict__ mask) {
    int t = blockIdx.x * 256 + threadIdx.x;     // byte index
    const int4* p = (const int4*)mask + (size_t)t * 2;
    int4 a = p[0], b = p[1];
    unsigned byte = (unsigned)(a.x != 0) | ((unsigned)(a.y != 0) << 1)
                  | ((unsigned)(a.z != 0) << 2) | ((unsigned)(a.w != 0) << 3)
                  | ((unsigned)(b.x != 0) << 4) | ((unsigned)(b.y != 0) << 5)
                  | ((unsigned)(b.z != 0) << 6) | ((unsigned)(b.w != 0) << 7);
    ((unsigned char*)g_pm)[t] = (unsigned char)byte;
}

// ---------------- 1. fold per-head 64x64 projections into the big weights ----
__global__ void fold_w_kernel(const float* __restrict__ wq,
                              const float* __restrict__ wk,
                              const float* __restrict__ wv,
                              const float* __restrict__ sw,
                              const float* __restrict__ kp,
                              const float* __restrict__ vl) {
    int f = blockIdx.y;
    int idx = blockIdx.x * 256 + threadIdx.x;
    const float* W = (f == 0) ? wq : (f == 1) ? wk : wv;
    const float* P = (f == 0) ? sw : (f == 1) ? kp : vl;
    float* O = (f == 0) ? g_wqf : (f == 1) ? g_wkf : g_wvf;
    int d = idx >> 10;
    int c = idx & 1023;
    int h = c >> 6;
    int ep = c & 63;
    const float* wrow = W + d * DD + (h << 6);
    float sum = 0.f;
#pragma unroll 8
    for (int e = 0; e < DK; e++) sum += wrow[e] * P[e * DK + ep];
    O[idx] = tf32r(sum);
}

// ---------------- 2. small precompute -----------------------------------------
__global__ void small_prep_kernel(const float* __restrict__ bq,
                                  const float* __restrict__ bk,
                                  const float* __restrict__ bv,
                                  const float* __restrict__ sw,
                                  const float* __restrict__ kp,
                                  const float* __restrict__ vl,
                                  const float* __restrict__ sb,
                                  const float* __restrict__ kpb,
                                  const float* __restrict__ vlb,
                                  const float* __restrict__ wk,
                                  const float* __restrict__ chan_w,
                                  const float* __restrict__ chan_b,
                                  const float* __restrict__ qproj_w,
                                  const float* __restrict__ qproj_b) {
    int T = blockIdx.x * 256 + threadIdx.x;
    if (T < 3072) {
        int f = T >> 10;
        int c = T & 1023;
        int h = c >> 6;
        int ep = c & 63;
        const float* b = (f == 0) ? bq : (f == 1) ? bk : bv;
        const float* P = (f == 0) ? sw : (f == 1) ? kp : vl;
        const float* pb = (f == 0) ? sb : (f == 1) ? kpb : vlb;
        float* O = (f == 0) ? g_bqf : (f == 1) ? g_bkf : g_bvf;
        float sum = pb[ep];
        for (int e = 0; e < DK; e++) sum += b[(h << 6) + e] * P[e * DK + ep];
        O[c] = sum;
        return;
    }
    T -= 3072;
    if (T < 16384) {
        int d = T >> 4, h = T & 15;
        float sum = 0.f;
        for (int e = 0; e < DK; e++) sum += wk[d * DD + (h << 6) + e] * chan_w[e];
        g_wck[d * HH + h] = sum;
        return;
    }
    T -= 16384;
    if (T < 16384) {
        int d = T >> 4, h = T & 15;
        float sum = 0.f;
        for (int e = 0; e < DK; e++) sum += wk[d * DD + (h << 6) + e] * chan_b[e];
        g_wcb[d * HH + h] = sum;
        return;
    }
    T -= 16384;
    if (T < 16) {
        float sum = 0.f;
        for (int e = 0; e < DK; e++) sum += bk[(T << 6) + e] * chan_w[e];
        g_bck[T] = sum;
        return;
    }
    T -= 16;
    if (T < 16) {
        float sum = 0.f;
        for (int e = 0; e < DK; e++) sum += bk[(T << 6) + e] * chan_b[e];
        g_bcb[T] = sum;
        return;
    }
    T -= 16;
    if (T < 64) {
        float sum = 0.f;
        for (int ep = 0; ep < DK; ep++) sum += qproj_w[T * DK + ep];
        g_qv[T] = sum * (1.f / 64.f);
        return;
    }
    T -= 64;
    if (T == 0) {
        float sum = 0.f;
        for (int ep = 0; ep < DK; ep++) sum += qproj_b[ep];
        g_bmean = sum * (1.f / 64.f);
    }
}

// ---------------- 3. tf32 tensor-core GEMM: C = act(A @ W + bias) -------------
// ACT==1 additionally tf32-rounds the output (feeds the attention kernel).
#define GSTAGES 3
#define GBK 32
#define AST 36
#define BST 136
#define ASZ (128 * AST)
#define BSZ (GBK * BST)
#define GSM_BYTES (GSTAGES * (ASZ + BSZ) * 4)   // 107520

struct GemmArgs {
    const float* A[3];
    const float* B[3];
    const float* bias[3];
    float* C[3];
};

__device__ __forceinline__ void gemm_load_stage(float* As, float* Bs,
                                                const float* A, const float* Bm,
                                                int brow, int bcol, int kt, int tid) {
#pragma unroll
    for (int l = 0; l < 4; l++) {
        int lin = tid + l * 256;
        int row = lin >> 3, c4 = (lin & 7) << 2;
        cpa16(&As[row * AST + c4], &A[(size_t)(brow + row) * DD + kt * GBK + c4]);
    }
#pragma unroll
    for (int l = 0; l < 4; l++) {
        int lin = tid + l * 256;
        int kr = lin >> 5, c4 = (lin & 31) << 2;
        cpa16(&Bs[kr * BST + c4], &Bm[(size_t)(kt * GBK + kr) * DD + bcol + c4]);
    }
}

template <int ACT>   // 0 = none, 1 = elu + tf32-round
__global__ void __launch_bounds__(256, 2)
gemm_tf32(GemmArgs ga) {
    extern __shared__ float smem[];
    float* Asm = smem;
    float* Bsm = smem + GSTAGES * ASZ;

    int z = blockIdx.z;
    const float* A = ga.A[z];
    const float* Bm = ga.B[z];
    const float* bias = ga.bias[z];
    float* C = ga.C[z];

    int tid = threadIdx.x;
    int brow = blockIdx.y * 128;
    int bcol = blockIdx.x * 128;
    int warp = tid >> 5;
    int lane = tid & 31;
    int gr = lane >> 2;
    int gc = lane & 3;
    int wrow = (warp >> 2) * 64;
    int wcol = (warp & 3) * 32;

    float acc[4][4][4];
#pragma unroll
    for (int mt = 0; mt < 4; mt++)
#pragma unroll
        for (int nt = 0; nt < 4; nt++)
#pragma unroll
            for (int r = 0; r < 4; r++) acc[mt][nt][r] = 0.f;

    const int KT = DD / GBK;    // 32
    gemm_load_stage(Asm, Bsm, A, Bm, brow, bcol, 0, tid);
    asm volatile("cp.async.commit_group;\n");
    gemm_load_stage(Asm + ASZ, Bsm + BSZ, A, Bm, brow, bcol, 1, tid);
    asm volatile("cp.async.commit_group;\n");

    int s0 = 0, s1 = 1, s2 = 2;
    for (int kt = 0; kt < KT; kt++) {
        asm volatile("cp.async.wait_group 1;\n" ::: "memory");
        __syncthreads();
        float* As = Asm + s0 * ASZ;
        float* Bs = Bsm + s0 * BSZ;
#pragma unroll
        for (int kb = 0; kb < GBK; kb += 8) {
            uint32_t af[4][4], bf[4][2];
#pragma unroll
            for (int mt = 0; mt < 4; mt++) {
                int row0 = wrow + mt * 16 + gr;
                af[mt][0] = __float_as_uint(As[row0 * AST + kb + gc]);
                af[mt][1] = __float_as_uint(As[(row0 + 8) * AST + kb + gc]);
                af[mt][2] = __float_as_uint(As[row0 * AST + kb + gc + 4]);
                af[mt][3] = __float_as_uint(As[(row0 + 8) * AST + kb + gc + 4]);
            }
#pragma unroll
            for (int nt = 0; nt < 4; nt++) {
                int col0 = wcol + nt * 8 + gr;
                bf[nt][0] = __float_as_uint(Bs[(kb + gc) * BST + col0]);
                bf[nt][1] = __float_as_uint(Bs[(kb + gc + 4) * BST + col0]);
            }
#pragma unroll
            for (int mt = 0; mt < 4; mt++)
#pragma unroll
                for (int nt = 0; nt < 4; nt++)
                    MMA_TF32(acc[mt][nt], af[mt], bf[nt]);
        }
        int nk = kt + 2;
        if (nk < KT)
            gemm_load_stage(Asm + s2 * ASZ, Bsm + s2 * BSZ, A, Bm, brow, bcol, nk, tid);
        asm volatile("cp.async.commit_group;\n");
        int t = s0; s0 = s1; s1 = s2; s2 = t;
    }

    // epilogue: bias + optional ELU (+ tf32 rounding for downstream MMA use)
#pragma unroll
    for (int mt = 0; mt < 4; mt++) {
        int r0 = brow + wrow + mt * 16 + gr;
#pragma unroll
        for (int nt = 0; nt < 4; nt++) {
            int c0 = bcol + wcol + nt * 8 + (gc << 1);
            float b0 = bias[c0], b1 = bias[c0 + 1];
            float v0 = acc[mt][nt][0] + b0;
            float v1 = acc[mt][nt][1] + b1;
            float v2 = acc[mt][nt][2] + b0;
            float v3 = acc[mt][nt][3] + b1;
            if (ACT == 1) {
                v0 = v0 > 0.f ? v0 : (__expf(v0) - 1.f);
                v1 = v1 > 0.f ? v1 : (__expf(v1) - 1.f);
                v2 = v2 > 0.f ? v2 : (__expf(v2) - 1.f);
                v3 = v3 > 0.f ? v3 : (__expf(v3) - 1.f);
                v0 = tf32r(v0); v1 = tf32r(v1); v2 = tf32r(v2); v3 = tf32r(v3);
            }
            *(float2*)&C[(size_t)r0 * DD + c0] = make_float2(v0, v1);
            *(float2*)&C[(size_t)(r0 + 8) * DD + c0] = make_float2(v2, v3);
        }
    }
}

// ---------------- 4. ck/cb skinny GEMV ----------------------------------------
__global__ void ckcb_kernel(const float* __restrict__ key) {
    __shared__ float rows[8][1024];
    int tid = threadIdx.x;
    int row0 = blockIdx.x * 8;
#pragma unroll
    for (int l = 0; l < 8; l++) {
        int lin = tid + l * 256;
        int r = lin >> 8;
        int c4 = (lin & 255) << 2;
        *(float4*)&rows[r][c4] = *(const float4*)&key[(size_t)(row0 + r) * DD + c4];
    }
    __syncthreads();
    int r = tid >> 5;
    int o = tid & 31;
    int h = o & 15;
    int isB = o >> 4;
    const float* wp = isB ? g_wcb : g_wck;
    float sum = isB ? g_bcb[h] : g_bck[h];
#pragma unroll 8
    for (int d = 0; d < DD; d++) sum += rows[r][d] * wp[d * HH + h];
    (isB ? g_cb : g_ck)[(size_t)(row0 + r) * HH + h] = sum;
}

// ---------------- 5. tensor-core flash attention, cp.async, occ 2 -------------
// CTA: 64 q-rows x (b,h). 4 warps x 16 q-rows. K-tiles of 64, 2-buffer cp.async.
// K smem stride 68 (=4 mod 32), V kept [k][e] stride 72 (=8 mod 32) — both
// B-fragment LDS patterns bank-conflict-free. All inputs pre-rounded to tf32.
#define AKS 68
#define AVS 72
#define PS_F (64 * AKS)
#define KB_F (64 * AKS)
#define VB_F (64 * AVS)
#define ASM_BYTES ((PS_F + 2 * KB_F + 2 * VB_F + 256) * 4)   // 90112

__global__ void __launch_bounds__(128, 2) attn_tc_kernel() {
    extern __shared__ float sm[];
    float* Ps  = sm;                       // Q staging, then P [q][key]
    float* KsB = sm + PS_F;                // 2 x [key][e] stride 68
    float* VsB = KsB + 2 * KB_F;           // 2 x [key][e] stride 72
    float* ckB = VsB + 2 * VB_F;           // 2 x 64
    float* cbB = ckB + 128;                // 2 x 64

    int tid = threadIdx.x;
    int q0 = blockIdx.x * 64;
    int h = blockIdx.y;
    int b = blockIdx.z;
    int warp = tid >> 5;
    int lane = tid & 31;
    int gr = lane >> 2;
    int gc = lane & 3;
    int wrow = warp * 16;

    // issue Q staging (group 0)
#pragma unroll
    for (int l = 0; l < 8; l++) {
        int lin = tid + l * 128;
        int r = lin >> 4;
        int e4 = (lin & 15) << 2;
        cpa16(&Ps[r * AKS + e4],
              &g_qs[(size_t)((b << 10) + q0 + r) * DD + (h << 6) + e4]);
    }
    asm volatile("cp.async.commit_group;\n");

    // issue tile-0 K/V/ck/cb (group 1)
    auto issue_tile = [&](int kt, int buf) {
        int k0 = kt * 64;
        float* Ks = KsB + buf * KB_F;
        float* Vs = VsB + buf * VB_F;
#pragma unroll
        for (int l = 0; l < 8; l++) {
            int lin = tid + l * 128;
            int r = lin >> 4;
            int e4 = (lin & 15) << 2;
            size_t gi = (size_t)((b << 10) + k0 + r) * DD + (h << 6) + e4;
            cpa16(&Ks[r * AKS + e4], &g_k2[gi]);
            cpa16(&Vs[r * AVS + e4], &g_v2[gi]);
        }
        if (tid < 64) {
            cpa4(&ckB[buf * 64 + tid], &g_ck[(size_t)((b << 10) + k0 + tid) * HH + h]);
            cpa4(&cbB[buf * 64 + tid], &g_cb[(size_t)((b << 10) + k0 + tid) * HH + h]);
        }
        asm volatile("cp.async.commit_group;\n");
    };
    issue_tile(0, 0);

    // wait Q (leave tile-0 in flight), extract Q fragments + gate scalar m
    asm volatile("cp.async.wait_group 1;\n" ::: "memory");
    __syncthreads();

    uint32_t qf[8][4];
#pragma unroll
    for (int c = 0; c < 8; c++) {
        qf[c][0] = __float_as_uint(Ps[(wrow + gr) * AKS + c * 8 + gc]);
        qf[c][1] = __float_as_uint(Ps[(wrow + gr + 8) * AKS + c * 8 + gc]);
        qf[c][2] = __float_as_uint(Ps[(wrow + gr) * AKS + c * 8 + gc + 4]);
        qf[c][3] = __float_as_uint(Ps[(wrow + gr + 8) * AKS + c * 8 + gc + 4]);
    }
    float a0 = 0.f, a1 = 0.f;
#pragma unroll
    for (int e16 = 0; e16 < 16; e16++) {
        int e = gc * 16 + e16;
        float qv = __ldg(&g_qv[e]);
        a0 = fmaf(Ps[(wrow + gr) * AKS + e], qv, a0);
        a1 = fmaf(Ps[(wrow + gr + 8) * AKS + e], qv, a1);
    }
#pragma unroll
    for (int d = 1; d < 4; d <<= 1) {
        a0 += __shfl_xor_sync(0xffffffffu, a0, d);
        a1 += __shfl_xor_sync(0xffffffffu, a1, d);
    }
    float bmean = g_bmean;
    float mq0 = a0 + bmean;
    float mq1 = a1 + bmean;

    int qrow0 = q0 + wrow + gr;
    int qrow1 = qrow0 + 8;
    float rm0 = -INFINITY, rm1 = -INFINITY, rs0 = 0.f, rs1 = 0.f;
    float ofr[8][4];
#pragma unroll
    for (int nf = 0; nf < 8; nf++)
#pragma unroll
        for (int r = 0; r < 4; r++) ofr[nf][r] = 0.f;

    unsigned pmbase0 = ((unsigned)((b << 10) + qrow0)) << 5;
    unsigned pmbase1 = ((unsigned)((b << 10) + qrow1)) << 5;

    for (int kt = 0; kt < 16; kt++) {
        int cur = kt & 1;
        __syncthreads();                       // buf[nxt] consumers (tile kt-1) done
        if (kt < 15) issue_tile(kt + 1, 1 - cur);
        if (kt < 15) { asm volatile("cp.async.wait_group 1;\n" ::: "memory"); }
        else         { asm volatile("cp.async.wait_group 0;\n" ::: "memory"); }
        __syncthreads();                       // tile kt loads visible CTA-wide

        float* Ks = KsB + cur * KB_F;
        float* Vs = VsB + cur * VB_F;
        float* ckv = ckB + cur * 64;
        float* cbv = cbB + cur * 64;
        int k0 = kt * 64;

        // ---- scores S = Q @ K^T ----
        float sfr[8][4];
#pragma unroll
        for (int nf = 0; nf < 8; nf++)
#pragma unroll
            for (int r = 0; r < 4; r++) sfr[nf][r] = 0.f;
#pragma unroll
        for (int c = 0; c < 8; c++) {
#pragma unroll
            for (int nf = 0; nf < 8; nf++) {
                uint32_t bf[2];
                bf[0] = __float_as_uint(Ks[(nf * 8 + gr) * AKS + c * 8 + gc]);
                bf[1] = __float_as_uint(Ks[(nf * 8 + gr) * AKS + c * 8 + gc + 4]);
                MMA_TF32(sfr[nf], qf[c], bf);
            }
        }

        // ---- gate + mask ----
        unsigned w00 = g_pm[pmbase0 + (k0 >> 5)];
        unsigned w01 = g_pm[pmbase0 + (k0 >> 5) + 1];
        unsigned w10 = g_pm[pmbase1 + (k0 >> 5)];
        unsigned w11 = g_pm[pmbase1 + (k0 >> 5) + 1];
#pragma unroll
        for (int nf = 0; nf < 8; nf++) {
            int c0 = nf * 8 + (gc << 1);
            int c1 = c0 + 1;
            float lk0 = ckv[c0], lk1 = ckv[c1];
            float lb0 = cbv[c0], lb1 = cbv[c1];
            float g00 = __fdividef(1.f, 1.f + __expf(-fmaf(mq0, lk0, lb0)));
            float g01 = __fdividef(1.f, 1.f + __expf(-fmaf(mq0, lk1, lb1)));
            float g10 = __fdividef(1.f, 1.f + __expf(-fmaf(mq1, lk0, lb0)));
            float g11 = __fdividef(1.f, 1.f + __expf(-fmaf(mq1, lk1, lb1)));
            float v0 = sfr[nf][0] * 0.125f * g00;
            float v1 = sfr[nf][1] * 0.125f * g01;
            float v2 = sfr[nf][2] * 0.125f * g10;
            float v3 = sfr[nf][3] * 0.125f * g11;
            unsigned wa0 = (c0 < 32) ? w00 : w01;
            unsigned wa1 = (c1 < 32) ? w00 : w01;
            unsigned wb0 = (c0 < 32) ? w10 : w11;
            unsigned wb1 = (c1 < 32) ? w10 : w11;
            if (!((wa0 >> (c0 & 31)) & 1u)) v0 = -1e9f;
            if (!((wa1 >> (c1 & 31)) & 1u)) v1 = -1e9f;
            if (!((wb0 >> (c0 & 31)) & 1u)) v2 = -1e9f;
            if (!((wb1 >> (c1 & 31)) & 1u)) v3 = -1e9f;
            sfr[nf][0] = v0; sfr[nf][1] = v1; sfr[nf][2] = v2; sfr[nf][3] = v3;
        }

        // ---- online softmax ----
        float m0 = -INFINITY, m1 = -INFINITY;
#pragma unroll
        for (int nf = 0; nf < 8; nf++) {
            m0 = fmaxf(m0, fmaxf(sfr[nf][0], sfr[nf][1]));
            m1 = fmaxf(m1, fmaxf(sfr[nf][2], sfr[nf][3]));
        }
#pragma unroll
        for (int d = 1; d < 4; d <<= 1) {
            m0 = fmaxf(m0, __shfl_xor_sync(0xffffffffu, m0, d));
            m1 = fmaxf(m1, __shfl_xor_sync(0xffffffffu, m1, d));
        }
        float tm0 = fmaxf(rm0, m0);
        float tm1 = fmaxf(rm1, m1);
        float sc0 = __expf(rm0 - tm0);
        float sc1 = __expf(rm1 - tm1);
        rm0 = tm0; rm1 = tm1;
        float sum0 = 0.f, sum1 = 0.f;
#pragma unroll
        for (int nf = 0; nf < 8; nf++) {
            float p0 = __expf(sfr[nf][0] - tm0);
            float p1 = __expf(sfr[nf][1] - tm0);
            float p2 = __expf(sfr[nf][2] - tm1);
            float p3 = __expf(sfr[nf][3] - tm1);
            sum0 += p0 + p1;
            sum1 += p2 + p3;
            sfr[nf][0] = p0; sfr[nf][1] = p1; sfr[nf][2] = p2; sfr[nf][3] = p3;
        }
#pragma unroll
        for (int d = 1; d < 4; d <<= 1) {
            sum0 += __shfl_xor_sync(0xffffffffu, sum0, d);
            sum1 += __shfl_xor_sync(0xffffffffu, sum1, d);
        }
        rs0 = rs0 * sc0 + sum0;
        rs1 = rs1 * sc1 + sum1;
#pragma unroll
        for (int nf = 0; nf < 8; nf++) {
            ofr[nf][0] *= sc0; ofr[nf][1] *= sc0;
            ofr[nf][2] *= sc1; ofr[nf][3] *= sc1;
        }

        // ---- store P (warp-private rows, tf32-rounded) ----
#pragma unroll
        for (int nf = 0; nf < 8; nf++) {
            int c0 = nf * 8 + (gc << 1);
            *(float2*)&Ps[(wrow + gr) * AKS + c0] =
                make_float2(tf32r(sfr[nf][0]), tf32r(sfr[nf][1]));
            *(float2*)&Ps[(wrow + gr + 8) * AKS + c0] =
                make_float2(tf32r(sfr[nf][2]), tf32r(sfr[nf][3]));
        }
        __syncwarp();

        // ---- O += P @ V  (V as [k][e], stride 72 => conflict-free B frags) ----
#pragma unroll
        for (int c = 0; c < 8; c++) {
            uint32_t af[4];
            af[0] = __float_as_uint(Ps[(wrow + gr) * AKS + c * 8 + gc]);
            af[1] = __float_as_uint(Ps[(wrow + gr + 8) * AKS + c * 8 + gc]);
            af[2] = __float_as_uint(Ps[(wrow + gr) * AKS + c * 8 + gc + 4]);
            af[3] = __float_as_uint(Ps[(wrow + gr + 8) * AKS + c * 8 + gc + 4]);
#pragma unroll
            for (int nf = 0; nf < 8; nf++) {
                uint32_t bf[2];
                bf[0] = __float_as_uint(Vs[(c * 8 + gc) * AVS + nf * 8 + gr]);
                bf[1] = __float_as_uint(Vs[(c * 8 + gc + 4) * AVS + nf * 8 + gr]);
                MMA_TF32(ofr[nf], af, bf);
            }
        }
    }

    // ---- normalize + write (tf32-rounded for the out-proj GEMM) ----
    float inv0 = 1.f / rs0;
    float inv1 = 1.f / rs1;
#pragma unroll
    for (int nf = 0; nf < 8; nf++) {
        int c0 = (h << 6) + nf * 8 + (gc << 1);
        *(float2*)&g_x[(size_t)((b << 10) + qrow0) * DD + c0] =
            make_float2(tf32r(ofr[nf][0] * inv0), tf32r(ofr[nf][1] * inv0));
        *(float2*)&g_x[(size_t)((b << 10) + qrow1) * DD + c0] =
            make_float2(tf32r(ofr[nf][2] * inv1), tf32r(ofr[nf][3] * inv1));
    }
}

// ---------------- launch ------------------------------------------------------
extern "C" void kernel_launch(void* const* d_in, const int* in_sizes, int n_in,
                              void* d_out, int out_size) {
    const float* query = (const float*)d_in[0];
    const float* key   = (const float*)d_in[1];
    const float* value = (const float*)d_in[2];
    const int*   mask  = (const int*)d_in[3];
    const float* wq = (const float*)d_in[4];
    const float* bq = (const float*)d_in[5];
    const float* wk = (const float*)d_in[6];
    const float* bk = (const float*)d_in[7];
    const float* wv = (const float*)d_in[8];
    const float* bv = (const float*)d_in[9];
    const float* wo = (const float*)d_in[10];
    const float* bo = (const float*)d_in[11];
    const float* spatial_w = (const float*)d_in[12];
    const float* spatial_b = (const float*)d_in[13];
    const float* qproj_w = (const float*)d_in[14];
    const float* qproj_b = (const float*)d_in[15];
    const float* kproj_w = (const float*)d_in[16];
    const float* kproj_b = (const float*)d_in[17];
    const float* vlin_w = (const float*)d_in[18];
    const float* vlin_b = (const float*)d_in[19];
    const float* chan_w = (const float*)d_in[20];
    const float* chan_b = (const float*)d_in[21];
    float* out = (float*)d_out;

    float *p_wqf, *p_wkf, *p_wvf, *p_wof, *p_bqf, *p_bkf, *p_bvf;
    float *p_qs, *p_k2, *p_v2, *p_x, *p_aq, *p_ak, *p_av;
    cudaGetSymbolAddress((void**)&p_wqf, g_wqf);
    cudaGetSymbolAddress((void**)&p_wkf, g_wkf);
    cudaGetSymbolAddress((void**)&p_wvf, g_wvf);
    cudaGetSymbolAddress((void**)&p_wof, g_wof);
    cudaGetSymbolAddress((void**)&p_bqf, g_bqf);
    cudaGetSymbolAddress((void**)&p_bkf, g_bkf);
    cudaGetSymbolAddress((void**)&p_bvf, g_bvf);
    cudaGetSymbolAddress((void**)&p_qs, g_qs);
    cudaGetSymbolAddress((void**)&p_k2, g_k2);
    cudaGetSymbolAddress((void**)&p_v2, g_v2);
    cudaGetSymbolAddress((void**)&p_x, g_x);
    cudaGetSymbolAddress((void**)&p_aq, g_aq);
    cudaGetSymbolAddress((void**)&p_ak, g_ak);
    cudaGetSymbolAddress((void**)&p_av, g_av);

    cudaFuncSetAttribute(gemm_tf32<1>, cudaFuncAttributeMaxDynamicSharedMemorySize, GSM_BYTES);
    cudaFuncSetAttribute(gemm_tf32<0>, cudaFuncAttributeMaxDynamicSharedMemorySize, GSM_BYTES);
    cudaFuncSetAttribute(attn_tc_kernel, cudaFuncAttributeMaxDynamicSharedMemorySize, ASM_BYTES);

    // 1. fold small projections into big weights (tf32-rounded)
    fold_w_kernel<<<dim3(DD * DD / 256, 3), 256>>>(wq, wk, wv, spatial_w, kproj_w, vlin_w);
    // 2. biases / chan fold / qv / bmean
    small_prep_kernel<<<141, 256>>>(bq, bk, bv, spatial_w, kproj_w, vlin_w,
                                    spatial_b, kproj_b, vlin_b,
                                    wk, chan_w, chan_b, qproj_w, qproj_b);
    // 3. round wo; pack mask; ck/cb gate scalars (raw key)
    tf32_cvt_kernel<<<DD * DD / 1024, 256>>>(wo, p_wof);
    mask_pack_kernel<<<BB * SS * SS / 8 / 256, 256>>>(mask);
    ckcb_kernel<<<MM / 8, 256>>>(key);

    // 4. round all three activations
    tf32_cvt_kernel<<<MM * DD / 1024, 256>>>(query, p_aq);
    tf32_cvt_kernel<<<MM * DD / 1024, 256>>>(key, p_ak);
    tf32_cvt_kernel<<<MM * DD / 1024, 256>>>(value, p_av);

    // 5. merged QKV GEMM (z = 0,1,2) with fused ELU + tf32-rounded outputs
    GemmArgs gqkv;
    gqkv.A[0] = p_aq;  gqkv.A[1] = p_ak;  gqkv.A[2] = p_av;
    gqkv.B[0] = p_wqf; gqkv.B[1] = p_wkf; gqkv.B[2] = p_wvf;
    gqkv.bias[0] = p_bqf; gqkv.bias[1] = p_bkf; gqkv.bias[2] = p_bvf;
    gqkv.C[0] = p_qs;  gqkv.C[1] = p_k2;  gqkv.C[2] = p_v2;
    gemm_tf32<1><<<dim3(DD / 128, MM / 128, 3), 256, GSM_BYTES>>>(gqkv);

    // 6. tensor-core attention (cp.async pipeline, occ 2)
    attn_tc_kernel<<<dim3(SS / 64, HH, BB), 128, ASM_BYTES>>>();

    // 7. output projection
    GemmArgs go;
    go.A[0] = go.A[1] = go.A[2] = p_x;
    go.B[0] = go.B[1] = go.B[2] = p_wof;
    go.bias[0] = go.bias[1] = go.bias[2] = bo;
    go.C[0] = go.C[1] = go.C[2] = out;
    gemm_tf32<0><<<dim3(DD / 128, MM / 128, 1), 256, GSM_BYTES>>>(go);
}

// round 10
// speedup vs baseline: 4.0546x; 1.3042x over previous
#include <cuda_runtime.h>
#include <cuda_fp16.h>
#include <math.h>
#include <stdint.h>

#define BB 4
#define SS 1024
#define DD 1024
#define HH 16
#define DK 64
#define MM (BB * SS)   // 4096

// ---------------- scratch (device globals; no allocation allowed) -------------
__device__ uint32_t g_wqp[DD / 2 * DD];   // fp16 weights, k-pair packed [kp][n]
__device__ uint32_t g_wkp[DD / 2 * DD];
__device__ uint32_t g_wvp[DD / 2 * DD];
__device__ uint32_t g_wop[DD / 2 * DD];
__device__ float g_bqf[DD];
__device__ float g_bkf[DD];
__device__ float g_bvf[DD];
__device__ float g_wck[DD * HH];
__device__ float g_wcb[DD * HH];
__device__ float g_bck[HH];
__device__ float g_bcb[HH];
__device__ float g_qv[DK];
__device__ float g_bmean;
__device__ uint32_t g_aq[MM * DD / 2];    // fp16-packed activations
__device__ uint32_t g_ak[MM * DD / 2];
__device__ uint32_t g_av[MM * DD / 2];
__device__ uint32_t g_qs[MM * DD / 2];    // Q proj (fp16 packed)
__device__ uint32_t g_k2[MM * DD / 2];    // K proj (fp16 packed)
__device__ float g_v2[MM * DD];           // V proj (f32, tf32-rounded)
__device__ uint32_t g_xp[MM * DD / 2];    // attention out (fp16 packed)
__device__ float g_ck[MM * HH];
__device__ float g_cb[MM * HH];
__device__ unsigned g_pm[BB * SS * SS / 32];   // packed mask bits

__device__ __forceinline__ float tf32r(float x) {
    float y;
    asm("cvt.rna.tf32.f32 %0, %1;" : "=f"(y) : "f"(x));
    return y;
}
__device__ __forceinline__ uint32_t packh2(float a, float b) {
    __half2 h = __floats2half2_rn(a, b);
    return *(uint32_t*)&h;
}

#define MMA_TF32(d, a, b) \
    asm volatile("mma.sync.aligned.m16n8k8.row.col.f32.tf32.tf32.f32 " \
                 "{%0,%1,%2,%3},{%4,%5,%6,%7},{%8,%9},{%0,%1,%2,%3};" \
                 : "+f"(d[0]), "+f"(d[1]), "+f"(d[2]), "+f"(d[3]) \
                 : "r"(a[0]), "r"(a[1]), "r"(a[2]), "r"(a[3]), "r"(b[0]), "r"(b[1]));

#define MMA_F16(d, a, b) \
    asm volatile("mma.sync.aligned.m16n8k16.row.col.f32.f16.f16.f32 " \
                 "{%0,%1,%2,%3},{%4,%5,%6,%7},{%8,%9},{%0,%1,%2,%3};" \
                 : "+f"(d[0]), "+f"(d[1]), "+f"(d[2]), "+f"(d[3]) \
                 : "r"(a[0]), "r"(a[1]), "r"(a[2]), "r"(a[3]), "r"(b[0]), "r"(b[1]));

__device__ __forceinline__ void cpa16(void* dst, const void* src) {
    unsigned d = (unsigned)__cvta_generic_to_shared(dst);
    asm volatile("cp.async.cg.shared.global [%0], [%1], 16;\n" :: "r"(d), "l"(src));
}
__device__ __forceinline__ void cpa4(void* dst, const void* src) {
    unsigned d = (unsigned)__cvta_generic_to_shared(dst);
    asm volatile("cp.async.ca.shared.global [%0], [%1], 4;\n" :: "r"(d), "l"(src));
}

// ---------------- 0. f32 -> fp16x2 pack pass -----------------------------------
__global__ void h16_cvt_kernel(const float* __restrict__ in, uint32_t* __restrict__ out) {
    int i = blockIdx.x * 256 + threadIdx.x;
    float4 v = ((const float4*)in)[i];
    uint2 o;
    o.x = packh2(v.x, v.y);
    o.y = packh2(v.z, v.w);
    ((uint2*)out)[i] = o;
}

// ---------------- 0b. pack mask into bits ---------------------------------------
__global__ void mask_pack_kernel(const int* __restrict__ mask) {
    int t = blockIdx.x * 256 + threadIdx.x;
    const int4* p = (const int4*)mask + (size_t)t * 2;
    int4 a = p[0], b = p[1];
    unsigned byte = (unsigned)(a.x != 0) | ((unsigned)(a.y != 0) << 1)
                  | ((unsigned)(a.z != 0) << 2) | ((unsigned)(a.w != 0) << 3)
                  | ((unsigned)(b.x != 0) << 4) | ((unsigned)(b.y != 0) << 5)
                  | ((unsigned)(b.z != 0) << 6) | ((unsigned)(b.w != 0) << 7);
    ((unsigned char*)g_pm)[t] = (unsigned char)byte;
}

// ---------------- 1. fold projections -> fp16 k-pair-packed weights ------------
// O[k][n] = sum_e W[k, h*64+e] * P[e, ep];  word[kp][n] = (O[2kp][n], O[2kp+1][n])
__global__ void fold_w_kernel(const float* __restrict__ wq,
                              const float* __restrict__ wk,
                              const float* __restrict__ wv,
                              const float* __restrict__ sw,
                              const float* __restrict__ kp,
                              const float* __restrict__ vl) {
    int f = blockIdx.y;
    int idx = blockIdx.x * 256 + threadIdx.x;   // [0, 512*1024)
    int kp2 = idx >> 10;
    int n = idx & 1023;
    int h = n >> 6;
    int ep = n & 63;
    const float* W = (f == 0) ? wq : (f == 1) ? wk : wv;
    const float* P = (f == 0) ? sw : (f == 1) ? kp : vl;
    const float* w0 = W + (size_t)(2 * kp2) * DD + (h << 6);
    const float* w1 = w0 + DD;
    float s0 = 0.f, s1 = 0.f;
#pragma unroll 8
    for (int e = 0; e < DK; e++) {
        float pv = P[e * DK + ep];
        s0 = fmaf(w0[e], pv, s0);
        s1 = fmaf(w1[e], pv, s1);
    }
    uint32_t o = packh2(s0, s1);
    ((f == 0) ? g_wqp : (f == 1) ? g_wkp : g_wvp)[idx] = o;
}

// ---------------- 1b. wo -> fp16 k-pair-packed ----------------------------------
__global__ void wo_pack_kernel(const float* __restrict__ wo) {
    int idx = blockIdx.x * 256 + threadIdx.x;
    int kp2 = idx >> 10;
    int n = idx & 1023;
    float s0 = __ldg(&wo[(size_t)(2 * kp2) * DD + n]);
    float s1 = __ldg(&wo[(size_t)(2 * kp2 + 1) * DD + n]);
    g_wop[idx] = packh2(s0, s1);
}

// ---------------- 2. small precompute -------------------------------------------
__global__ void small_prep_kernel(const float* __restrict__ bq,
                                  const float* __restrict__ bk,
                                  const float* __restrict__ bv,
                                  const float* __restrict__ sw,
                                  const float* __restrict__ kp,
                                  const float* __restrict__ vl,
                                  const float* __restrict__ sb,
                                  const float* __restrict__ kpb,
                                  const float* __restrict__ vlb,
                                  const float* __restrict__ wk,
                                  const float* __restrict__ chan_w,
                                  const float* __restrict__ chan_b,
                                  const float* __restrict__ qproj_w,
                                  const float* __restrict__ qproj_b) {
    int T = blockIdx.x * 256 + threadIdx.x;
    if (T < 3072) {
        int f = T >> 10;
        int c = T & 1023;
        int h = c >> 6;
        int ep = c & 63;
        const float* b = (f == 0) ? bq : (f == 1) ? bk : bv;
        const float* P = (f == 0) ? sw : (f == 1) ? kp : vl;
        const float* pb = (f == 0) ? sb : (f == 1) ? kpb : vlb;
        float* O = (f == 0) ? g_bqf : (f == 1) ? g_bkf : g_bvf;
        float sum = pb[ep];
        for (int e = 0; e < DK; e++) sum += b[(h << 6) + e] * P[e * DK + ep];
        O[c] = sum;
        return;
    }
    T -= 3072;
    if (T < 16384) {
        int d = T >> 4, h = T & 15;
        float sum = 0.f;
        for (int e = 0; e < DK; e++) sum += wk[d * DD + (h << 6) + e] * chan_w[e];
        g_wck[d * HH + h] = sum;
        return;
    }
    T -= 16384;
    if (T < 16384) {
        int d = T >> 4, h = T & 15;
        float sum = 0.f;
        for (int e = 0; e < DK; e++) sum += wk[d * DD + (h << 6) + e] * chan_b[e];
        g_wcb[d * HH + h] = sum;
        return;
    }
    T -= 16384;
    if (T < 16) {
        float sum = 0.f;
        for (int e = 0; e < DK; e++) sum += bk[(T << 6) + e] * chan_w[e];
        g_bck[T] = sum;
        return;
    }
    T -= 16;
    if (T < 16) {
        float sum = 0.f;
        for (int e = 0; e < DK; e++) sum += bk[(T << 6) + e] * chan_b[e];
        g_bcb[T] = sum;
        return;
    }
    T -= 16;
    if (T < 64) {
        float sum = 0.f;
        for (int ep = 0; ep < DK; ep++) sum += qproj_w[T * DK + ep];
        g_qv[T] = sum * (1.f / 64.f);
        return;
    }
    T -= 64;
    if (T == 0) {
        float sum = 0.f;
        for (int ep = 0; ep < DK; ep++) sum += qproj_b[ep];
        g_bmean = sum * (1.f / 64.f);
    }
}

// ---------------- 3. fp16 tensor-core GEMM: C = act(A @ W + bias) ---------------
// A [M, K/2] u32 (fp16 k-pairs), W [K/2, N] u32 (fp16 k-pairs).
// 128x128 tile, 16 kp (=32 k) per stage, 3-stage cp.async, m16n8k16 fp16 MMA.
// mode: 0 = f32 out, 1 = elu + tf32-round f32 out, 2 = elu + fp16-pack out.
#define GSTAGES 3
#define GBKP 16
#define ASTP 20
#define BSTP 136
#define ASZP (128 * ASTP)
#define BSZP (GBKP * BSTP)
#define GSM_BYTES (GSTAGES * (ASZP + BSZP) * 4)   // 56832

struct GemmArgs {
    const uint32_t* A[3];
    const uint32_t* B[3];
    const float* bias[3];
    void* C[3];
    int mode[3];
};

__device__ __forceinline__ void gemm_load_stage(uint32_t* As, uint32_t* Bs,
                                                const uint32_t* A, const uint32_t* Bm,
                                                int brow, int bcol, int kt, int tid) {
#pragma unroll
    for (int l = 0; l < 2; l++) {
        int lin = tid + l * 256;
        int row = lin >> 2, c4 = (lin & 3) << 2;
        cpa16(&As[row * ASTP + c4], &A[(size_t)(brow + row) * (DD / 2) + kt * GBKP + c4]);
    }
#pragma unroll
    for (int l = 0; l < 2; l++) {
        int lin = tid + l * 256;
        int kr = lin >> 5, c4 = (lin & 31) << 2;
        cpa16(&Bs[kr * BSTP + c4], &Bm[(size_t)(kt * GBKP + kr) * DD + bcol + c4]);
    }
}

__global__ void __launch_bounds__(256, 2)
gemm_f16(GemmArgs ga) {
    extern __shared__ uint32_t smem_u[];
    uint32_t* Asm = smem_u;
    uint32_t* Bsm = smem_u + GSTAGES * ASZP;

    int z = blockIdx.z;
    const uint32_t* A = ga.A[z];
    const uint32_t* Bm = ga.B[z];
    const float* bias = ga.bias[z];
    int mode = ga.mode[z];

    int tid = threadIdx.x;
    int brow = blockIdx.y * 128;
    int bcol = blockIdx.x * 128;
    int warp = tid >> 5;
    int lane = tid & 31;
    int gr = lane >> 2;
    int gc = lane & 3;
    int wrow = (warp >> 2) * 64;
    int wcol = (warp & 3) * 32;

    float acc[4][4][4];
#pragma unroll
    for (int mt = 0; mt < 4; mt++)
#pragma unroll
        for (int nt = 0; nt < 4; nt++)
#pragma unroll
            for (int r = 0; r < 4; r++) acc[mt][nt][r] = 0.f;

    const int KT = (DD / 2) / GBKP;   // 32
    gemm_load_stage(Asm, Bsm, A, Bm, brow, bcol, 0, tid);
    asm volatile("cp.async.commit_group;\n");
    gemm_load_stage(Asm + ASZP, Bsm + BSZP, A, Bm, brow, bcol, 1, tid);
    asm volatile("cp.async.commit_group;\n");

    int s0 = 0, s1 = 1, s2 = 2;
    for (int kt = 0; kt < KT; kt++) {
        asm volatile("cp.async.wait_group 1;\n" ::: "memory");
        __syncthreads();
        uint32_t* As = Asm + s0 * ASZP;
        uint32_t* Bs = Bsm + s0 * BSZP;
#pragma unroll
        for (int c2 = 0; c2 < 2; c2++) {
            int kpb = c2 * 8;
            uint32_t af[4][4], bf[4][2];
#pragma unroll
            for (int mt = 0; mt < 4; mt++) {
                int row0 = wrow + mt * 16 + gr;
                af[mt][0] = As[row0 * ASTP + kpb + gc];
                af[mt][1] = As[(row0 + 8) * ASTP + kpb + gc];
                af[mt][2] = As[row0 * ASTP + kpb + gc + 4];
                af[mt][3] = As[(row0 + 8) * ASTP + kpb + gc + 4];
            }
#pragma unroll
            for (int nt = 0; nt < 4; nt++) {
                int col0 = wcol + nt * 8 + gr;
                bf[nt][0] = Bs[(kpb + gc) * BSTP + col0];
                bf[nt][1] = Bs[(kpb + gc + 4) * BSTP + col0];
            }
#pragma unroll
            for (int mt = 0; mt < 4; mt++)
#pragma unroll
                for (int nt = 0; nt < 4; nt++)
                    MMA_F16(acc[mt][nt], af[mt], bf[nt]);
        }
        int nk = kt + 2;
        if (nk < KT)
            gemm_load_stage(Asm + s2 * ASZP, Bsm + s2 * BSZP, A, Bm, brow, bcol, nk, tid);
        asm volatile("cp.async.commit_group;\n");
        int t = s0; s0 = s1; s1 = s2; s2 = t;
    }

    // epilogue
#pragma unroll
    for (int mt = 0; mt < 4; mt++) {
        int r0 = brow + wrow + mt * 16 + gr;
#pragma unroll
        for (int nt = 0; nt < 4; nt++) {
            int c0 = bcol + wcol + nt * 8 + (gc << 1);
            float b0 = bias[c0], b1 = bias[c0 + 1];
            float v0 = acc[mt][nt][0] + b0;
            float v1 = acc[mt][nt][1] + b1;
            float v2 = acc[mt][nt][2] + b0;
            float v3 = acc[mt][nt][3] + b1;
            if (mode >= 1) {
                v0 = v0 > 0.f ? v0 : (__expf(v0) - 1.f);
                v1 = v1 > 0.f ? v1 : (__expf(v1) - 1.f);
                v2 = v2 > 0.f ? v2 : (__expf(v2) - 1.f);
                v3 = v3 > 0.f ? v3 : (__expf(v3) - 1.f);
            }
            if (mode == 2) {
                uint32_t* Cw = (uint32_t*)ga.C[z];
                Cw[(size_t)r0 * (DD / 2) + (c0 >> 1)] = packh2(v0, v1);
                Cw[(size_t)(r0 + 8) * (DD / 2) + (c0 >> 1)] = packh2(v2, v3);
            } else {
                if (mode == 1) { v0 = tf32r(v0); v1 = tf32r(v1); v2 = tf32r(v2); v3 = tf32r(v3); }
                float* Cf = (float*)ga.C[z];
                *(float2*)&Cf[(size_t)r0 * DD + c0] = make_float2(v0, v1);
                *(float2*)&Cf[(size_t)(r0 + 8) * DD + c0] = make_float2(v2, v3);
            }
        }
    }
}

// ---------------- 4. ck/cb skinny GEMV ------------------------------------------
__global__ void ckcb_kernel(const float* __restrict__ key) {
    __shared__ float rows[8][1024];
    int tid = threadIdx.x;
    int row0 = blockIdx.x * 8;
#pragma unroll
    for (int l = 0; l < 8; l++) {
        int lin = tid + l * 256;
        int r = lin >> 8;
        int c4 = (lin & 255) << 2;
        *(float4*)&rows[r][c4] = *(const float4*)&key[(size_t)(row0 + r) * DD + c4];
    }
    __syncthreads();
    int r = tid >> 5;
    int o = tid & 31;
    int h = o & 15;
    int isB = o >> 4;
    const float* wp = isB ? g_wcb : g_wck;
    float sum = isB ? g_bcb[h] : g_bck[h];
#pragma unroll 8
    for (int d = 0; d < DD; d++) sum += rows[r][d] * wp[d * HH + h];
    (isB ? g_cb : g_ck)[(size_t)(row0 + r) * HH + h] = sum;
}

// ---------------- 5. flash attention: fp16 QK^T, tf32 PV, cp.async, occ 2 -------
// CTA: 64 q-rows x (b,h). 4 warps x 16 q-rows. K-tiles of 64, 2-buffer cp.async.
// Q/K fp16 packed [row][ep], smem stride 36 u32 (=4 mod 32, conflict-free frags).
// V f32 [key][e] stride 72 (=8 mod 32). P f32 stride 68.
#define AKS 36     // u32 stride for Q/K
#define AVS 72     // f32 stride for V
#define APS 68     // f32 stride for P
#define PS_F (64 * APS)
#define QH_U (64 * AKS)
#define KB_U (64 * AKS)
#define VB_F (64 * AVS)
#define ASM_BYTES ((PS_F + QH_U + 2 * KB_U + 2 * VB_F + 256) * 4)   // 82944

__global__ void __launch_bounds__(128, 2) attn_tc_kernel() {
    extern __shared__ float sm[];
    float* Ps = sm;
    uint32_t* Qh = (uint32_t*)(sm + PS_F);
    uint32_t* KsB = Qh + QH_U;
    float* VsB = (float*)(KsB + 2 * KB_U);
    float* ckB = VsB + 2 * VB_F;
    float* cbB = ckB + 128;

    int tid = threadIdx.x;
    int q0 = blockIdx.x * 64;
    int h = blockIdx.y;
    int b = blockIdx.z;
    int warp = tid >> 5;
    int lane = tid & 31;
    int gr = lane >> 2;
    int gc = lane & 3;
    int wrow = warp * 16;

    // issue Q staging (group 0): 64 rows x 32 u32
#pragma unroll
    for (int l = 0; l < 4; l++) {
        int lin = tid + l * 128;
        int r = lin >> 3;
        int c4 = (lin & 7) << 2;
        cpa16(&Qh[r * AKS + c4],
              &g_qs[(size_t)((b << 10) + q0 + r) * (DD / 2) + (h << 5) + c4]);
    }
    asm volatile("cp.async.commit_group;\n");

    auto issue_tile = [&](int kt, int buf) {
        int k0 = kt * 64;
        uint32_t* Ks = KsB + buf * KB_U;
        float* Vs = VsB + buf * VB_F;
#pragma unroll
        for (int l = 0; l < 4; l++) {
            int lin = tid + l * 128;
            int r = lin >> 3;
            int c4 = (lin & 7) << 2;
            cpa16(&Ks[r * AKS + c4],
                  &g_k2[(size_t)((b << 10) + k0 + r) * (DD / 2) + (h << 5) + c4]);
        }
#pragma unroll
        for (int l = 0; l < 8; l++) {
            int lin = tid + l * 128;
            int r = lin >> 4;
            int e4 = (lin & 15) << 2;
            cpa16(&Vs[r * AVS + e4],
                  &g_v2[(size_t)((b << 10) + k0 + r) * DD + (h << 6) + e4]);
        }
        if (tid < 64) {
            cpa4(&ckB[buf * 64 + tid], &g_ck[(size_t)((b << 10) + k0 + tid) * HH + h]);
            cpa4(&cbB[buf * 64 + tid], &g_cb[(size_t)((b << 10) + k0 + tid) * HH + h]);
        }
        asm volatile("cp.async.commit_group;\n");
    };
    issue_tile(0, 0);

    asm volatile("cp.async.wait_group 1;\n" ::: "memory");
    __syncthreads();

    // Q fragments (fp16, 4 k16-chunks x 4 regs)
    uint32_t qf[4][4];
#pragma unroll
    for (int c = 0; c < 4; c++) {
        qf[c][0] = Qh[(wrow + gr) * AKS + c * 8 + gc];
        qf[c][1] = Qh[(wrow + gr + 8) * AKS + c * 8 + gc];
        qf[c][2] = Qh[(wrow + gr) * AKS + c * 8 + gc + 4];
        qf[c][3] = Qh[(wrow + gr + 8) * AKS + c * 8 + gc + 4];
    }
    // inline per-row gate scalar m = Q_row . qv + bmean
    const __half* q0h = (const __half*)(Qh + (wrow + gr) * AKS);
    const __half* q1h = (const __half*)(Qh + (wrow + gr + 8) * AKS);
    float a0 = 0.f, a1 = 0.f;
#pragma unroll
    for (int e16 = 0; e16 < 16; e16++) {
        int e = gc * 16 + e16;
        float qv = __ldg(&g_qv[e]);
        a0 = fmaf(__half2float(q0h[e]), qv, a0);
        a1 = fmaf(__half2float(q1h[e]), qv, a1);
    }
#pragma unroll
    for (int d = 1; d < 4; d <<= 1) {
        a0 += __shfl_xor_sync(0xffffffffu, a0, d);
        a1 += __shfl_xor_sync(0xffffffffu, a1, d);
    }
    float bmean = g_bmean;
    float mq0 = a0 + bmean;
    float mq1 = a1 + bmean;

    int qrow0 = q0 + wrow + gr;
    int qrow1 = qrow0 + 8;
    float rm0 = -INFINITY, rm1 = -INFINITY, rs0 = 0.f, rs1 = 0.f;
    float ofr[8][4];
#pragma unroll
    for (int nf = 0; nf < 8; nf++)
#pragma unroll
        for (int r = 0; r < 4; r++) ofr[nf][r] = 0.f;

    unsigned pmbase0 = ((unsigned)((b << 10) + qrow0)) << 5;
    unsigned pmbase1 = ((unsigned)((b << 10) + qrow1)) << 5;

    for (int kt = 0; kt < 16; kt++) {
        int cur = kt & 1;
        __syncthreads();
        if (kt < 15) issue_tile(kt + 1, 1 - cur);
        if (kt < 15) { asm volatile("cp.async.wait_group 1;\n" ::: "memory"); }
        else         { asm volatile("cp.async.wait_group 0;\n" ::: "memory"); }
        __syncthreads();

        uint32_t* Ks = KsB + cur * KB_U;
        float* Vs = VsB + cur * VB_F;
        float* ckv = ckB + cur * 64;
        float* cbv = cbB + cur * 64;
        int k0 = kt * 64;

        // ---- scores S = Q @ K^T (fp16 m16n8k16) ----
        float sfr[8][4];
#pragma unroll
        for (int nf = 0; nf < 8; nf++)
#pragma unroll
            for (int r = 0; r < 4; r++) sfr[nf][r] = 0.f;
#pragma unroll
        for (int c = 0; c < 4; c++) {
#pragma unroll
            for (int nf = 0; nf < 8; nf++) {
                uint32_t bf[2];
                bf[0] = Ks[(nf * 8 + gr) * AKS + c * 8 + gc];
                bf[1] = Ks[(nf * 8 + gr) * AKS + c * 8 + gc + 4];
                MMA_F16(sfr[nf], qf[c], bf);
            }
        }

        // ---- gate + mask ----
        unsigned w00 = g_pm[pmbase0 + (k0 >> 5)];
        unsigned w01 = g_pm[pmbase0 + (k0 >> 5) + 1];
        unsigned w10 = g_pm[pmbase1 + (k0 >> 5)];
        unsigned w11 = g_pm[pmbase1 + (k0 >> 5) + 1];
#pragma unroll
        for (int nf = 0; nf < 8; nf++) {
            int c0 = nf * 8 + (gc << 1);
            int c1 = c0 + 1;
            float lk0 = ckv[c0], lk1 = ckv[c1];
            float lb0 = cbv[c0], lb1 = cbv[c1];
            float g00 = __fdividef(1.f, 1.f + __expf(-fmaf(mq0, lk0, lb0)));
            float g01 = __fdividef(1.f, 1.f + __expf(-fmaf(mq0, lk1, lb1)));
            float g10 = __fdividef(1.f, 1.f + __expf(-fmaf(mq1, lk0, lb0)));
            float g11 = __fdividef(1.f, 1.f + __expf(-fmaf(mq1, lk1, lb1)));
            float v0 = sfr[nf][0] * 0.125f * g00;
            float v1 = sfr[nf][1] * 0.125f * g01;
            float v2 = sfr[nf][2] * 0.125f * g10;
            float v3 = sfr[nf][3] * 0.125f * g11;
            unsigned wa0 = (c0 < 32) ? w00 : w01;
            unsigned wa1 = (c1 < 32) ? w00 : w01;
            unsigned wb0 = (c0 < 32) ? w10 : w11;
            unsigned wb1 = (c1 < 32) ? w10 : w11;
            if (!((wa0 >> (c0 & 31)) & 1u)) v0 = -1e9f;
            if (!((wa1 >> (c1 & 31)) & 1u)) v1 = -1e9f;
            if (!((wb0 >> (c0 & 31)) & 1u)) v2 = -1e9f;
            if (!((wb1 >> (c1 & 31)) & 1u)) v3 = -1e9f;
            sfr[nf][0] = v0; sfr[nf][1] = v1; sfr[nf][2] = v2; sfr[nf][3] = v3;
        }

        // ---- online softmax ----
        float m0 = -INFINITY, m1 = -INFINITY;
#pragma unroll
        for (int nf = 0; nf < 8; nf++) {
            m0 = fmaxf(m0, fmaxf(sfr[nf][0], sfr[nf][1]));
            m1 = fmaxf(m1, fmaxf(sfr[nf][2], sfr[nf][3]));
        }
#pragma unroll
        for (int d = 1; d < 4; d <<= 1) {
            m0 = fmaxf(m0, __shfl_xor_sync(0xffffffffu, m0, d));
            m1 = fmaxf(m1, __shfl_xor_sync(0xffffffffu, m1, d));
        }
        float tm0 = fmaxf(rm0, m0);
        float tm1 = fmaxf(rm1, m1);
        float sc0 = __expf(rm0 - tm0);
        float sc1 = __expf(rm1 - tm1);
        rm0 = tm0; rm1 = tm1;
        float sum0 = 0.f, sum1 = 0.f;
#pragma unroll
        for (int nf = 0; nf < 8; nf++) {
            float p0 = __expf(sfr[nf][0] - tm0);
            float p1 = __expf(sfr[nf][1] - tm0);
            float p2 = __expf(sfr[nf][2] - tm1);
            float p3 = __expf(sfr[nf][3] - tm1);
            sum0 += p0 + p1;
            sum1 += p2 + p3;
            sfr[nf][0] = p0; sfr[nf][1] = p1; sfr[nf][2] = p2; sfr[nf][3] = p3;
        }
#pragma unroll
        for (int d = 1; d < 4; d <<= 1) {
            sum0 += __shfl_xor_sync(0xffffffffu, sum0, d);
            sum1 += __shfl_xor_sync(0xffffffffu, sum1, d);
        }
        rs0 = rs0 * sc0 + sum0;
        rs1 = rs1 * sc1 + sum1;
#pragma unroll
        for (int nf = 0; nf < 8; nf++) {
            ofr[nf][0] *= sc0; ofr[nf][1] *= sc0;
            ofr[nf][2] *= sc1; ofr[nf][3] *= sc1;
        }

        // ---- store P (warp-private rows, tf32-rounded, f32) ----
#pragma unroll
        for (int nf = 0; nf < 8; nf++) {
            int c0 = nf * 8 + (gc << 1);
            *(float2*)&Ps[(wrow + gr) * APS + c0] =
                make_float2(tf32r(sfr[nf][0]), tf32r(sfr[nf][1]));
            *(float2*)&Ps[(wrow + gr + 8) * APS + c0] =
                make_float2(tf32r(sfr[nf][2]), tf32r(sfr[nf][3]));
        }
        __syncwarp();

        // ---- O += P @ V (tf32; V [k][e] stride 72, conflict-free B frags) ----
#pragma unroll
        for (int c = 0; c < 8; c++) {
            uint32_t af[4];
            af[0] = __float_as_uint(Ps[(wrow + gr) * APS + c * 8 + gc]);
            af[1] = __float_as_uint(Ps[(wrow + gr + 8) * APS + c * 8 + gc]);
            af[2] = __float_as_uint(Ps[(wrow + gr) * APS + c * 8 + gc + 4]);
            af[3] = __float_as_uint(Ps[(wrow + gr + 8) * APS + c * 8 + gc + 4]);
#pragma unroll
            for (int nf = 0; nf < 8; nf++) {
                uint32_t bf[2];
                bf[0] = __float_as_uint(Vs[(c * 8 + gc) * AVS + nf * 8 + gr]);
                bf[1] = __float_as_uint(Vs[(c * 8 + gc + 4) * AVS + nf * 8 + gr]);
                MMA_TF32(ofr[nf], af, bf);
            }
        }
    }

    // ---- normalize + write fp16-packed (feeds fp16 out-projection) ----
    float inv0 = 1.f / rs0;
    float inv1 = 1.f / rs1;
#pragma unroll
    for (int nf = 0; nf < 8; nf++) {
        int c0 = (h << 6) + nf * 8 + (gc << 1);
        g_xp[(size_t)((b << 10) + qrow0) * (DD / 2) + (c0 >> 1)] =
            packh2(ofr[nf][0] * inv0, ofr[nf][1] * inv0);
        g_xp[(size_t)((b << 10) + qrow1) * (DD / 2) + (c0 >> 1)] =
            packh2(ofr[nf][2] * inv1, ofr[nf][3] * inv1);
    }
}

// ---------------- launch --------------------------------------------------------
extern "C" void kernel_launch(void* const* d_in, const int* in_sizes, int n_in,
                              void* d_out, int out_size) {
    const float* query = (const float*)d_in[0];
    const float* key   = (const float*)d_in[1];
    const float* value = (const float*)d_in[2];
    const int*   mask  = (const int*)d_in[3];
    const float* wq = (const float*)d_in[4];
    const float* bq = (const float*)d_in[5];
    const float* wk = (const float*)d_in[6];
    const float* bk = (const float*)d_in[7];
    const float* wv = (const float*)d_in[8];
    const float* bv = (const float*)d_in[9];
    const float* wo = (const float*)d_in[10];
    const float* bo = (const float*)d_in[11];
    const float* spatial_w = (const float*)d_in[12];
    const float* spatial_b = (const float*)d_in[13];
    const float* qproj_w = (const float*)d_in[14];
    const float* qproj_b = (const float*)d_in[15];
    const float* kproj_w = (const float*)d_in[16];
    const float* kproj_b = (const float*)d_in[17];
    const float* vlin_w = (const float*)d_in[18];
    const float* vlin_b = (const float*)d_in[19];
    const float* chan_w = (const float*)d_in[20];
    const float* chan_b = (const float*)d_in[21];
    float* out = (float*)d_out;

    float *p_bqf, *p_bkf, *p_bvf, *p_v2;
    uint32_t *p_wqp, *p_wkp, *p_wvp, *p_wop, *p_aq, *p_ak, *p_av, *p_qs, *p_k2, *p_xp;
    cudaGetSymbolAddress((void**)&p_bqf, g_bqf);
    cudaGetSymbolAddress((void**)&p_bkf, g_bkf);
    cudaGetSymbolAddress((void**)&p_bvf, g_bvf);
    cudaGetSymbolAddress((void**)&p_v2, g_v2);
    cudaGetSymbolAddress((void**)&p_wqp, g_wqp);
    cudaGetSymbolAddress((void**)&p_wkp, g_wkp);
    cudaGetSymbolAddress((void**)&p_wvp, g_wvp);
    cudaGetSymbolAddress((void**)&p_wop, g_wop);
    cudaGetSymbolAddress((void**)&p_aq, g_aq);
    cudaGetSymbolAddress((void**)&p_ak, g_ak);
    cudaGetSymbolAddress((void**)&p_av, g_av);
    cudaGetSymbolAddress((void**)&p_qs, g_qs);
    cudaGetSymbolAddress((void**)&p_k2, g_k2);
    cudaGetSymbolAddress((void**)&p_xp, g_xp);

    cudaFuncSetAttribute(gemm_f16, cudaFuncAttributeMaxDynamicSharedMemorySize, GSM_BYTES);
    cudaFuncSetAttribute(attn_tc_kernel, cudaFuncAttributeMaxDynamicSharedMemorySize, ASM_BYTES);

    // 1. fold small projections into fp16 packed weights
    fold_w_kernel<<<dim3(DD / 2 * DD / 256, 3), 256>>>(wq, wk, wv, spatial_w, kproj_w, vlin_w);
    // 2. biases / chan fold / qv / bmean
    small_prep_kernel<<<141, 256>>>(bq, bk, bv, spatial_w, kproj_w, vlin_w,
                                    spatial_b, kproj_b, vlin_b,
                                    wk, chan_w, chan_b, qproj_w, qproj_b);
    // 3. pack wo; pack mask; ck/cb gate scalars (raw key)
    wo_pack_kernel<<<DD / 2 * DD / 256, 256>>>(wo);
    mask_pack_kernel<<<BB * SS * SS / 8 / 256, 256>>>(mask);
    ckcb_kernel<<<MM / 8, 256>>>(key);

    // 4. pack all three activations to fp16
    h16_cvt_kernel<<<MM * DD / 1024, 256>>>(query, p_aq);
    h16_cvt_kernel<<<MM * DD / 1024, 256>>>(key, p_ak);
    h16_cvt_kernel<<<MM * DD / 1024, 256>>>(value, p_av);

    // 5. merged QKV fp16 GEMM: Q,K out fp16; V out f32+tf32r (all with ELU)
    GemmArgs gqkv;
    gqkv.A[0] = p_aq;  gqkv.A[1] = p_ak;  gqkv.A[2] = p_av;
    gqkv.B[0] = p_wqp; gqkv.B[1] = p_wkp; gqkv.B[2] = p_wvp;
    gqkv.bias[0] = p_bqf; gqkv.bias[1] = p_bkf; gqkv.bias[2] = p_bvf;
    gqkv.C[0] = p_qs;  gqkv.C[1] = p_k2;  gqkv.C[2] = p_v2;
    gqkv.mode[0] = 2;  gqkv.mode[1] = 2;  gqkv.mode[2] = 1;
    gemm_f16<<<dim3(DD / 128, MM / 128, 3), 256, GSM_BYTES>>>(gqkv);

    // 6. attention: fp16 QK^T + tf32 PV (occ 2, cp.async)
    attn_tc_kernel<<<dim3(SS / 64, HH, BB), 128, ASM_BYTES>>>();

    // 7. fp16 output projection
    GemmArgs go;
    go.A[0] = go.A[1] = go.A[2] = p_xp;
    go.B[0] = go.B[1] = go.B[2] = p_wop;
    go.bias[0] = go.bias[1] = go.bias[2] = bo;
    go.C[0] = go.C[1] = go.C[2] = out;
    go.mode[0] = go.mode[1] = go.mode[2] = 0;
    gemm_f16<<<dim3(DD / 128, MM / 128, 1), 256, GSM_BYTES>>>(go);
}

// round 12
// speedup vs baseline: 4.2932x; 1.0589x over previous
#include <cuda_runtime.h>
#include <cuda_fp16.h>
#include <math.h>
#include <stdint.h>

#define BB 4
#define SS 1024
#define DD 1024
#define HH 16
#define DK 64
#define MM (BB * SS)   // 4096

// ---------------- scratch (device globals; no allocation allowed) -------------
__device__ uint32_t g_wqp[DD / 2 * DD];    // fp16 weights, k-pair packed [kp][n]
__device__ uint32_t g_wkp[DD / 2 * DD];
__device__ uint32_t g_wvt[DD * DD / 2];    // V weights TRANSPOSED [e][dp]
__device__ uint32_t g_wop[DD / 2 * DD];
__device__ float g_bqf[DD];
__device__ float g_bkf[DD];
__device__ float g_bvf[DD];
__device__ float g_wck[DD * HH];
__device__ float g_wcb[DD * HH];
__device__ float g_bck[HH];
__device__ float g_bcb[HH];
__device__ float g_qv[DK];
__device__ float g_bmean;
__device__ uint32_t g_aq[MM * DD / 2];     // fp16-packed query activations
__device__ uint32_t g_ak[MM * DD / 2];     // fp16-packed key activations
__device__ uint32_t g_avt[DD / 2 * MM];    // value TRANSPOSED fp16 d-pair packed [dp][row]
__device__ uint32_t g_qs[MM * DD / 2];     // Q proj (fp16 packed)
__device__ uint32_t g_k2[MM * DD / 2];     // K proj (fp16 packed)
__device__ uint32_t g_v2t[DD * MM / 2];    // V proj TRANSPOSED key-pair packed [e][kp]
__device__ uint32_t g_xp[MM * DD / 2];     // attention out (fp16 packed)
__device__ float g_ck[MM * HH];
__device__ float g_cb[MM * HH];
__device__ unsigned g_pm[BB * SS * SS / 32];

__device__ __forceinline__ uint32_t packh2(float a, float b) {
    __half2 h = __floats2half2_rn(a, b);
    return *(uint32_t*)&h;
}

#define MMA_F16(d, a, b) \
    asm volatile("mma.sync.aligned.m16n8k16.row.col.f32.f16.f16.f32 " \
                 "{%0,%1,%2,%3},{%4,%5,%6,%7},{%8,%9},{%0,%1,%2,%3};" \
                 : "+f"(d[0]), "+f"(d[1]), "+f"(d[2]), "+f"(d[3]) \
                 : "r"(a[0]), "r"(a[1]), "r"(a[2]), "r"(a[3]), "r"(b[0]), "r"(b[1]));

__device__ __forceinline__ void cpa16(void* dst, const void* src) {
    unsigned d = (unsigned)__cvta_generic_to_shared(dst);
    asm volatile("cp.async.cg.shared.global [%0], [%1], 16;\n" :: "r"(d), "l"(src));
}
__device__ __forceinline__ void cpa4(void* dst, const void* src) {
    unsigned d = (unsigned)__cvta_generic_to_shared(dst);
    asm volatile("cp.async.ca.shared.global [%0], [%1], 4;\n" :: "r"(d), "l"(src));
}

// ---------------- 1. mega prep kernel (all independent prep in one launch) -----
// blocks [0,2048) fold Q; [2048,4096) fold K; [4096,6144) fold V transposed;
// [6144,8192) wo_pack; [8192,10240) mask_pack; [10240,14336) cvt query;
// [14336,18432) cvt key; [18432,20480) value transpose; [20480,20621) small prep
__global__ void __launch_bounds__(256)
mega_prep(const float* __restrict__ query, const float* __restrict__ key,
          const float* __restrict__ value, const int* __restrict__ mask,
          const float* __restrict__ wq, const float* __restrict__ bq,
          const float* __restrict__ wk, const float* __restrict__ bk,
          const float* __restrict__ wv, const float* __restrict__ bv,
          const float* __restrict__ wo,
          const float* __restrict__ sw, const float* __restrict__ sb,
          const float* __restrict__ qpw, const float* __restrict__ qpb,
          const float* __restrict__ kpw, const float* __restrict__ kpb,
          const float* __restrict__ vlw, const float* __restrict__ vlb,
          const float* __restrict__ chan_w, const float* __restrict__ chan_b) {
    __shared__ float ts[64][33];
    int bid = blockIdx.x;
    int tid = threadIdx.x;

    if (bid < 6144) {                       // fold projections
        int f = bid >> 11;
        int idx = (bid & 2047) * 256 + tid;
        int kp2 = idx >> 10;
        int n = idx & 1023;
        int h = n >> 6;
        int ep = n & 63;
        const float* W = (f == 0) ? wq : (f == 1) ? wk : wv;
        const float* P = (f == 0) ? sw : (f == 1) ? kpw : vlw;
        const float* w0 = W + (size_t)(2 * kp2) * DD + (h << 6);
        const float* w1 = w0 + DD;
        float s0 = 0.f, s1 = 0.f;
#pragma unroll 8
        for (int e = 0; e < DK; e++) {
            float pv = P[e * DK + ep];
            s0 = fmaf(w0[e], pv, s0);
            s1 = fmaf(w1[e], pv, s1);
        }
        uint32_t o = packh2(s0, s1);
        if (f == 0) g_wqp[idx] = o;
        else if (f == 1) g_wkp[idx] = o;
        else g_wvt[(size_t)n * (DD / 2) + kp2] = o;   // transposed [e][dp]
        return;
    }
    if (bid < 8192) {                       // wo pack
        int idx = (bid - 6144) * 256 + tid;
        int kp2 = idx >> 10;
        int n = idx & 1023;
        float s0 = __ldg(&wo[(size_t)(2 * kp2) * DD + n]);
        float s1 = __ldg(&wo[(size_t)(2 * kp2 + 1) * DD + n]);
        g_wop[idx] = packh2(s0, s1);
        return;
    }
    if (bid < 10240) {                      // mask pack
        int t = (bid - 8192) * 256 + tid;
        const int4* p = (const int4*)mask + (size_t)t * 2;
        int4 a = p[0], b = p[1];
        unsigned byte = (unsigned)(a.x != 0) | ((unsigned)(a.y != 0) << 1)
                      | ((unsigned)(a.z != 0) << 2) | ((unsigned)(a.w != 0) << 3)
                      | ((unsigned)(b.x != 0) << 4) | ((unsigned)(b.y != 0) << 5)
                      | ((unsigned)(b.z != 0) << 6) | ((unsigned)(b.w != 0) << 7);
        ((unsigned char*)g_pm)[t] = (unsigned char)byte;
        return;
    }
    if (bid < 18432) {                      // cvt query / key to fp16 pairs
        int isK = bid >= 14336;
        int i = (bid - (isK ? 14336 : 10240)) * 256 + tid;
        const float* in = isK ? key : query;
        uint32_t* out = isK ? g_ak : g_aq;
        float4 v = ((const float4*)in)[i];
        uint2 o;
        o.x = packh2(v.x, v.y);
        o.y = packh2(v.z, v.w);
        ((uint2*)out)[i] = o;
        return;
    }
    if (bid < 20480) {                      // value transpose -> g_avt [dp][row]
        int tb = bid - 18432;               // 2048 blocks: 64 row-tiles x 32 d-tiles
        int rbase = (tb & 63) * 64;
        int dbase = (tb >> 6) * 32;
        // load 64 rows x 32 cols = 512 float4 -> 2 iters of 256 threads
#pragma unroll
        for (int l = 0; l < 2; l++) {
            int lin = tid + l * 256;
            int r = lin >> 3;
            int c4 = (lin & 7) << 2;
            float4 v = *(const float4*)&value[(size_t)(rbase + r) * DD + dbase + c4];
            ts[r][c4] = v.x; ts[r][c4 + 1] = v.y;
            ts[r][c4 + 2] = v.z; ts[r][c4 + 3] = v.w;
        }
        __syncthreads();
        // store 16 dp-rows x 64 rows = 1024 u32 -> 4 iters
#pragma unroll
        for (int l = 0; l < 4; l++) {
            int u = tid + l * 256;
            int row = u & 63;
            int dp = u >> 6;                // 0..15
            uint32_t w = packh2(ts[row][2 * dp], ts[row][2 * dp + 1]);
            g_avt[(size_t)((dbase >> 1) + dp) * MM + rbase + row] = w;
        }
        return;
    }
    // small precompute
    int T = (bid - 20480) * 256 + tid;
    if (T < 3072) {
        int f = T >> 10;
        int c = T & 1023;
        int h = c >> 6;
        int ep = c & 63;
        const float* b = (f == 0) ? bq : (f == 1) ? bk : bv;
        const float* P = (f == 0) ? sw : (f == 1) ? kpw : vlw;
        const float* pb = (f == 0) ? sb : (f == 1) ? kpb : vlb;
        float* O = (f == 0) ? g_bqf : (f == 1) ? g_bkf : g_bvf;
        float sum = pb[ep];
        for (int e = 0; e < DK; e++) sum += b[(h << 6) + e] * P[e * DK + ep];
        O[c] = sum;
        return;
    }
    T -= 3072;
    if (T < 16384) {
        int d = T >> 4, h = T & 15;
        float sum = 0.f;
        for (int e = 0; e < DK; e++) sum += wk[d * DD + (h << 6) + e] * chan_w[e];
        g_wck[d * HH + h] = sum;
        return;
    }
    T -= 16384;
    if (T < 16384) {
        int d = T >> 4, h = T & 15;
        float sum = 0.f;
        for (int e = 0; e < DK; e++) sum += wk[d * DD + (h << 6) + e] * chan_b[e];
        g_wcb[d * HH + h] = sum;
        return;
    }
    T -= 16384;
    if (T < 16) {
        float sum = 0.f;
        for (int e = 0; e < DK; e++) sum += bk[(T << 6) + e] * chan_w[e];
        g_bck[T] = sum;
        return;
    }
    T -= 16;
    if (T < 16) {
        float sum = 0.f;
        for (int e = 0; e < DK; e++) sum += bk[(T << 6) + e] * chan_b[e];
        g_bcb[T] = sum;
        return;
    }
    T -= 16;
    if (T < 64) {
        float sum = 0.f;
        for (int ep = 0; ep < DK; ep++) sum += qpw[T * DK + ep];
        g_qv[T] = sum * (1.f / 64.f);
        return;
    }
    T -= 64;
    if (T == 0) {
        float sum = 0.f;
        for (int ep = 0; ep < DK; ep++) sum += qpb[ep];
        g_bmean = sum * (1.f / 64.f);
    }
}

// ---------------- 2. fp16 tensor-core GEMM -------------------------------------
// mode 0: f32 out [row][DD].  mode 2: elu + fp16-pack out [row][DD/2].
// mode 3 (transposed V): M=e rows, N=key cols; bias per-ROW; elu; out key-pair
//                        packed [e][MM/2].
#define GSTAGES 3
#define GBKP 16
#define ASTP 20
#define BSTP 136
#define ASZP (128 * ASTP)
#define BSZP (GBKP * BSTP)
#define GSM_BYTES (GSTAGES * (ASZP + BSZP) * 4)   // 56832

struct GemmArgs {
    const uint32_t* A[3];
    const uint32_t* B[3];
    const float* bias[3];
    void* C[3];
    int mode[3];
    int Nn[3];
};

__device__ __forceinline__ void gemm_load_stage(uint32_t* As, uint32_t* Bs,
                                                const uint32_t* A, const uint32_t* Bm,
                                                int brow, int bcol, int kt, int tid,
                                                int Nn) {
#pragma unroll
    for (int l = 0; l < 2; l++) {
        int lin = tid + l * 256;
        int row = lin >> 2, c4 = (lin & 3) << 2;
        cpa16(&As[row * ASTP + c4], &A[(size_t)(brow + row) * (DD / 2) + kt * GBKP + c4]);
    }
#pragma unroll
    for (int l = 0; l < 2; l++) {
        int lin = tid + l * 256;
        int kr = lin >> 5, c4 = (lin & 31) << 2;
        cpa16(&Bs[kr * BSTP + c4], &Bm[(size_t)(kt * GBKP + kr) * Nn + bcol + c4]);
    }
}

__global__ void __launch_bounds__(256, 2)
gemm_f16(GemmArgs ga) {
    extern __shared__ uint32_t smem_u[];
    uint32_t* Asm = smem_u;
    uint32_t* Bsm = smem_u + GSTAGES * ASZP;

    int z = blockIdx.z;
    const uint32_t* A = ga.A[z];
    const uint32_t* Bm = ga.B[z];
    const float* bias = ga.bias[z];
    int mode = ga.mode[z];
    int Nn = ga.Nn[z];

    int tid = threadIdx.x;
    int brow, bcol;
    if (mode == 3) { brow = blockIdx.x * 128; bcol = blockIdx.y * 128; }
    else           { brow = blockIdx.y * 128; bcol = blockIdx.x * 128; }
    int warp = tid >> 5;
    int lane = tid & 31;
    int gr = lane >> 2;
    int gc = lane & 3;
    int wrow = (warp >> 2) * 64;
    int wcol = (warp & 3) * 32;

    float acc[4][4][4];
#pragma unroll
    for (int mt = 0; mt < 4; mt++)
#pragma unroll
        for (int nt = 0; nt < 4; nt++)
#pragma unroll
            for (int r = 0; r < 4; r++) acc[mt][nt][r] = 0.f;

    const int KT = (DD / 2) / GBKP;   // 32
    gemm_load_stage(Asm, Bsm, A, Bm, brow, bcol, 0, tid, Nn);
    asm volatile("cp.async.commit_group;\n");
    gemm_load_stage(Asm + ASZP, Bsm + BSZP, A, Bm, brow, bcol, 1, tid, Nn);
    asm volatile("cp.async.commit_group;\n");

    int s0 = 0, s1 = 1, s2 = 2;
    for (int kt = 0; kt < KT; kt++) {
        asm volatile("cp.async.wait_group 1;\n" ::: "memory");
        __syncthreads();
        uint32_t* As = Asm + s0 * ASZP;
        uint32_t* Bs = Bsm + s0 * BSZP;
#pragma unroll
        for (int c2 = 0; c2 < 2; c2++) {
            int kpb = c2 * 8;
            uint32_t af[4][4], bf[4][2];
#pragma unroll
            for (int mt = 0; mt < 4; mt++) {
                int row0 = wrow + mt * 16 + gr;
                af[mt][0] = As[row0 * ASTP + kpb + gc];
                af[mt][1] = As[(row0 + 8) * ASTP + kpb + gc];
                af[mt][2] = As[row0 * ASTP + kpb + gc + 4];
                af[mt][3] = As[(row0 + 8) * ASTP + kpb + gc + 4];
            }
#pragma unroll
            for (int nt = 0; nt < 4; nt++) {
                int col0 = wcol + nt * 8 + gr;
                bf[nt][0] = Bs[(kpb + gc) * BSTP + col0];
                bf[nt][1] = Bs[(kpb + gc + 4) * BSTP + col0];
            }
#pragma unroll
            for (int mt = 0; mt < 4; mt++)
#pragma unroll
                for (int nt = 0; nt < 4; nt++)
                    MMA_F16(acc[mt][nt], af[mt], bf[nt]);
        }
        int nk = kt + 2;
        if (nk < KT)
            gemm_load_stage(Asm + s2 * ASZP, Bsm + s2 * BSZP, A, Bm, brow, bcol, nk, tid, Nn);
        asm volatile("cp.async.commit_group;\n");
        int t = s0; s0 = s1; s1 = s2; s2 = t;
    }

    // epilogue
#pragma unroll
    for (int mt = 0; mt < 4; mt++) {
        int r0 = brow + wrow + mt * 16 + gr;
#pragma unroll
        for (int nt = 0; nt < 4; nt++) {
            int c0 = bcol + wcol + nt * 8 + (gc << 1);
            float v0, v1, v2, v3;
            if (mode == 3) {
                float rb0 = bias[r0], rb1 = bias[r0 + 8];
                v0 = acc[mt][nt][0] + rb0;
                v1 = acc[mt][nt][1] + rb0;
                v2 = acc[mt][nt][2] + rb1;
                v3 = acc[mt][nt][3] + rb1;
            } else {
                float b0 = bias[c0], b1 = bias[c0 + 1];
                v0 = acc[mt][nt][0] + b0;
                v1 = acc[mt][nt][1] + b1;
                v2 = acc[mt][nt][2] + b0;
                v3 = acc[mt][nt][3] + b1;
            }
            if (mode >= 2) {
                v0 = v0 > 0.f ? v0 : (__expf(v0) - 1.f);
                v1 = v1 > 0.f ? v1 : (__expf(v1) - 1.f);
                v2 = v2 > 0.f ? v2 : (__expf(v2) - 1.f);
                v3 = v3 > 0.f ? v3 : (__expf(v3) - 1.f);
            }
            if (mode == 3) {
                uint32_t* Cw = (uint32_t*)ga.C[z];
                Cw[(size_t)r0 * (MM / 2) + (c0 >> 1)] = packh2(v0, v1);
                Cw[(size_t)(r0 + 8) * (MM / 2) + (c0 >> 1)] = packh2(v2, v3);
            } else if (mode == 2) {
                uint32_t* Cw = (uint32_t*)ga.C[z];
                Cw[(size_t)r0 * (DD / 2) + (c0 >> 1)] = packh2(v0, v1);
                Cw[(size_t)(r0 + 8) * (DD / 2) + (c0 >> 1)] = packh2(v2, v3);
            } else {
                float* Cf = (float*)ga.C[z];
                *(float2*)&Cf[(size_t)r0 * DD + c0] = make_float2(v0, v1);
                *(float2*)&Cf[(size_t)(r0 + 8) * DD + c0] = make_float2(v2, v3);
            }
        }
    }
}

// ---------------- 3. ck/cb skinny GEMV ------------------------------------------
__global__ void ckcb_kernel(const float* __restrict__ key) {
    __shared__ float rows[8][1024];
    int tid = threadIdx.x;
    int row0 = blockIdx.x * 8;
#pragma unroll
    for (int l = 0; l < 8; l++) {
        int lin = tid + l * 256;
        int r = lin >> 8;
        int c4 = (lin & 255) << 2;
        *(float4*)&rows[r][c4] = *(const float4*)&key[(size_t)(row0 + r) * DD + c4];
    }
    __syncthreads();
    int r = tid >> 5;
    int o = tid & 31;
    int h = o & 15;
    int isB = o >> 4;
    const float* wp = isB ? g_wcb : g_wck;
    float sum = isB ? g_bcb[h] : g_bck[h];
#pragma unroll 8
    for (int d = 0; d < DD; d++) sum += rows[r][d] * wp[d * HH + h];
    (isB ? g_cb : g_ck)[(size_t)(row0 + r) * HH + h] = sum;
}

// ---------------- 4. flash attention: all-fp16 MMA, cp.async, occ 2+ -----------
// CTA: 64 q-rows x (b,h). 4 warps x 16 q-rows. K-tiles of 64, 2-buffer cp.async.
// Q/K fp16 [row][ep] stride 36 u32; V fp16 transposed [e][kp] stride 36 u32;
// P fp16 [q][kp] stride 36 u32. All strides = 4 mod 32 -> conflict-free frags.
#define AKS 36
#define TILE_U (64 * AKS)
#define ASM_BYTES ((6 * TILE_U + 256) * 4)   // 56320

__global__ void __launch_bounds__(128, 2) attn_tc_kernel() {
    extern __shared__ uint32_t smu[];
    uint32_t* PsH = smu;                    // P [q][kp]
    uint32_t* Qh  = smu + TILE_U;           // Q [q][ep]
    uint32_t* KsB = smu + 2 * TILE_U;       // 2 x K [key][ep]
    uint32_t* VtB = smu + 4 * TILE_U;       // 2 x V^T [e][kp]
    float* ckB = (float*)(smu + 6 * TILE_U);
    float* cbB = ckB + 128;

    int tid = threadIdx.x;
    int q0 = blockIdx.x * 64;
    int h = blockIdx.y;
    int b = blockIdx.z;
    int warp = tid >> 5;
    int lane = tid & 31;
    int gr = lane >> 2;
    int gc = lane & 3;
    int wrow = warp * 16;

    // issue Q staging (group 0)
#pragma unroll
    for (int l = 0; l < 4; l++) {
        int lin = tid + l * 128;
        int r = lin >> 3;
        int c4 = (lin & 7) << 2;
        cpa16(&Qh[r * AKS + c4],
              &g_qs[(size_t)((b << 10) + q0 + r) * (DD / 2) + (h << 5) + c4]);
    }
    asm volatile("cp.async.commit_group;\n");

    auto issue_tile = [&](int kt, int buf) {
        int k0 = kt * 64;
        uint32_t* Ks = KsB + buf * TILE_U;
        uint32_t* Vt = VtB + buf * TILE_U;
#pragma unroll
        for (int l = 0; l < 4; l++) {
            int lin = tid + l * 128;
            int r = lin >> 3;
            int c4 = (lin & 7) << 2;
            cpa16(&Ks[r * AKS + c4],
                  &g_k2[(size_t)((b << 10) + k0 + r) * (DD / 2) + (h << 5) + c4]);
            cpa16(&Vt[r * AKS + c4],
                  &g_v2t[(size_t)((h << 6) + r) * (MM / 2) + (((b << 10) + k0) >> 1) + c4]);
        }
        if (tid < 64) {
            cpa4(&ckB[buf * 64 + tid], &g_ck[(size_t)((b << 10) + k0 + tid) * HH + h]);
            cpa4(&cbB[buf * 64 + tid], &g_cb[(size_t)((b << 10) + k0 + tid) * HH + h]);
        }
        asm volatile("cp.async.commit_group;\n");
    };
    issue_tile(0, 0);

    asm volatile("cp.async.wait_group 1;\n" ::: "memory");
    __syncthreads();

    // Q fragments
    uint32_t qf[4][4];
#pragma unroll
    for (int c = 0; c < 4; c++) {
        qf[c][0] = Qh[(wrow + gr) * AKS + c * 8 + gc];
        qf[c][1] = Qh[(wrow + gr + 8) * AKS + c * 8 + gc];
        qf[c][2] = Qh[(wrow + gr) * AKS + c * 8 + gc + 4];
        qf[c][3] = Qh[(wrow + gr + 8) * AKS + c * 8 + gc + 4];
    }
    // inline per-row gate scalar m = Q_row . qv + bmean
    const __half* q0h = (const __half*)(Qh + (wrow + gr) * AKS);
    const __half* q1h = (const __half*)(Qh + (wrow + gr + 8) * AKS);
    float a0 = 0.f, a1 = 0.f;
#pragma unroll
    for (int e16 = 0; e16 < 16; e16++) {
        int e = gc * 16 + e16;
        float qv = __ldg(&g_qv[e]);
        a0 = fmaf(__half2float(q0h[e]), qv, a0);
        a1 = fmaf(__half2float(q1h[e]), qv, a1);
    }
#pragma unroll
    for (int d = 1; d < 4; d <<= 1) {
        a0 += __shfl_xor_sync(0xffffffffu, a0, d);
        a1 += __shfl_xor_sync(0xffffffffu, a1, d);
    }
    float bmean = g_bmean;
    float mq0 = a0 + bmean;
    float mq1 = a1 + bmean;

    int qrow0 = q0 + wrow + gr;
    int qrow1 = qrow0 + 8;
    float rm0 = -INFINITY, rm1 = -INFINITY, rs0 = 0.f, rs1 = 0.f;
    float ofr[8][4];
#pragma unroll
    for (int nf = 0; nf < 8; nf++)
#pragma unroll
        for (int r = 0; r < 4; r++) ofr[nf][r] = 0.f;

    unsigned pmbase0 = ((unsigned)((b << 10) + qrow0)) << 5;
    unsigned pmbase1 = ((unsigned)((b << 10) + qrow1)) << 5;

    for (int kt = 0; kt < 16; kt++) {
        int cur = kt & 1;
        __syncthreads();
        if (kt < 15) issue_tile(kt + 1, 1 - cur);
        if (kt < 15) { asm volatile("cp.async.wait_group 1;\n" ::: "memory"); }
        else         { asm volatile("cp.async.wait_group 0;\n" ::: "memory"); }
        __syncthreads();

        uint32_t* Ks = KsB + cur * TILE_U;
        uint32_t* Vt = VtB + cur * TILE_U;
        float* ckv = ckB + cur * 64;
        float* cbv = cbB + cur * 64;
        int k0 = kt * 64;

        // ---- scores S = Q @ K^T (fp16) ----
        float sfr[8][4];
#pragma unroll
        for (int nf = 0; nf < 8; nf++)
#pragma unroll
            for (int r = 0; r < 4; r++) sfr[nf][r] = 0.f;
#pragma unroll
        for (int c = 0; c < 4; c++) {
#pragma unroll
            for (int nf = 0; nf < 8; nf++) {
                uint32_t bf[2];
                bf[0] = Ks[(nf * 8 + gr) * AKS + c * 8 + gc];
                bf[1] = Ks[(nf * 8 + gr) * AKS + c * 8 + gc + 4];
                MMA_F16(sfr[nf], qf[c], bf);
            }
        }

        // ---- gate + mask ----
        unsigned w00 = g_pm[pmbase0 + (k0 >> 5)];
        unsigned w01 = g_pm[pmbase0 + (k0 >> 5) + 1];
        unsigned w10 = g_pm[pmbase1 + (k0 >> 5)];
        unsigned w11 = g_pm[pmbase1 + (k0 >> 5) + 1];
#pragma unroll
        for (int nf = 0; nf < 8; nf++) {
            int c0 = nf * 8 + (gc << 1);
            int c1 = c0 + 1;
            float lk0 = ckv[c0], lk1 = ckv[c1];
            float lb0 = cbv[c0], lb1 = cbv[c1];
            float g00 = __fdividef(1.f, 1.f + __expf(-fmaf(mq0, lk0, lb0)));
            float g01 = __fdividef(1.f, 1.f + __expf(-fmaf(mq0, lk1, lb1)));
            float g10 = __fdividef(1.f, 1.f + __expf(-fmaf(mq1, lk0, lb0)));
            float g11 = __fdividef(1.f, 1.f + __expf(-fmaf(mq1, lk1, lb1)));
            float v0 = sfr[nf][0] * 0.125f * g00;
            float v1 = sfr[nf][1] * 0.125f * g01;
            float v2 = sfr[nf][2] * 0.125f * g10;
            float v3 = sfr[nf][3] * 0.125f * g11;
            unsigned wa0 = (c0 < 32) ? w00 : w01;
            unsigned wa1 = (c1 < 32) ? w00 : w01;
            unsigned wb0 = (c0 < 32) ? w10 : w11;
            unsigned wb1 = (c1 < 32) ? w10 : w11;
            if (!((wa0 >> (c0 & 31)) & 1u)) v0 = -1e9f;
            if (!((wa1 >> (c1 & 31)) & 1u)) v1 = -1e9f;
            if (!((wb0 >> (c0 & 31)) & 1u)) v2 = -1e9f;
            if (!((wb1 >> (c1 & 31)) & 1u)) v3 = -1e9f;
            sfr[nf][0] = v0; sfr[nf][1] = v1; sfr[nf][2] = v2; sfr[nf][3] = v3;
        }

        // ---- online softmax ----
        float m0 = -INFINITY, m1 = -INFINITY;
#pragma unroll
        for (int nf = 0; nf < 8; nf++) {
            m0 = fmaxf(m0, fmaxf(sfr[nf][0], sfr[nf][1]));
            m1 = fmaxf(m1, fmaxf(sfr[nf][2], sfr[nf][3]));
        }
#pragma unroll
        for (int d = 1; d < 4; d <<= 1) {
            m0 = fmaxf(m0, __shfl_xor_sync(0xffffffffu, m0, d));
            m1 = fmaxf(m1, __shfl_xor_sync(0xffffffffu, m1, d));
        }
        float tm0 = fmaxf(rm0, m0);
        float tm1 = fmaxf(rm1, m1);
        float sc0 = __expf(rm0 - tm0);
        float sc1 = __expf(rm1 - tm1);
        rm0 = tm0; rm1 = tm1;
        float sum0 = 0.f, sum1 = 0.f;
#pragma unroll
        for (int nf = 0; nf < 8; nf++) {
            float p0 = __expf(sfr[nf][0] - tm0);
            float p1 = __expf(sfr[nf][1] - tm0);
            float p2 = __expf(sfr[nf][2] - tm1);
            float p3 = __expf(sfr[nf][3] - tm1);
            sum0 += p0 + p1;
            sum1 += p2 + p3;
            sfr[nf][0] = p0; sfr[nf][1] = p1; sfr[nf][2] = p2; sfr[nf][3] = p3;
        }
#pragma unroll
        for (int d = 1; d < 4; d <<= 1) {
            sum0 += __shfl_xor_sync(0xffffffffu, sum0, d);
            sum1 += __shfl_xor_sync(0xffffffffu, sum1, d);
        }
        rs0 = rs0 * sc0 + sum0;
        rs1 = rs1 * sc1 + sum1;
#pragma unroll
        for (int nf = 0; nf < 8; nf++) {
            ofr[nf][0] *= sc0; ofr[nf][1] *= sc0;
            ofr[nf][2] *= sc1; ofr[nf][3] *= sc1;
        }

        // ---- store P as fp16 key-pairs (warp-private rows) ----
#pragma unroll
        for (int nf = 0; nf < 8; nf++) {
            int kp = nf * 4 + gc;
            PsH[(wrow + gr) * AKS + kp] = packh2(sfr[nf][0], sfr[nf][1]);
            PsH[(wrow + gr + 8) * AKS + kp] = packh2(sfr[nf][2], sfr[nf][3]);
        }
        __syncwarp();

        // ---- O += P @ V (fp16; V^T [e][kp]) ----
#pragma unroll
        for (int c = 0; c < 4; c++) {
            uint32_t af[4];
            af[0] = PsH[(wrow + gr) * AKS + c * 8 + gc];
            af[1] = PsH[(wrow + gr + 8) * AKS + c * 8 + gc];
            af[2] = PsH[(wrow + gr) * AKS + c * 8 + gc + 4];
            af[3] = PsH[(wrow + gr + 8) * AKS + c * 8 + gc + 4];
#pragma unroll
            for (int nf = 0; nf < 8; nf++) {
                uint32_t bf[2];
                bf[0] = Vt[(nf * 8 + gr) * AKS + c * 8 + gc];
                bf[1] = Vt[(nf * 8 + gr) * AKS + c * 8 + gc + 4];
                MMA_F16(ofr[nf], af, bf);
            }
        }
    }

    // ---- normalize + write fp16-packed ----
    float inv0 = 1.f / rs0;
    float inv1 = 1.f / rs1;
#pragma unroll
    for (int nf = 0; nf < 8; nf++) {
        int c0 = (h << 6) + nf * 8 + (gc << 1);
        g_xp[(size_t)((b << 10) + qrow0) * (DD / 2) + (c0 >> 1)] =
            packh2(ofr[nf][0] * inv0, ofr[nf][1] * inv0);
        g_xp[(size_t)((b << 10) + qrow1) * (DD / 2) + (c0 >> 1)] =
            packh2(ofr[nf][2] * inv1, ofr[nf][3] * inv1);
    }
}

// ---------------- launch --------------------------------------------------------
extern "C" void kernel_launch(void* const* d_in, const int* in_sizes, int n_in,
                              void* d_out, int out_size) {
    const float* query = (const float*)d_in[0];
    const float* key   = (const float*)d_in[1];
    const float* value = (const float*)d_in[2];
    const int*   mask  = (const int*)d_in[3];
    const float* wq = (const float*)d_in[4];
    const float* bq = (const float*)d_in[5];
    const float* wk = (const float*)d_in[6];
    const float* bk = (const float*)d_in[7];
    const float* wv = (const float*)d_in[8];
    const float* bv = (const float*)d_in[9];
    const float* wo = (const float*)d_in[10];
    const float* bo = (const float*)d_in[11];
    const float* spatial_w = (const float*)d_in[12];
    const float* spatial_b = (const float*)d_in[13];
    const float* qproj_w = (const float*)d_in[14];
    const float* qproj_b = (const float*)d_in[15];
    const float* kproj_w = (const float*)d_in[16];
    const float* kproj_b = (const float*)d_in[17];
    const float* vlin_w = (const float*)d_in[18];
    const float* vlin_b = (const float*)d_in[19];
    const float* chan_w = (const float*)d_in[20];
    const float* chan_b = (const float*)d_in[21];
    float* out = (float*)d_out;

    float *p_bqf, *p_bkf, *p_bvf;
    uint32_t *p_wqp, *p_wkp, *p_wvt, *p_wop, *p_aq, *p_ak, *p_avt;
    uint32_t *p_qs, *p_k2, *p_v2t, *p_xp;
    cudaGetSymbolAddress((void**)&p_bqf, g_bqf);
    cudaGetSymbolAddress((void**)&p_bkf, g_bkf);
    cudaGetSymbolAddress((void**)&p_bvf, g_bvf);
    cudaGetSymbolAddress((void**)&p_wqp, g_wqp);
    cudaGetSymbolAddress((void**)&p_wkp, g_wkp);
    cudaGetSymbolAddress((void**)&p_wvt, g_wvt);
    cudaGetSymbolAddress((void**)&p_wop, g_wop);
    cudaGetSymbolAddress((void**)&p_aq, g_aq);
    cudaGetSymbolAddress((void**)&p_ak, g_ak);
    cudaGetSymbolAddress((void**)&p_avt, g_avt);
    cudaGetSymbolAddress((void**)&p_qs, g_qs);
    cudaGetSymbolAddress((void**)&p_k2, g_k2);
    cudaGetSymbolAddress((void**)&p_v2t, g_v2t);
    cudaGetSymbolAddress((void**)&p_xp, g_xp);

    cudaFuncSetAttribute(gemm_f16, cudaFuncAttributeMaxDynamicSharedMemorySize, GSM_BYTES);
    cudaFuncSetAttribute(attn_tc_kernel, cudaFuncAttributeMaxDynamicSharedMemorySize, ASM_BYTES);

    // 1. all independent prep in one launch
    mega_prep<<<20621, 256>>>(query, key, value, mask,
                              wq, bq, wk, bk, wv, bv, wo,
                              spatial_w, spatial_b, qproj_w, qproj_b,
                              kproj_w, kproj_b, vlin_w, vlin_b, chan_w, chan_b);
    // 2. ck/cb gate scalars (needs small-prep outputs)
    ckcb_kernel<<<MM / 8, 256>>>(key);

    // 3. merged QKV fp16 GEMM: Q,K normal; V transposed (key-pair packed out)
    GemmArgs gqkv;
    gqkv.A[0] = p_aq;  gqkv.A[1] = p_ak;  gqkv.A[2] = p_wvt;
    gqkv.B[0] = p_wqp; gqkv.B[1] = p_wkp; gqkv.B[2] = p_avt;
    gqkv.bias[0] = p_bqf; gqkv.bias[1] = p_bkf; gqkv.bias[2] = p_bvf;
    gqkv.C[0] = p_qs;  gqkv.C[1] = p_k2;  gqkv.C[2] = p_v2t;
    gqkv.mode[0] = 2;  gqkv.mode[1] = 2;  gqkv.mode[2] = 3;
    gqkv.Nn[0] = DD;   gqkv.Nn[1] = DD;   gqkv.Nn[2] = MM;
    gemm_f16<<<dim3(8, 32, 3), 256, GSM_BYTES>>>(gqkv);

    // 4. attention: all-fp16 MMA (occ 2+, cp.async)
    attn_tc_kernel<<<dim3(SS / 64, HH, BB), 128, ASM_BYTES>>>();

    // 5. fp16 output projection
    GemmArgs go;
    go.A[0] = go.A[1] = go.A[2] = p_xp;
    go.B[0] = go.B[1] = go.B[2] = p_wop;
    go.bias[0] = go.bias[1] = go.bias[2] = bo;
    go.C[0] = go.C[1] = go.C[2] = out;
    go.mode[0] = go.mode[1] = go.mode[2] = 0;
    go.Nn[0] = go.Nn[1] = go.Nn[2] = DD;
    gemm_f16<<<dim3(8, 32, 1), 256, GSM_BYTES>>>(go);
}

// round 13
// speedup vs baseline: 4.4562x; 1.0380x over previous
#include <cuda_runtime.h>
#include <cuda_fp16.h>
#include <math.h>
#include <stdint.h>

#define BB 4
#define SS 1024
#define DD 1024
#define HH 16
#define DK 64
#define MM (BB * SS)   // 4096

// ---------------- scratch (device globals; no allocation allowed) -------------
__device__ uint32_t g_wqp[DD / 2 * DD];    // fp16 weights, k-pair packed [kp][n]
__device__ uint32_t g_wkp[DD / 2 * DD];
__device__ uint32_t g_wvt[DD * DD / 2];    // V weights TRANSPOSED [e][dp]
__device__ uint32_t g_wop[DD / 2 * DD];
__device__ float g_bqf[DD];
__device__ float g_bkf[DD];
__device__ float g_bvf[DD];
__device__ float g_wck[DD * HH];
__device__ float g_wcb[DD * HH];
__device__ float g_bck[HH];
__device__ float g_bcb[HH];
__device__ float g_qv[DK];
__device__ float g_bmean;
__device__ uint32_t g_aq[MM * DD / 2];     // fp16-packed query activations
__device__ uint32_t g_ak[MM * DD / 2];     // fp16-packed key activations
__device__ uint32_t g_avt[DD / 2 * MM];    // value TRANSPOSED fp16 d-pair packed [dp][row]
__device__ uint32_t g_qs[MM * DD / 2];     // Q proj (fp16 packed, pre-scaled by 1/8)
__device__ uint32_t g_k2[MM * DD / 2];     // K proj (fp16 packed)
__device__ uint32_t g_v2t[DD * MM / 2];    // V proj TRANSPOSED key-pair packed [e][kp]
__device__ uint32_t g_xp[MM * DD / 2];     // attention out (fp16 packed)
__device__ __half g_ckh[HH * MM];          // gate ck, head-major fp16 [h][key]
__device__ __half g_cbh[HH * MM];          // gate cb, head-major fp16 [h][key]
__device__ unsigned g_pm[BB * SS * SS / 32];

__device__ __forceinline__ uint32_t packh2(float a, float b) {
    __half2 h = __floats2half2_rn(a, b);
    return *(uint32_t*)&h;
}

#define MMA_F16(d, a, b) \
    asm volatile("mma.sync.aligned.m16n8k16.row.col.f32.f16.f16.f32 " \
                 "{%0,%1,%2,%3},{%4,%5,%6,%7},{%8,%9},{%0,%1,%2,%3};" \
                 : "+f"(d[0]), "+f"(d[1]), "+f"(d[2]), "+f"(d[3]) \
                 : "r"(a[0]), "r"(a[1]), "r"(a[2]), "r"(a[3]), "r"(b[0]), "r"(b[1]));

__device__ __forceinline__ void cpa16(void* dst, const void* src) {
    unsigned d = (unsigned)__cvta_generic_to_shared(dst);
    asm volatile("cp.async.cg.shared.global [%0], [%1], 16;\n" :: "r"(d), "l"(src));
}

// ---------------- 1. mega prep kernel ------------------------------------------
// blocks [0,2048) fold Q; [2048,4096) fold K; [4096,6144) fold V transposed;
// [6144,8192) wo_pack; [8192,10240) mask_pack; [10240,14336) cvt query;
// [14336,18432) cvt key; [18432,20480) value transpose; [20480,20621) small prep
__global__ void __launch_bounds__(256)
mega_prep(const float* __restrict__ query, const float* __restrict__ key,
          const float* __restrict__ value, const int* __restrict__ mask,
          const float* __restrict__ wq, const float* __restrict__ bq,
          const float* __restrict__ wk, const float* __restrict__ bk,
          const float* __restrict__ wv, const float* __restrict__ bv,
          const float* __restrict__ wo,
          const float* __restrict__ sw, const float* __restrict__ sb,
          const float* __restrict__ qpw, const float* __restrict__ qpb,
          const float* __restrict__ kpw, const float* __restrict__ kpb,
          const float* __restrict__ vlw, const float* __restrict__ vlb,
          const float* __restrict__ chan_w, const float* __restrict__ chan_b) {
    __shared__ float ts[64][33];
    int bid = blockIdx.x;
    int tid = threadIdx.x;

    if (bid < 6144) {                       // fold projections
        int f = bid >> 11;
        int idx = (bid & 2047) * 256 + tid;
        int kp2 = idx >> 10;
        int n = idx & 1023;
        int h = n >> 6;
        int ep = n & 63;
        const float* W = (f == 0) ? wq : (f == 1) ? wk : wv;
        const float* P = (f == 0) ? sw : (f == 1) ? kpw : vlw;
        const float* w0 = W + (size_t)(2 * kp2) * DD + (h << 6);
        const float* w1 = w0 + DD;
        float s0 = 0.f, s1 = 0.f;
#pragma unroll 8
        for (int e = 0; e < DK; e++) {
            float pv = P[e * DK + ep];
            s0 = fmaf(w0[e], pv, s0);
            s1 = fmaf(w1[e], pv, s1);
        }
        uint32_t o = packh2(s0, s1);
        if (f == 0) g_wqp[idx] = o;
        else if (f == 1) g_wkp[idx] = o;
        else g_wvt[(size_t)n * (DD / 2) + kp2] = o;   // transposed [e][dp]
        return;
    }
    if (bid < 8192) {                       // wo pack
        int idx = (bid - 6144) * 256 + tid;
        int kp2 = idx >> 10;
        int n = idx & 1023;
        float s0 = __ldg(&wo[(size_t)(2 * kp2) * DD + n]);
        float s1 = __ldg(&wo[(size_t)(2 * kp2 + 1) * DD + n]);
        g_wop[idx] = packh2(s0, s1);
        return;
    }
    if (bid < 10240) {                      // mask pack
        int t = (bid - 8192) * 256 + tid;
        const int4* p = (const int4*)mask + (size_t)t * 2;
        int4 a = p[0], b = p[1];
        unsigned byte = (unsigned)(a.x != 0) | ((unsigned)(a.y != 0) << 1)
                      | ((unsigned)(a.z != 0) << 2) | ((unsigned)(a.w != 0) << 3)
                      | ((unsigned)(b.x != 0) << 4) | ((unsigned)(b.y != 0) << 5)
                      | ((unsigned)(b.z != 0) << 6) | ((unsigned)(b.w != 0) << 7);
        ((unsigned char*)g_pm)[t] = (unsigned char)byte;
        return;
    }
    if (bid < 18432) {                      // cvt query / key to fp16 pairs
        int isK = bid >= 14336;
        int i = (bid - (isK ? 14336 : 10240)) * 256 + tid;
        const float* in = isK ? key : query;
        uint32_t* out = isK ? g_ak : g_aq;
        float4 v = ((const float4*)in)[i];
        uint2 o;
        o.x = packh2(v.x, v.y);
        o.y = packh2(v.z, v.w);
        ((uint2*)out)[i] = o;
        return;
    }
    if (bid < 20480) {                      // value transpose -> g_avt [dp][row]
        int tb = bid - 18432;               // 2048 blocks: 64 row-tiles x 32 d-tiles
        int rbase = (tb & 63) * 64;
        int dbase = (tb >> 6) * 32;
#pragma unroll
        for (int l = 0; l < 2; l++) {
            int lin = tid + l * 256;
            int r = lin >> 3;
            int c4 = (lin & 7) << 2;
            float4 v = *(const float4*)&value[(size_t)(rbase + r) * DD + dbase + c4];
            ts[r][c4] = v.x; ts[r][c4 + 1] = v.y;
            ts[r][c4 + 2] = v.z; ts[r][c4 + 3] = v.w;
        }
        __syncthreads();
#pragma unroll
        for (int l = 0; l < 4; l++) {
            int u = tid + l * 256;
            int row = u & 63;
            int dp = u >> 6;
            uint32_t w = packh2(ts[row][2 * dp], ts[row][2 * dp + 1]);
            g_avt[(size_t)((dbase >> 1) + dp) * MM + rbase + row] = w;
        }
        return;
    }
    // small precompute
    int T = (bid - 20480) * 256 + tid;
    if (T < 3072) {
        int f = T >> 10;
        int c = T & 1023;
        int h = c >> 6;
        int ep = c & 63;
        const float* b = (f == 0) ? bq : (f == 1) ? bk : bv;
        const float* P = (f == 0) ? sw : (f == 1) ? kpw : vlw;
        const float* pb = (f == 0) ? sb : (f == 1) ? kpb : vlb;
        float* O = (f == 0) ? g_bqf : (f == 1) ? g_bkf : g_bvf;
        float sum = pb[ep];
        for (int e = 0; e < DK; e++) sum += b[(h << 6) + e] * P[e * DK + ep];
        O[c] = sum;
        return;
    }
    T -= 3072;
    if (T < 16384) {
        int d = T >> 4, h = T & 15;
        float sum = 0.f;
        for (int e = 0; e < DK; e++) sum += wk[d * DD + (h << 6) + e] * chan_w[e];
        g_wck[d * HH + h] = sum;
        return;
    }
    T -= 16384;
    if (T < 16384) {
        int d = T >> 4, h = T & 15;
        float sum = 0.f;
        for (int e = 0; e < DK; e++) sum += wk[d * DD + (h << 6) + e] * chan_b[e];
        g_wcb[d * HH + h] = sum;
        return;
    }
    T -= 16384;
    if (T < 16) {
        float sum = 0.f;
        for (int e = 0; e < DK; e++) sum += bk[(T << 6) + e] * chan_w[e];
        g_bck[T] = sum;
        return;
    }
    T -= 16;
    if (T < 16) {
        float sum = 0.f;
        for (int e = 0; e < DK; e++) sum += bk[(T << 6) + e] * chan_b[e];
        g_bcb[T] = sum;
        return;
    }
    T -= 16;
    if (T < 64) {                           // qv scaled x8 (Q stored pre-scaled /8)
        float sum = 0.f;
        for (int ep = 0; ep < DK; ep++) sum += qpw[T * DK + ep];
        g_qv[T] = sum * 0.125f;             // (1/64) * 8
        return;
    }
    T -= 64;
    if (T == 0) {
        float sum = 0.f;
        for (int ep = 0; ep < DK; ep++) sum += qpb[ep];
        g_bmean = sum * (1.f / 64.f);
    }
}

// ---------------- 2. fp16 tensor-core GEMM -------------------------------------
// mode 0: f32 out. mode 2: elu+pack. mode 3: transposed-V (bias/row, elu, pack
// key-pairs [e][MM/2]). mode 4: elu, x0.125, pack (Q projection).
#define GSTAGES 3
#define GBKP 16
#define ASTP 20
#define BSTP 136
#define ASZP (128 * ASTP)
#define BSZP (GBKP * BSTP)
#define GSM_BYTES (GSTAGES * (ASZP + BSZP) * 4)   // 56832

struct GemmArgs {
    const uint32_t* A[3];
    const uint32_t* B[3];
    const float* bias[3];
    void* C[3];
    int mode[3];
    int Nn[3];
};

__device__ __forceinline__ void gemm_load_stage(uint32_t* As, uint32_t* Bs,
                                                const uint32_t* A, const uint32_t* Bm,
                                                int brow, int bcol, int kt, int tid,
                                                int Nn) {
#pragma unroll
    for (int l = 0; l < 2; l++) {
        int lin = tid + l * 256;
        int row = lin >> 2, c4 = (lin & 3) << 2;
        cpa16(&As[row * ASTP + c4], &A[(size_t)(brow + row) * (DD / 2) + kt * GBKP + c4]);
    }
#pragma unroll
    for (int l = 0; l < 2; l++) {
        int lin = tid + l * 256;
        int kr = lin >> 5, c4 = (lin & 31) << 2;
        cpa16(&Bs[kr * BSTP + c4], &Bm[(size_t)(kt * GBKP + kr) * Nn + bcol + c4]);
    }
}

__global__ void __launch_bounds__(256, 2)
gemm_f16(GemmArgs ga) {
    extern __shared__ uint32_t smem_u[];
    uint32_t* Asm = smem_u;
    uint32_t* Bsm = smem_u + GSTAGES * ASZP;

    int z = blockIdx.z;
    const uint32_t* A = ga.A[z];
    const uint32_t* Bm = ga.B[z];
    const float* bias = ga.bias[z];
    int mode = ga.mode[z];
    int Nn = ga.Nn[z];

    int tid = threadIdx.x;
    int brow, bcol;
    if (mode == 3) { brow = blockIdx.x * 128; bcol = blockIdx.y * 128; }
    else           { brow = blockIdx.y * 128; bcol = blockIdx.x * 128; }
    int warp = tid >> 5;
    int lane = tid & 31;
    int gr = lane >> 2;
    int gc = lane & 3;
    int wrow = (warp >> 2) * 64;
    int wcol = (warp & 3) * 32;

    float acc[4][4][4];
#pragma unroll
    for (int mt = 0; mt < 4; mt++)
#pragma unroll
        for (int nt = 0; nt < 4; nt++)
#pragma unroll
            for (int r = 0; r < 4; r++) acc[mt][nt][r] = 0.f;

    const int KT = (DD / 2) / GBKP;   // 32
    gemm_load_stage(Asm, Bsm, A, Bm, brow, bcol, 0, tid, Nn);
    asm volatile("cp.async.commit_group;\n");
    gemm_load_stage(Asm + ASZP, Bsm + BSZP, A, Bm, brow, bcol, 1, tid, Nn);
    asm volatile("cp.async.commit_group;\n");

    int s0 = 0, s1 = 1, s2 = 2;
    for (int kt = 0; kt < KT; kt++) {
        asm volatile("cp.async.wait_group 1;\n" ::: "memory");
        __syncthreads();
        uint32_t* As = Asm + s0 * ASZP;
        uint32_t* Bs = Bsm + s0 * BSZP;
#pragma unroll
        for (int c2 = 0; c2 < 2; c2++) {
            int kpb = c2 * 8;
            uint32_t af[4][4], bf[4][2];
#pragma unroll
            for (int mt = 0; mt < 4; mt++) {
                int row0 = wrow + mt * 16 + gr;
                af[mt][0] = As[row0 * ASTP + kpb + gc];
                af[mt][1] = As[(row0 + 8) * ASTP + kpb + gc];
                af[mt][2] = As[row0 * ASTP + kpb + gc + 4];
                af[mt][3] = As[(row0 + 8) * ASTP + kpb + gc + 4];
            }
#pragma unroll
            for (int nt = 0; nt < 4; nt++) {
                int col0 = wcol + nt * 8 + gr;
                bf[nt][0] = Bs[(kpb + gc) * BSTP + col0];
                bf[nt][1] = Bs[(kpb + gc + 4) * BSTP + col0];
            }
#pragma unroll
            for (int mt = 0; mt < 4; mt++)
#pragma unroll
                for (int nt = 0; nt < 4; nt++)
                    MMA_F16(acc[mt][nt], af[mt], bf[nt]);
        }
        int nk = kt + 2;
        if (nk < KT)
            gemm_load_stage(Asm + s2 * ASZP, Bsm + s2 * BSZP, A, Bm, brow, bcol, nk, tid, Nn);
        asm volatile("cp.async.commit_group;\n");
        int t = s0; s0 = s1; s1 = s2; s2 = t;
    }

    // epilogue
#pragma unroll
    for (int mt = 0; mt < 4; mt++) {
        int r0 = brow + wrow + mt * 16 + gr;
#pragma unroll
        for (int nt = 0; nt < 4; nt++) {
            int c0 = bcol + wcol + nt * 8 + (gc << 1);
            float v0, v1, v2, v3;
            if (mode == 3) {
                float rb0 = bias[r0], rb1 = bias[r0 + 8];
                v0 = acc[mt][nt][0] + rb0;
                v1 = acc[mt][nt][1] + rb0;
                v2 = acc[mt][nt][2] + rb1;
                v3 = acc[mt][nt][3] + rb1;
            } else {
                float b0 = bias[c0], b1 = bias[c0 + 1];
                v0 = acc[mt][nt][0] + b0;
                v1 = acc[mt][nt][1] + b1;
                v2 = acc[mt][nt][2] + b0;
                v3 = acc[mt][nt][3] + b1;
            }
            if (mode >= 2) {
                v0 = v0 > 0.f ? v0 : (__expf(v0) - 1.f);
                v1 = v1 > 0.f ? v1 : (__expf(v1) - 1.f);
                v2 = v2 > 0.f ? v2 : (__expf(v2) - 1.f);
                v3 = v3 > 0.f ? v3 : (__expf(v3) - 1.f);
            }
            if (mode == 4) {
                v0 *= 0.125f; v1 *= 0.125f; v2 *= 0.125f; v3 *= 0.125f;
            }
            if (mode == 3) {
                uint32_t* Cw = (uint32_t*)ga.C[z];
                Cw[(size_t)r0 * (MM / 2) + (c0 >> 1)] = packh2(v0, v1);
                Cw[(size_t)(r0 + 8) * (MM / 2) + (c0 >> 1)] = packh2(v2, v3);
            } else if (mode >= 2) {
                uint32_t* Cw = (uint32_t*)ga.C[z];
                Cw[(size_t)r0 * (DD / 2) + (c0 >> 1)] = packh2(v0, v1);
                Cw[(size_t)(r0 + 8) * (DD / 2) + (c0 >> 1)] = packh2(v2, v3);
            } else {
                float* Cf = (float*)ga.C[z];
                *(float2*)&Cf[(size_t)r0 * DD + c0] = make_float2(v0, v1);
                *(float2*)&Cf[(size_t)(r0 + 8) * DD + c0] = make_float2(v2, v3);
            }
        }
    }
}

// ---------------- 3. ck/cb skinny GEMV (writes fp16 head-major) -----------------
__global__ void ckcb_kernel(const float* __restrict__ key) {
    __shared__ float rows[8][1024];
    int tid = threadIdx.x;
    int row0 = blockIdx.x * 8;
#pragma unroll
    for (int l = 0; l < 8; l++) {
        int lin = tid + l * 256;
        int r = lin >> 8;
        int c4 = (lin & 255) << 2;
        *(float4*)&rows[r][c4] = *(const float4*)&key[(size_t)(row0 + r) * DD + c4];
    }
    __syncthreads();
    int r = tid >> 5;
    int o = tid & 31;
    int h = o & 15;
    int isB = o >> 4;
    const float* wp = isB ? g_wcb : g_wck;
    float sum = isB ? g_bcb[h] : g_bck[h];
#pragma unroll 8
    for (int d = 0; d < DD; d++) sum += rows[r][d] * wp[d * HH + h];
    (isB ? g_cbh : g_ckh)[(size_t)h * MM + row0 + r] = __float2half(sum);
}

// ---------------- 4. flash attention: all-fp16 MMA + f16x2 gate, occ 3 ---------
// CTA: 64 q-rows x (b,h). 4 warps x 16 q-rows. K-tiles of 64, 2-buffer cp.async.
#define AKS 36
#define TILE_U (64 * AKS)
#define ASM_BYTES ((6 * TILE_U + 128) * 4)   // 55808

__global__ void __launch_bounds__(128, 3) attn_tc_kernel() {
    extern __shared__ uint32_t smu[];
    uint32_t* PsH = smu;                    // P [q][kp]
    uint32_t* Qh  = smu + TILE_U;           // Q [q][ep]
    uint32_t* KsB = smu + 2 * TILE_U;       // 2 x K [key][ep]
    uint32_t* VtB = smu + 4 * TILE_U;       // 2 x V^T [e][kp]
    uint32_t* ckB = smu + 6 * TILE_U;       // 2 x 32 u32 (64 fp16 ck)
    uint32_t* cbB = ckB + 64;               // 2 x 32 u32 (64 fp16 cb)

    int tid = threadIdx.x;
    int q0 = blockIdx.x * 64;
    int h = blockIdx.y;
    int b = blockIdx.z;
    int warp = tid >> 5;
    int lane = tid & 31;
    int gr = lane >> 2;
    int gc = lane & 3;
    int wrow = warp * 16;

    // issue Q staging (group 0)
#pragma unroll
    for (int l = 0; l < 4; l++) {
        int lin = tid + l * 128;
        int r = lin >> 3;
        int c4 = (lin & 7) << 2;
        cpa16(&Qh[r * AKS + c4],
              &g_qs[(size_t)((b << 10) + q0 + r) * (DD / 2) + (h << 5) + c4]);
    }
    asm volatile("cp.async.commit_group;\n");

    auto issue_tile = [&](int kt, int buf) {
        int k0 = kt * 64;
        uint32_t* Ks = KsB + buf * TILE_U;
        uint32_t* Vt = VtB + buf * TILE_U;
#pragma unroll
        for (int l = 0; l < 4; l++) {
            int lin = tid + l * 128;
            int r = lin >> 3;
            int c4 = (lin & 7) << 2;
            cpa16(&Ks[r * AKS + c4],
                  &g_k2[(size_t)((b << 10) + k0 + r) * (DD / 2) + (h << 5) + c4]);
            cpa16(&Vt[r * AKS + c4],
                  &g_v2t[(size_t)((h << 6) + r) * (MM / 2) + (((b << 10) + k0) >> 1) + c4]);
        }
        if (tid < 8)
            cpa16(&ckB[buf * 32 + tid * 4], &g_ckh[(size_t)h * MM + (b << 10) + k0 + tid * 8]);
        else if (tid < 16)
            cpa16(&cbB[buf * 32 + (tid - 8) * 4],
                  &g_cbh[(size_t)h * MM + (b << 10) + k0 + (tid - 8) * 8]);
        asm volatile("cp.async.commit_group;\n");
    };
    issue_tile(0, 0);

    asm volatile("cp.async.wait_group 1;\n" ::: "memory");
    __syncthreads();

    // Q fragments
    uint32_t qf[4][4];
#pragma unroll
    for (int c = 0; c < 4; c++) {
        qf[c][0] = Qh[(wrow + gr) * AKS + c * 8 + gc];
        qf[c][1] = Qh[(wrow + gr + 8) * AKS + c * 8 + gc];
        qf[c][2] = Qh[(wrow + gr) * AKS + c * 8 + gc + 4];
        qf[c][3] = Qh[(wrow + gr + 8) * AKS + c * 8 + gc + 4];
    }
    // inline per-row gate scalar m = Q_row . qv + bmean  (qv pre-scaled x8)
    const __half* q0h = (const __half*)(Qh + (wrow + gr) * AKS);
    const __half* q1h = (const __half*)(Qh + (wrow + gr + 8) * AKS);
    float a0 = 0.f, a1 = 0.f;
#pragma unroll
    for (int e16 = 0; e16 < 16; e16++) {
        int e = gc * 16 + e16;
        float qv = __ldg(&g_qv[e]);
        a0 = fmaf(__half2float(q0h[e]), qv, a0);
        a1 = fmaf(__half2float(q1h[e]), qv, a1);
    }
#pragma unroll
    for (int d = 1; d < 4; d <<= 1) {
        a0 += __shfl_xor_sync(0xffffffffu, a0, d);
        a1 += __shfl_xor_sync(0xffffffffu, a1, d);
    }
    float bmean = g_bmean;
    __half2 mq0h2 = __float2half2_rn(a0 + bmean);
    __half2 mq1h2 = __float2half2_rn(a1 + bmean);
    const __half2 nlog2e = __float2half2_rn(-1.44269504f);
    const __half2 oneh2 = __float2half2_rn(1.f);

    int qrow0 = q0 + wrow + gr;
    int qrow1 = qrow0 + 8;
    float rm0 = -INFINITY, rm1 = -INFINITY, rs0 = 0.f, rs1 = 0.f;
    float ofr[8][4];
#pragma unroll
    for (int nf = 0; nf < 8; nf++)
#pragma unroll
        for (int r = 0; r < 4; r++) ofr[nf][r] = 0.f;

    unsigned pmbase0 = ((unsigned)((b << 10) + qrow0)) << 5;
    unsigned pmbase1 = ((unsigned)((b << 10) + qrow1)) << 5;

    for (int kt = 0; kt < 16; kt++) {
        int cur = kt & 1;
        __syncthreads();
        if (kt < 15) issue_tile(kt + 1, 1 - cur);
        if (kt < 15) { asm volatile("cp.async.wait_group 1;\n" ::: "memory"); }
        else         { asm volatile("cp.async.wait_group 0;\n" ::: "memory"); }
        __syncthreads();

        uint32_t* Ks = KsB + cur * TILE_U;
        uint32_t* Vt = VtB + cur * TILE_U;
        const __half2* ckh = (const __half2*)(ckB + cur * 32);
        const __half2* cbh = (const __half2*)(cbB + cur * 32);
        int k0 = kt * 64;

        // ---- scores S = Q @ K^T (fp16; Q pre-scaled by 1/8) ----
        float sfr[8][4];
#pragma unroll
        for (int nf = 0; nf < 8; nf++)
#pragma unroll
            for (int r = 0; r < 4; r++) sfr[nf][r] = 0.f;
#pragma unroll
        for (int c = 0; c < 4; c++) {
#pragma unroll
            for (int nf = 0; nf < 8; nf++) {
                uint32_t bf[2];
                bf[0] = Ks[(nf * 8 + gr) * AKS + c * 8 + gc];
                bf[1] = Ks[(nf * 8 + gr) * AKS + c * 8 + gc + 4];
                MMA_F16(sfr[nf], qf[c], bf);
            }
        }

        // ---- gate (f16x2 sigmoid) + mask ----
        unsigned w00 = g_pm[pmbase0 + (k0 >> 5)];
        unsigned w01 = g_pm[pmbase0 + (k0 >> 5) + 1];
        unsigned w10 = g_pm[pmbase1 + (k0 >> 5)];
        unsigned w11 = g_pm[pmbase1 + (k0 >> 5) + 1];
#pragma unroll
        for (int nf = 0; nf < 8; nf++) {
            int c0 = nf * 8 + (gc << 1);
            int c1 = c0 + 1;
            __half2 ckp = ckh[nf * 4 + gc];
            __half2 cbp = cbh[nf * 4 + gc];
            __half2 l0 = __hfma2(mq0h2, ckp, cbp);
            __half2 l1 = __hfma2(mq1h2, ckp, cbp);
            __half2 g0h = h2rcp(__hadd2(oneh2, h2exp2(__hmul2(l0, nlog2e))));
            __half2 g1h = h2rcp(__hadd2(oneh2, h2exp2(__hmul2(l1, nlog2e))));
            float2 gf0 = __half22float2(g0h);
            float2 gf1 = __half22float2(g1h);
            float v0 = sfr[nf][0] * gf0.x;
            float v1 = sfr[nf][1] * gf0.y;
            float v2 = sfr[nf][2] * gf1.x;
            float v3 = sfr[nf][3] * gf1.y;
            unsigned wa0 = (c0 < 32) ? w00 : w01;
            unsigned wa1 = (c1 < 32) ? w00 : w01;
            unsigned wb0 = (c0 < 32) ? w10 : w11;
            unsigned wb1 = (c1 < 32) ? w10 : w11;
            if (!((wa0 >> (c0 & 31)) & 1u)) v0 = -1e9f;
            if (!((wa1 >> (c1 & 31)) & 1u)) v1 = -1e9f;
            if (!((wb0 >> (c0 & 31)) & 1u)) v2 = -1e9f;
            if (!((wb1 >> (c1 & 31)) & 1u)) v3 = -1e9f;
            sfr[nf][0] = v0; sfr[nf][1] = v1; sfr[nf][2] = v2; sfr[nf][3] = v3;
        }

        // ---- online softmax ----
        float m0 = -INFINITY, m1 = -INFINITY;
#pragma unroll
        for (int nf = 0; nf < 8; nf++) {
            m0 = fmaxf(m0, fmaxf(sfr[nf][0], sfr[nf][1]));
            m1 = fmaxf(m1, fmaxf(sfr[nf][2], sfr[nf][3]));
        }
#pragma unroll
        for (int d = 1; d < 4; d <<= 1) {
            m0 = fmaxf(m0, __shfl_xor_sync(0xffffffffu, m0, d));
            m1 = fmaxf(m1, __shfl_xor_sync(0xffffffffu, m1, d));
        }
        float tm0 = fmaxf(rm0, m0);
        float tm1 = fmaxf(rm1, m1);
        float sc0 = __expf(rm0 - tm0);
        float sc1 = __expf(rm1 - tm1);
        rm0 = tm0; rm1 = tm1;
        float sum0 = 0.f, sum1 = 0.f;
#pragma unroll
        for (int nf = 0; nf < 8; nf++) {
            float p0 = __expf(sfr[nf][0] - tm0);
            float p1 = __expf(sfr[nf][1] - tm0);
            float p2 = __expf(sfr[nf][2] - tm1);
            float p3 = __expf(sfr[nf][3] - tm1);
            sum0 += p0 + p1;
            sum1 += p2 + p3;
            sfr[nf][0] = p0; sfr[nf][1] = p1; sfr[nf][2] = p2; sfr[nf][3] = p3;
        }
#pragma unroll
        for (int d = 1; d < 4; d <<= 1) {
            sum0 += __shfl_xor_sync(0xffffffffu, sum0, d);
            sum1 += __shfl_xor_sync(0xffffffffu, sum1, d);
        }
        rs0 = rs0 * sc0 + sum0;
        rs1 = rs1 * sc1 + sum1;
#pragma unroll
        for (int nf = 0; nf < 8; nf++) {
            ofr[nf][0] *= sc0; ofr[nf][1] *= sc0;
            ofr[nf][2] *= sc1; ofr[nf][3] *= sc1;
        }

        // ---- store P as fp16 key-pairs (warp-private rows) ----
#pragma unroll
        for (int nf = 0; nf < 8; nf++) {
            int kp = nf * 4 + gc;
            PsH[(wrow + gr) * AKS + kp] = packh2(sfr[nf][0], sfr[nf][1]);
            PsH[(wrow + gr + 8) * AKS + kp] = packh2(sfr[nf][2], sfr[nf][3]);
        }
        __syncwarp();

        // ---- O += P @ V (fp16; V^T [e][kp]) ----
#pragma unroll
        for (int c = 0; c < 4; c++) {
            uint32_t af[4];
            af[0] = PsH[(wrow + gr) * AKS + c * 8 + gc];
            af[1] = PsH[(wrow + gr + 8) * AKS + c * 8 + gc];
            af[2] = PsH[(wrow + gr) * AKS + c * 8 + gc + 4];
            af[3] = PsH[(wrow + gr + 8) * AKS + c * 8 + gc + 4];
#pragma unroll
            for (int nf = 0; nf < 8; nf++) {
                uint32_t bf[2];
                bf[0] = Vt[(nf * 8 + gr) * AKS + c * 8 + gc];
                bf[1] = Vt[(nf * 8 + gr) * AKS + c * 8 + gc + 4];
                MMA_F16(ofr[nf], af, bf);
            }
        }
    }

    // ---- normalize + write fp16-packed ----
    float inv0 = 1.f / rs0;
    float inv1 = 1.f / rs1;
#pragma unroll
    for (int nf = 0; nf < 8; nf++) {
        int c0 = (h << 6) + nf * 8 + (gc << 1);
        g_xp[(size_t)((b << 10) + qrow0) * (DD / 2) + (c0 >> 1)] =
            packh2(ofr[nf][0] * inv0, ofr[nf][1] * inv0);
        g_xp[(size_t)((b << 10) + qrow1) * (DD / 2) + (c0 >> 1)] =
            packh2(ofr[nf][2] * inv1, ofr[nf][3] * inv1);
    }
}

// ---------------- launch --------------------------------------------------------
extern "C" void kernel_launch(void* const* d_in, const int* in_sizes, int n_in,
                              void* d_out, int out_size) {
    const float* query = (const float*)d_in[0];
    const float* key   = (const float*)d_in[1];
    const float* value = (const float*)d_in[2];
    const int*   mask  = (const int*)d_in[3];
    const float* wq = (const float*)d_in[4];
    const float* bq = (const float*)d_in[5];
    const float* wk = (const float*)d_in[6];
    const float* bk = (const float*)d_in[7];
    const float* wv = (const float*)d_in[8];
    const float* bv = (const float*)d_in[9];
    const float* wo = (const float*)d_in[10];
    const float* bo = (const float*)d_in[11];
    const float* spatial_w = (const float*)d_in[12];
    const float* spatial_b = (const float*)d_in[13];
    const float* qproj_w = (const float*)d_in[14];
    const float* qproj_b = (const float*)d_in[15];
    const float* kproj_w = (const float*)d_in[16];
    const float* kproj_b = (const float*)d_in[17];
    const float* vlin_w = (const float*)d_in[18];
    const float* vlin_b = (const float*)d_in[19];
    const float* chan_w = (const float*)d_in[20];
    const float* chan_b = (const float*)d_in[21];
    float* out = (float*)d_out;

    float *p_bqf, *p_bkf, *p_bvf;
    uint32_t *p_wqp, *p_wkp, *p_wvt, *p_wop, *p_aq, *p_ak, *p_avt;
    uint32_t *p_qs, *p_k2, *p_v2t, *p_xp;
    cudaGetSymbolAddress((void**)&p_bqf, g_bqf);
    cudaGetSymbolAddress((void**)&p_bkf, g_bkf);
    cudaGetSymbolAddress((void**)&p_bvf, g_bvf);
    cudaGetSymbolAddress((void**)&p_wqp, g_wqp);
    cudaGetSymbolAddress((void**)&p_wkp, g_wkp);
    cudaGetSymbolAddress((void**)&p_wvt, g_wvt);
    cudaGetSymbolAddress((void**)&p_wop, g_wop);
    cudaGetSymbolAddress((void**)&p_aq, g_aq);
    cudaGetSymbolAddress((void**)&p_ak, g_ak);
    cudaGetSymbolAddress((void**)&p_avt, g_avt);
    cudaGetSymbolAddress((void**)&p_qs, g_qs);
    cudaGetSymbolAddress((void**)&p_k2, g_k2);
    cudaGetSymbolAddress((void**)&p_v2t, g_v2t);
    cudaGetSymbolAddress((void**)&p_xp, g_xp);

    cudaFuncSetAttribute(gemm_f16, cudaFuncAttributeMaxDynamicSharedMemorySize, GSM_BYTES);
    cudaFuncSetAttribute(attn_tc_kernel, cudaFuncAttributeMaxDynamicSharedMemorySize, ASM_BYTES);

    // 1. all independent prep in one launch
    mega_prep<<<20621, 256>>>(query, key, value, mask,
                              wq, bq, wk, bk, wv, bv, wo,
                              spatial_w, spatial_b, qproj_w, qproj_b,
                              kproj_w, kproj_b, vlin_w, vlin_b, chan_w, chan_b);
    // 2. ck/cb gate scalars (fp16, head-major)
    ckcb_kernel<<<MM / 8, 256>>>(key);

    // 3. merged QKV fp16 GEMM: Q (elu, x1/8), K (elu), V transposed (elu)
    GemmArgs gqkv;
    gqkv.A[0] = p_aq;  gqkv.A[1] = p_ak;  gqkv.A[2] = p_wvt;
    gqkv.B[0] = p_wqp; gqkv.B[1] = p_wkp; gqkv.B[2] = p_avt;
    gqkv.bias[0] = p_bqf; gqkv.bias[1] = p_bkf; gqkv.bias[2] = p_bvf;
    gqkv.C[0] = p_qs;  gqkv.C[1] = p_k2;  gqkv.C[2] = p_v2t;
    gqkv.mode[0] = 4;  gqkv.mode[1] = 2;  gqkv.mode[2] = 3;
    gqkv.Nn[0] = DD;   gqkv.Nn[1] = DD;   gqkv.Nn[2] = MM;
    gemm_f16<<<dim3(8, 32, 3), 256, GSM_BYTES>>>(gqkv);

    // 4. attention: all-fp16 MMA + f16x2 gate (occ 3, cp.async)
    attn_tc_kernel<<<dim3(SS / 64, HH, BB), 128, ASM_BYTES>>>();

    // 5. fp16 output projection
    GemmArgs go;
    go.A[0] = go.A[1] = go.A[2] = p_xp;
    go.B[0] = go.B[1] = go.B[2] = p_wop;
    go.bias[0] = go.bias[1] = go.bias[2] = bo;
    go.C[0] = go.C[1] = go.C[2] = out;
    go.mode[0] = go.mode[1] = go.mode[2] = 0;
    go.Nn[0] = go.Nn[1] = go.Nn[2] = DD;
    gemm_f16<<<dim3(8, 32, 1), 256, GSM_BYTES>>>(go);
}